// round 10
// baseline (speedup 1.0000x reference)
#include <cuda_runtime.h>
#include <cuda_bf16.h>
#include <stdint.h>
#include <math.h>

#define H_   12
#define T_   512
#define D_   64
#define C_   768
#define B_   32
#define NQKV_ 2304
#define BT_  16384
#define QSCALE 0.125f

// ------------- device-global scratch (no runtime alloc allowed) -------------
// combined granule: 16B = [hi(k),hi(k+1),hi(k+8),hi(k+9) | lo(same 4)]
__device__ __align__(16) uint8_t g_xc[(size_t)BT_*3072];
__device__ __align__(16) uint8_t g_wqc[(size_t)NQKV_*3072];
__device__ __align__(16) uint8_t g_oc[(size_t)BT_*3072];
__device__ __align__(16) uint8_t g_wcc[(size_t)C_*3072];
__device__ __align__(16) uint8_t g_qc[(size_t)B_*H_*T_*256];   // [b,h,t] rows, 256B
__device__ __align__(16) uint8_t g_kc[(size_t)B_*H_*T_*256];
__device__ __align__(16) __nv_bfloat16 g_vhi[(size_t)B_*H_*T_*D_];
__device__ __align__(16) __nv_bfloat16 g_vlo[(size_t)B_*H_*T_*D_];
__device__ __align__(16) uint8_t g_vtc[(size_t)B_*H_*64*2048];  // [b,h,d] rows, 2048B
__device__ __align__(16) float g_wcomb[C_*C_];
__device__ __align__(16) float g_bcomb[C_];

// ------------------------------ helpers -------------------------------------
__device__ __forceinline__ uint32_t smem_u32(const void* p) {
    uint32_t a;
    asm("{ .reg .u64 t; cvta.to.shared.u64 t, %1; cvt.u32.u64 %0, t; }"
        : "=r"(a) : "l"(p));
    return a;
}
__device__ __forceinline__ void mma_bf16(float* c, const uint32_t* a,
                                         uint32_t b0, uint32_t b1) {
    asm volatile(
        "mma.sync.aligned.m16n8k16.row.col.f32.bf16.bf16.f32 "
        "{%0,%1,%2,%3}, {%4,%5,%6,%7}, {%8,%9}, {%0,%1,%2,%3};"
        : "+f"(c[0]), "+f"(c[1]), "+f"(c[2]), "+f"(c[3])
        : "r"(a[0]), "r"(a[1]), "r"(a[2]), "r"(a[3]), "r"(b0), "r"(b1));
}
#define LDS128O(x,y,z,w,base,imm) \
    asm volatile("ld.shared.v4.b32 {%0,%1,%2,%3}, [%4+%5];" \
        : "=r"(x), "=r"(y), "=r"(z), "=r"(w) : "r"(base), "n"(imm))

__device__ __forceinline__ void split_bf16(float v, __nv_bfloat16& h, __nv_bfloat16& l) {
    h = __float2bfloat16(v);
    l = __float2bfloat16(v - __bfloat162float(h));
}
__device__ __forceinline__ uint32_t pack2(float a, float b) {
    __nv_bfloat162 t = __floats2bfloat162_rn(a, b);
    return *(uint32_t*)&t;
}
__device__ __forceinline__ float resid(float v) {
    return v - __bfloat162float(__float2bfloat16(v));
}
__device__ __forceinline__ void pack_granule(float f0, float f1, float f2, float f3,
                                             uint32_t* w) {
    __nv_bfloat16 h0,l0,h1,l1,h2,l2,h3,l3;
    split_bf16(f0,h0,l0); split_bf16(f1,h1,l1);
    split_bf16(f2,h2,l2); split_bf16(f3,h3,l3);
    __nv_bfloat162 t;
    t.x=h0; t.y=h1; w[0] = *(uint32_t*)&t;
    t.x=h2; t.y=h3; w[1] = *(uint32_t*)&t;
    t.x=l0; t.y=l1; w[2] = *(uint32_t*)&t;
    t.x=l2; t.y=l3; w[3] = *(uint32_t*)&t;
}

// ------------------------------ prep kernels --------------------------------
__global__ void __launch_bounds__(256) k_prep_xc(const float* __restrict__ x) {
    int gid = blockIdx.x * 256 + threadIdx.x;
    int lc = gid & 3, g = (gid >> 2) % 48;
    int m = gid / 192;
    const float* xr = x + (size_t)m * 768 + g * 16 + lc * 2;
    uint32_t w[4];
    pack_granule(xr[0], xr[1], xr[8], xr[9], w);
    *(uint4*)(g_xc + (size_t)m * 3072 + g * 64 + lc * 16) = *(uint4*)w;
}

__global__ void __launch_bounds__(256) k_prep_wqc(const float* __restrict__ W) {
    int gid = blockIdx.x * 256 + threadIdx.x;
    int lc = gid & 3, g = (gid >> 2) % 48;
    int n = gid / 192;
    int h = n / 192, j = n % 192;
    const float* wb = W + ((size_t)h * 768 + g * 16 + lc * 2) * 192 + j;
    uint32_t w[4];
    pack_granule(wb[0], wb[192], wb[8*192], wb[9*192], w);
    *(uint4*)(g_wqc + (size_t)n * 3072 + g * 64 + lc * 16) = *(uint4*)w;
}

__global__ void __launch_bounds__(256) k_prep_wccT() {
    int gid = blockIdx.x * 256 + threadIdx.x;
    int lc = gid & 3, g = (gid >> 2) % 48;
    int n = gid / 192;
    int k0 = g * 16 + lc * 2;
    uint32_t w[4];
    pack_granule(g_wcomb[(size_t)k0*768 + n],     g_wcomb[(size_t)(k0+1)*768 + n],
                 g_wcomb[(size_t)(k0+8)*768 + n], g_wcomb[(size_t)(k0+9)*768 + n], w);
    *(uint4*)(g_wcc + (size_t)n * 3072 + g * 64 + lc * 16) = *(uint4*)w;
}

__global__ void __launch_bounds__(256) k_binit(const float* __restrict__ bproj) {
    int idx = blockIdx.x * 256 + threadIdx.x;
    if (idx < C_*C_) g_wcomb[idx] = 0.0f;
    int j = idx - C_*C_;
    if (j >= 0 && j < C_) g_bcomb[j] = bproj[j];
}

__global__ void __launch_bounds__(256) k_bcomb(const float* __restrict__ bph,
                                               const float* __restrict__ Wproj) {
    int r0 = blockIdx.x * 32;
    int t = threadIdx.x;
    float a0 = 0.f, a1 = 0.f, a2 = 0.f;
    for (int rr = 0; rr < 32; ++rr) {
        int r = r0 + rr;
        float bv = bph[r];
        const float* wr = Wproj + (size_t)r * C_;
        a0 = fmaf(bv, wr[t],       a0);
        a1 = fmaf(bv, wr[t + 256], a1);
        a2 = fmaf(bv, wr[t + 512], a2);
    }
    atomicAdd(&g_bcomb[t],       a0);
    atomicAdd(&g_bcomb[t + 256], a1);
    atomicAdd(&g_bcomb[t + 512], a2);
}

// ------- Wcomb precompute: fp32, 4-way K-split, atomic accumulate -----------
__global__ void __launch_bounds__(256) sgemm64ks(
    const float* __restrict__ A, const float* __restrict__ Bm,
    float* __restrict__ Cm)
{
    __shared__ float As[16][68];
    __shared__ float Bs[16][68];
    const int z = blockIdx.z;
    const float* Ab = A  + (size_t)z * 64 * C_;
    const float* Bb = Bm + (size_t)z * C_ * C_;
    float*       Cb = Cm + (size_t)z * 64 * C_;
    const int tid = threadIdx.x;
    const int tx = tid % 16, ty = tid / 16;
    const int n0 = blockIdx.y * 64;
    const int kbeg = blockIdx.x * 192, kend = kbeg + 192;
    float acc[4][4] = {};
    for (int kt = kbeg; kt < kend; kt += 16) {
        {
            int m = tid / 4, kq = (tid % 4) * 4;
            float4 v = *(const float4*)(Ab + (size_t)m*C_ + kt + kq);
            As[kq+0][m] = v.x; As[kq+1][m] = v.y; As[kq+2][m] = v.z; As[kq+3][m] = v.w;
        }
        {
            int kk = tid / 16, nn = (tid % 16) * 4;
            *(float4*)&Bs[kk][nn] = *(const float4*)(Bb + (size_t)(kt+kk)*C_ + n0 + nn);
        }
        __syncthreads();
        #pragma unroll
        for (int k = 0; k < 16; ++k) {
            float a[4], b[4];
            #pragma unroll
            for (int i = 0; i < 4; ++i) a[i] = As[k][ty*4+i];
            *(float4*)b = *(const float4*)&Bs[k][tx*4];
            #pragma unroll
            for (int i = 0; i < 4; ++i)
                #pragma unroll
                for (int j = 0; j < 4; ++j)
                    acc[i][j] = fmaf(a[i], b[j], acc[i][j]);
        }
        __syncthreads();
    }
    #pragma unroll
    for (int i = 0; i < 4; ++i) {
        int m = ty*4 + i;
        #pragma unroll
        for (int j = 0; j < 4; ++j)
            atomicAdd(&Cb[(size_t)m*C_ + n0 + tx*4 + j], acc[i][j]);
    }
}

// ------------------- HMMA bf16-split GEMM (combined v4 layout) --------------
// CSTR = 144B: 36 words == 4 (mod 32) -> 8 consecutive rows hit 8 distinct
// bank-quads -> conflict-free LDS.128. (192B was 4-way conflicted.)
#define CSTR 144
#define CTILE (128*CSTR)      // 18432
#define CSTAGE (2*CTILE)      // 36864
#define HM_SMEM (2*CSTAGE)    // 73728

#define A_FRAG(mt, ks, AH, AL) do { \
    uint32_t x0,y0,z0,w0,x1,y1,z1,w1; \
    LDS128O(x0,y0,z0,w0, aB, (mt)*16*CSTR + (ks)*64); \
    LDS128O(x1,y1,z1,w1, aB, (mt)*16*CSTR + 8*CSTR + (ks)*64); \
    AH[0]=x0; AH[1]=x1; AH[2]=y0; AH[3]=y1; \
    AL[0]=z0; AL[1]=z1; AL[2]=w0; AL[3]=w1; } while(0)

// nt-pair interleaved: dependent MMAs are 4 apart
#define B_PAIR(nt0, ks) do { \
    uint32_t b00,b01,b02,b03, b10,b11,b12,b13; \
    LDS128O(b00,b01,b02,b03, bB, (nt0)*8*CSTR + (ks)*64); \
    LDS128O(b10,b11,b12,b13, bB, ((nt0)+1)*8*CSTR + (ks)*64); \
    mma_bf16(acc[0][(nt0)],   AH0, b00, b01); \
    mma_bf16(acc[1][(nt0)],   AH1, b00, b01); \
    mma_bf16(acc[0][(nt0)+1], AH0, b10, b11); \
    mma_bf16(acc[1][(nt0)+1], AH1, b10, b11); \
    mma_bf16(acc[0][(nt0)],   AH0, b02, b03); \
    mma_bf16(acc[1][(nt0)],   AH1, b02, b03); \
    mma_bf16(acc[0][(nt0)+1], AH0, b12, b13); \
    mma_bf16(acc[1][(nt0)+1], AH1, b12, b13); \
    mma_bf16(acc[0][(nt0)],   AL0, b00, b01); \
    mma_bf16(acc[1][(nt0)],   AL1, b00, b01); \
    mma_bf16(acc[0][(nt0)+1], AL0, b10, b11); \
    mma_bf16(acc[1][(nt0)+1], AL1, b10, b11); } while(0)

#define KS_BLOCK(ks) do { \
    uint32_t AH0[4],AL0[4],AH1[4],AL1[4]; \
    A_FRAG(0, ks, AH0, AL0); \
    A_FRAG(1, ks, AH1, AL1); \
    B_PAIR(0,ks); B_PAIR(2,ks); B_PAIR(4,ks); B_PAIR(6,ks); } while(0)

template<int EPI>
__global__ void __launch_bounds__(256, 2) hmma_gemm(
    const uint8_t* __restrict__ Ac, const uint8_t* __restrict__ Bc,
    float* __restrict__ Cout, const float* __restrict__ bias)
{
    extern __shared__ char smem[];
    const uint32_t sbase = smem_u32(smem);
    const int tid = threadIdx.x;
    const int wid = tid >> 5, ln = tid & 31;
    const int n0 = blockIdx.x * 128, m0 = blockIdx.y * 128;
    const int wm = wid & 3, wn = wid >> 2;
    const int mrow = wm * 32, ncol = wn * 64;
    const int lr = ln >> 2, lc = ln & 3;

    const uint8_t* gA = Ac + (size_t)m0 * 3072;
    const uint8_t* gB = Bc + (size_t)n0 * 3072;

    auto load_chunk = [&](int kc, int stage) {
        uint32_t sb = sbase + stage * CSTAGE;
        const uint8_t* pA = gA + kc * 128;
        const uint8_t* pB = gB + kc * 128;
        #pragma unroll
        for (int i = 0; i < 4; ++i) {
            int gid = tid + i * 256;
            int r = gid >> 3, c = gid & 7;
            asm volatile("cp.async.cg.shared.global [%0], [%1], 16;"
                :: "r"(sb + r*CSTR + c*16), "l"(pA + (size_t)r*3072 + c*16));
        }
        #pragma unroll
        for (int i = 0; i < 4; ++i) {
            int gid = tid + i * 256;
            int r = gid >> 3, c = gid & 7;
            asm volatile("cp.async.cg.shared.global [%0], [%1], 16;"
                :: "r"(sb + CTILE + r*CSTR + c*16), "l"(pB + (size_t)r*3072 + c*16));
        }
        asm volatile("cp.async.commit_group;");
    };

    const uint32_t wA = sbase + (uint32_t)((mrow + lr)*CSTR + lc*16);
    const uint32_t wB = sbase + CTILE + (uint32_t)((ncol + lr)*CSTR + lc*16);

    float acc[2][8][4] = {};
    load_chunk(0, 0);
    for (int c = 0; c < 24; ++c) {
        int s = c & 1;
        asm volatile("cp.async.wait_group 0;");
        __syncthreads();
        if (c + 1 < 24) load_chunk(c + 1, s ^ 1);

        const uint32_t aB = wA + s * CSTAGE;
        const uint32_t bB = wB + s * CSTAGE;
        KS_BLOCK(0);
        KS_BLOCK(1);
        __syncthreads();
    }

    // ------------------------------- epilogue --------------------------------
    if (EPI == 0) {
        #pragma unroll
        for (int mt = 0; mt < 2; ++mt) {
            int m = m0 + mrow + mt*16 + lr;
            #pragma unroll
            for (int nt = 0; nt < 8; ++nt) {
                int n = n0 + ncol + nt*8 + lc*2;
                float b0 = bias[n], b1 = bias[n+1];
                float* ac = acc[mt][nt];
                float2 v0 = {ac[0] + b0, ac[1] + b1};
                float2 v1 = {ac[2] + b0, ac[3] + b1};
                *(float2*)(Cout + (size_t)m * C_ + n) = v0;
                *(float2*)(Cout + (size_t)(m+8) * C_ + n) = v1;
            }
        }
    } else {
        const int nbase = n0 + ncol;                 // 64-aligned -> one block
        const int h = nbase / 192, rb = nbase % 192, blk = rb >> 6;
        if (blk < 2) {
            uint8_t* dst = (blk == 0) ? g_qc : g_kc;
            const float sc = (blk == 0) ? QSCALE : 1.0f;
            #pragma unroll
            for (int mt = 0; mt < 2; ++mt) {
                #pragma unroll
                for (int rr = 0; rr < 2; ++rr) {
                    int mm = m0 + mrow + mt*16 + lr + rr*8;
                    int b_ = mm >> 9, t_ = mm & 511;
                    size_t rowb = (((size_t)b_*H_ + h)*T_ + t_) * 256;
                    #pragma unroll
                    for (int ge = 0; ge < 4; ++ge) {
                        int nA = nbase + ge*16 + lc*2;
                        float v0 = (acc[mt][2*ge][rr*2+0]   + bias[nA])   * sc;
                        float v1 = (acc[mt][2*ge][rr*2+1]   + bias[nA+1]) * sc;
                        float v2 = (acc[mt][2*ge+1][rr*2+0] + bias[nA+8]) * sc;
                        float v3 = (acc[mt][2*ge+1][rr*2+1] + bias[nA+9]) * sc;
                        uint32_t w[4];
                        pack_granule(v0, v1, v2, v3, w);
                        *(uint4*)(dst + rowb + ge*64 + lc*16) = *(uint4*)w;
                    }
                }
            }
        } else {
            #pragma unroll
            for (int mt = 0; mt < 2; ++mt) {
                int m = m0 + mrow + mt*16 + lr;
                #pragma unroll
                for (int nt = 0; nt < 8; ++nt) {
                    int n = nbase + nt*8 + lc*2;
                    int roff = (n % 192) & 63;
                    float b0 = bias[n], b1 = bias[n+1];
                    float* ac = acc[mt][nt];
                    #pragma unroll
                    for (int rr = 0; rr < 2; ++rr) {
                        int mm = m + rr*8;
                        int b_ = mm >> 9, t_ = mm & 511;
                        size_t o = (((size_t)b_ * H_ + h) * T_ + t_) * 64 + roff;
                        float v0 = ac[rr*2+0] + b0;
                        float v1 = ac[rr*2+1] + b1;
                        __nv_bfloat16 h0,h1,l0,l1;
                        split_bf16(v0,h0,l0); split_bf16(v1,h1,l1);
                        __nv_bfloat162 ph; ph.x=h0; ph.y=h1;
                        __nv_bfloat162 pl; pl.x=l0; pl.y=l1;
                        *(__nv_bfloat162*)(g_vhi + o) = ph;
                        *(__nv_bfloat162*)(g_vlo + o) = pl;
                    }
                }
            }
        }
    }
}

// ---------------- V transpose: [s][d] -> [d][s] combined granules ------------
__global__ void __launch_bounds__(256) k_vT() {
    __shared__ __nv_bfloat16 thi[64][72];
    __shared__ __nv_bfloat16 tlo[64][72];
    const int s0 = blockIdx.x * 64;
    const int bh = blockIdx.y;
    const int tid = threadIdx.x;
    const int r = tid >> 2, cs = (tid & 3) * 16;
    const size_t sbase = ((size_t)bh * T_ + s0 + r) * 64 + cs;
    #pragma unroll
    for (int j = 0; j < 2; ++j) {
        *(uint4*)&thi[r][cs + j*8] = *(const uint4*)(g_vhi + sbase + j*8);
        *(uint4*)&tlo[r][cs + j*8] = *(const uint4*)(g_vlo + sbase + j*8);
    }
    __syncthreads();
    const int d = tid >> 2, ss = (tid & 3) * 16;
    const int gidx = (s0 + ss) >> 4;
    const size_t base = (((size_t)bh * 64 + d) * 32 + gidx) * 64;
    #pragma unroll
    for (int lcx = 0; lcx < 4; ++lcx) {
        int s = ss + 2*lcx;
        uint32_t w[4];
        __nv_bfloat162 t;
        t.x = thi[s][d];   t.y = thi[s+1][d];   w[0] = *(uint32_t*)&t;
        t.x = thi[s+8][d]; t.y = thi[s+9][d];   w[1] = *(uint32_t*)&t;
        t.x = tlo[s][d];   t.y = tlo[s+1][d];   w[2] = *(uint32_t*)&t;
        t.x = tlo[s+8][d]; t.y = tlo[s+9][d];   w[3] = *(uint32_t*)&t;
        *(uint4*)(g_vtc + base + lcx*16) = *(uint4*)w;
    }
}

// --------------------------- HMMA fused attention ----------------------------
// Conflict-free strides: 272B (68w == 4 mod 32), 2064B (516w == 4 mod 32).
#define KSTR2 272
#define QSTR2 272
#define VTSTR2 2064
#define SM_K 0u
#define SM_VT 0u
#define SM_Q 139264u
#define SM_OBUF 139264u
#define OSTRF 72
#define SM_EXM 157696u
#define SM_EXS 158720u
#define ATTN_SMEM 159744

#define Q_FRAG(ks) do { \
    uint32_t x0,y0,z0,w0,x1,y1,z1,w1; \
    LDS128O(x0,y0,z0,w0, qfb, (ks)*64); \
    LDS128O(x1,y1,z1,w1, qfb, 8*QSTR2 + (ks)*64); \
    aH[ks][0]=x0; aH[ks][1]=x1; aH[ks][2]=y0; aH[ks][3]=y1; \
    aL[ks][0]=z0; aL[ks][1]=z1; aL[ks][2]=w0; aL[ks][3]=w1; } while(0)

// nt-pair interleaved S step: dependent MMAs 2 apart
#define S_PAIR(nt0, ks) do { \
    uint32_t b00,b01,b02,b03, b10,b11,b12,b13; \
    LDS128O(b00,b01,b02,b03, kb0, (ks)*64); \
    LDS128O(b10,b11,b12,b13, kb1, (ks)*64); \
    mma_bf16(acc[(nt0)],   aH[ks], b00, b01); \
    mma_bf16(acc[(nt0)+1], aH[ks], b10, b11); \
    mma_bf16(acc[(nt0)],   aH[ks], b02, b03); \
    mma_bf16(acc[(nt0)+1], aH[ks], b12, b13); \
    mma_bf16(acc[(nt0)],   aL[ks], b00, b01); \
    mma_bf16(acc[(nt0)+1], aL[ks], b10, b11); } while(0)

// dn-pair interleaved PV step: dependent MMAs 2 apart
#define PV_PAIR(dn) do { \
    uint32_t b00,b01,b02,b03, b10,b11,b12,b13; \
    LDS128O(b00,b01,b02,b03, vb, (dn)*8*VTSTR2); \
    LDS128O(b10,b11,b12,b13, vb, ((dn)+1)*8*VTSTR2); \
    mma_bf16(oacc[(dn)],   phi, b00, b01); \
    mma_bf16(oacc[(dn)+1], phi, b10, b11); \
    mma_bf16(oacc[(dn)],   phi, b02, b03); \
    mma_bf16(oacc[(dn)+1], phi, b12, b13); \
    mma_bf16(oacc[(dn)],   plo, b00, b01); \
    mma_bf16(oacc[(dn)+1], plo, b10, b11); } while(0)

__global__ void __launch_bounds__(512) attn_k(float* __restrict__ probs)
{
    extern __shared__ char smem[];
    const uint32_t sb = smem_u32(smem);
    const int tid = threadIdx.x;
    const int wid = tid >> 5, ln = tid & 31;
    const int wm = wid & 3, wq = wid >> 2;
    const int b = blockIdx.z, h = blockIdx.y, t0 = blockIdx.x * 64;
    const int bh = b * H_ + h;
    const int lr = ln >> 2, lc = ln & 3;

    // ---- load K (512 rows x 256B) + Q (64 rows x 256B), combined ----
    {
        const uint8_t* kc = g_kc + (size_t)bh * T_ * 256;
        #pragma unroll
        for (int i = 0; i < 16; ++i) {
            int idx = tid + i * 512;
            int r = idx >> 4, c = idx & 15;
            asm volatile("cp.async.cg.shared.global [%0], [%1], 16;"
                :: "r"(sb + SM_K + r*KSTR2 + c*16), "l"(kc + (size_t)r*256 + c*16));
        }
        const uint8_t* qc = g_qc + ((size_t)bh * T_ + t0) * 256;
        #pragma unroll
        for (int i = 0; i < 2; ++i) {
            int idx = tid + i * 512;
            int r = idx >> 4, c = idx & 15;
            asm volatile("cp.async.cg.shared.global [%0], [%1], 16;"
                :: "r"(sb + SM_Q + r*QSTR2 + c*16), "l"(qc + (size_t)r*256 + c*16));
        }
        asm volatile("cp.async.commit_group;");
        asm volatile("cp.async.wait_group 0;");
    }
    __syncthreads();

    // ---- Q fragments ----
    uint32_t aH[4][4], aL[4][4];
    {
        const uint32_t qfb = sb + SM_Q + (uint32_t)((wm*16 + lr)*QSTR2 + lc*16);
        Q_FRAG(0); Q_FRAG(1); Q_FRAG(2); Q_FRAG(3);
    }

    // ---- S = Q K^T (nt pairs, interleaved chains) ----
    float acc[16][4];
    #pragma unroll
    for (int nt = 0; nt < 16; ++nt) { acc[nt][0]=acc[nt][1]=acc[nt][2]=acc[nt][3]=0.f; }
    {
        const uint32_t kb_warp = sb + SM_K + (uint32_t)((wq*128 + lr)*KSTR2 + lc*16);
        #pragma unroll
        for (int nt0 = 0; nt0 < 16; nt0 += 2) {
            const uint32_t kb0 = kb_warp + nt0*8*KSTR2;
            const uint32_t kb1 = kb0 + 8*KSTR2;
            S_PAIR(nt0, 0); S_PAIR(nt0, 1); S_PAIR(nt0, 2); S_PAIR(nt0, 3);
        }
    }

    // ---- softmax over 512 keys ----
    const int row0 = wm * 16 + lr;
    {
        float mx0 = -1e30f, mx1 = -1e30f;
        #pragma unroll
        for (int nt = 0; nt < 16; ++nt) {
            mx0 = fmaxf(mx0, fmaxf(acc[nt][0], acc[nt][1]));
            mx1 = fmaxf(mx1, fmaxf(acc[nt][2], acc[nt][3]));
        }
        mx0 = fmaxf(mx0, __shfl_xor_sync(0xffffffffu, mx0, 1));
        mx0 = fmaxf(mx0, __shfl_xor_sync(0xffffffffu, mx0, 2));
        mx1 = fmaxf(mx1, __shfl_xor_sync(0xffffffffu, mx1, 1));
        mx1 = fmaxf(mx1, __shfl_xor_sync(0xffffffffu, mx1, 2));
        float* exm = (float*)(smem + SM_EXM);
        if (lc == 0) { exm[wq*64 + row0] = mx0; exm[wq*64 + row0 + 8] = mx1; }
        __syncthreads();     // all warps past S MMAs -> K region dead

        // ---- prefetch VT (combined) into K region ----
        {
            const uint8_t* vt = g_vtc + (size_t)bh * 64 * 2048;
            #pragma unroll
            for (int i = 0; i < 16; ++i) {
                int idx = tid + i * 512;
                int d = idx >> 7, c = idx & 127;
                asm volatile("cp.async.cg.shared.global [%0], [%1], 16;"
                    :: "r"(sb + SM_VT + d*VTSTR2 + c*16), "l"(vt + (size_t)d*2048 + c*16));
            }
            asm volatile("cp.async.commit_group;");
        }

        float m0 = fmaxf(fmaxf(exm[row0],      exm[64+row0]),
                         fmaxf(exm[128+row0],  exm[192+row0]));
        float m1 = fmaxf(fmaxf(exm[row0+8],    exm[64+row0+8]),
                         fmaxf(exm[128+row0+8],exm[192+row0+8]));
        float s0 = 0.f, s1 = 0.f;
        #pragma unroll
        for (int nt = 0; nt < 16; ++nt) {
            acc[nt][0] = __expf(acc[nt][0] - m0); s0 += acc[nt][0];
            acc[nt][1] = __expf(acc[nt][1] - m0); s0 += acc[nt][1];
            acc[nt][2] = __expf(acc[nt][2] - m1); s1 += acc[nt][2];
            acc[nt][3] = __expf(acc[nt][3] - m1); s1 += acc[nt][3];
        }
        s0 += __shfl_xor_sync(0xffffffffu, s0, 1);
        s0 += __shfl_xor_sync(0xffffffffu, s0, 2);
        s1 += __shfl_xor_sync(0xffffffffu, s1, 1);
        s1 += __shfl_xor_sync(0xffffffffu, s1, 2);
        float* exs = (float*)(smem + SM_EXS);
        if (lc == 0) { exs[wq*64 + row0] = s0; exs[wq*64 + row0 + 8] = s1; }
        __syncthreads();
        float inv0 = 1.0f / (exs[row0] + exs[64+row0] + exs[128+row0] + exs[192+row0]);
        float inv1 = 1.0f / (exs[row0+8] + exs[64+row0+8] + exs[128+row0+8] + exs[192+row0+8]);
        #pragma unroll
        for (int nt = 0; nt < 16; ++nt) {
            acc[nt][0] *= inv0; acc[nt][1] *= inv0;
            acc[nt][2] *= inv1; acc[nt][3] *= inv1;
        }
    }

    // ---- wait VT, then PV with probs stores interleaved ----
    asm volatile("cp.async.wait_group 0;");
    __syncthreads();

    float* p0 = probs + ((size_t)bh * T_ + t0 + row0) * 512 + wq*128 + lc*2;
    float* p1 = p0 + (size_t)8 * 512;

    float oacc[8][4];
    #pragma unroll
    for (int dn = 0; dn < 8; ++dn) { oacc[dn][0]=oacc[dn][1]=oacc[dn][2]=oacc[dn][3]=0.f; }
    const uint32_t vb_warp = sb + SM_VT + (uint32_t)(lr*VTSTR2 + wq*512 + lc*16);
    #pragma unroll
    for (int kk = 0; kk < 8; ++kk) {
        uint32_t phi[4], plo[4];
        phi[0] = pack2(acc[2*kk][0],   acc[2*kk][1]);
        phi[1] = pack2(acc[2*kk][2],   acc[2*kk][3]);
        phi[2] = pack2(acc[2*kk+1][0], acc[2*kk+1][1]);
        phi[3] = pack2(acc[2*kk+1][2], acc[2*kk+1][3]);
        plo[0] = pack2(resid(acc[2*kk][0]),   resid(acc[2*kk][1]));
        plo[1] = pack2(resid(acc[2*kk][2]),   resid(acc[2*kk][3]));
        plo[2] = pack2(resid(acc[2*kk+1][0]), resid(acc[2*kk+1][1]));
        plo[3] = pack2(resid(acc[2*kk+1][2]), resid(acc[2*kk+1][3]));
        {
            float2 v00 = {acc[2*kk][0],   acc[2*kk][1]};
            float2 v01 = {acc[2*kk][2],   acc[2*kk][3]};
            float2 v10 = {acc[2*kk+1][0], acc[2*kk+1][1]};
            float2 v11 = {acc[2*kk+1][2], acc[2*kk+1][3]};
            *(float2*)(p0 + (2*kk)*8)   = v00;
            *(float2*)(p1 + (2*kk)*8)   = v01;
            *(float2*)(p0 + (2*kk+1)*8) = v10;
            *(float2*)(p1 + (2*kk+1)*8) = v11;
        }
        const uint32_t vb = vb_warp + kk*64;
        PV_PAIR(0); PV_PAIR(2); PV_PAIR(4); PV_PAIR(6);
    }

    // ---- cross-warp reduce ----
    float* obuf = (float*)(smem + SM_OBUF);
    #pragma unroll
    for (int g = 0; g < 4; ++g) {
        if (wq == g) {
            #pragma unroll
            for (int dn = 0; dn < 8; ++dn) {
                int c = dn*8 + lc*2;
                float* b0 = obuf + row0 * OSTRF + c;
                float* b1 = obuf + (row0 + 8) * OSTRF + c;
                if (g == 0) {
                    b0[0] = oacc[dn][0]; b0[1] = oacc[dn][1];
                    b1[0] = oacc[dn][2]; b1[1] = oacc[dn][3];
                } else {
                    b0[0] += oacc[dn][0]; b0[1] += oacc[dn][1];
                    b1[0] += oacc[dn][2]; b1[1] += oacc[dn][3];
                }
            }
        }
        __syncthreads();
    }

    // ---- write O in combined layout for OUT gemm ----
    {
        int row = tid >> 3, s2 = tid & 7;
        const float* src = obuf + row * OSTRF;
        size_t rb = ((size_t)b * T_ + t0 + row) * 3072 + (size_t)h * 256;
        #pragma unroll
        for (int u = 0; u < 2; ++u) {
            int s = s2 * 2 + u;
            int g = s >> 2, lcx = s & 3;
            int k0 = g * 16 + lcx * 2;
            uint32_t w[4];
            pack_granule(src[k0], src[k0+1], src[k0+8], src[k0+9], w);
            *(uint4*)(g_oc + rb + g*64 + lcx*16) = *(uint4*)w;
        }
    }
}

// --------------------------------- launcher ---------------------------------
extern "C" void kernel_launch(void* const* d_in, const int* in_sizes, int n_in,
                              void* d_out, int out_size)
{
    const float* x     = (const float*)d_in[0];
    const float* Wqkv  = (const float*)d_in[1];
    const float* bqkv  = (const float*)d_in[2];
    const float* Wph   = (const float*)d_in[3];
    const float* bph   = (const float*)d_in[4];
    const float* Wproj = (const float*)d_in[5];
    const float* bproj = (const float*)d_in[6];
    float* out = (float*)d_out;
    float* sa_out = out;
    float* probs  = out + (size_t)BT_*C_;

    uint8_t *xc_p, *wqc_p, *oc_p, *wcc_p;
    float *wcomb_p, *bcomb_p;
    cudaGetSymbolAddress((void**)&xc_p,   g_xc);
    cudaGetSymbolAddress((void**)&wqc_p,  g_wqc);
    cudaGetSymbolAddress((void**)&oc_p,   g_oc);
    cudaGetSymbolAddress((void**)&wcc_p,  g_wcc);
    cudaGetSymbolAddress((void**)&wcomb_p, g_wcomb);
    cudaGetSymbolAddress((void**)&bcomb_p, g_bcomb);

    static int attrs_set = 0;
    if (!attrs_set) {
        cudaFuncSetAttribute(hmma_gemm<0>, cudaFuncAttributeMaxDynamicSharedMemorySize, HM_SMEM);
        cudaFuncSetAttribute(hmma_gemm<1>, cudaFuncAttributeMaxDynamicSharedMemorySize, HM_SMEM);
        cudaFuncSetAttribute(attn_k, cudaFuncAttributeMaxDynamicSharedMemorySize, ATTN_SMEM);
        attrs_set = 1;
    }

    // 1-3: prep on QKV critical path (+ wcomb zero / bcomb init)
    k_prep_xc<<<BT_*192/256, 256>>>(x);
    k_prep_wqc<<<NQKV_*192/256, 256>>>(Wqkv);
    k_binit<<<(C_*C_ + C_ + 255)/256, 256>>>(bproj);

    // 4: QKV GEMM (profiled slot) -> q/k combined, v hi/lo
    hmma_gemm<1><<<dim3(NQKV_/128, BT_/128), 256, HM_SMEM>>>(
        xc_p, wqc_p, nullptr, bqkv);

    // 5-7: Wcomb chain (independent of attention)
    k_bcomb<<<288, 256>>>(bph, Wproj);
    sgemm64ks<<<dim3(4, 12, 12), 256>>>(Wph, Wproj, wcomb_p);
    k_prep_wccT<<<C_*192/256, 256>>>();

    // 8: V transpose -> combined [b,h,d,s]
    k_vT<<<dim3(T_/64, B_*H_), 256>>>();

    // 9: fused attention -> probs + O(combined)
    attn_k<<<dim3(T_/64, H_, B_), 512, ATTN_SMEM>>>(probs);

    // 10: output GEMM + bcomb -> sa_out
    hmma_gemm<0><<<dim3(C_/128, BT_/128), 256, HM_SMEM>>>(
        oc_p, wcc_p, sa_out, bcomb_p);
}

// round 11
// speedup vs baseline: 1.1847x; 1.1847x over previous
#include <cuda_runtime.h>
#include <cuda_bf16.h>
#include <stdint.h>
#include <math.h>

#define H_   12
#define T_   512
#define D_   64
#define C_   768
#define B_   32
#define NQKV_ 2304
#define BT_  16384
#define BHTD_ ((size_t)B_*H_*T_*D_)
#define QSCALE 0.125f

// ------------- device-global scratch (no runtime alloc allowed) -------------
// combined granule: 16B = [hi(k),hi(k+1),hi(k+8),hi(k+9) | lo(same 4)]
__device__ __align__(16) uint8_t g_xc[(size_t)BT_*3072];
__device__ __align__(16) uint8_t g_wqc[(size_t)NQKV_*3072];
__device__ __align__(16) uint8_t g_oc[(size_t)BT_*3072];
__device__ __align__(16) uint8_t g_wcc[(size_t)C_*3072];
__device__ __align__(16) __nv_bfloat16 g_qhi[BHTD_];
__device__ __align__(16) __nv_bfloat16 g_qlo[BHTD_];
__device__ __align__(16) __nv_bfloat16 g_khi[BHTD_];
__device__ __align__(16) __nv_bfloat16 g_klo[BHTD_];
__device__ __align__(16) __nv_bfloat16 g_vhi[BHTD_];
__device__ __align__(16) __nv_bfloat16 g_vlo[BHTD_];
__device__ __align__(16) __nv_bfloat16 g_vthi[BHTD_];   // [b,h,d,s]
__device__ __align__(16) __nv_bfloat16 g_vtlo[BHTD_];
__device__ __align__(16) float g_wcomb[C_*C_];
__device__ __align__(16) float g_bcomb[C_];

// ------------------------------ helpers -------------------------------------
__device__ __forceinline__ uint32_t smem_u32(const void* p) {
    uint32_t a;
    asm("{ .reg .u64 t; cvta.to.shared.u64 t, %1; cvt.u32.u64 %0, t; }"
        : "=r"(a) : "l"(p));
    return a;
}
__device__ __forceinline__ void mma_bf16(float* c, const uint32_t* a,
                                         uint32_t b0, uint32_t b1) {
    asm volatile(
        "mma.sync.aligned.m16n8k16.row.col.f32.bf16.bf16.f32 "
        "{%0,%1,%2,%3}, {%4,%5,%6,%7}, {%8,%9}, {%0,%1,%2,%3};"
        : "+f"(c[0]), "+f"(c[1]), "+f"(c[2]), "+f"(c[3])
        : "r"(a[0]), "r"(a[1]), "r"(a[2]), "r"(a[3]), "r"(b0), "r"(b1));
}
__device__ __forceinline__ uint32_t lds32(uint32_t a) {
    uint32_t v;
    asm volatile("ld.shared.b32 %0, [%1];" : "=r"(v) : "r"(a));
    return v;
}
__device__ __forceinline__ void lds128(uint32_t a, uint32_t& x, uint32_t& y,
                                       uint32_t& z, uint32_t& w) {
    asm volatile("ld.shared.v4.b32 {%0,%1,%2,%3}, [%4];"
                 : "=r"(x), "=r"(y), "=r"(z), "=r"(w) : "r"(a));
}
__device__ __forceinline__ void split_bf16(float v, __nv_bfloat16& h, __nv_bfloat16& l) {
    h = __float2bfloat16(v);
    l = __float2bfloat16(v - __bfloat162float(h));
}
__device__ __forceinline__ uint32_t pack2(float a, float b) {
    __nv_bfloat162 t = __floats2bfloat162_rn(a, b);
    return *(uint32_t*)&t;
}
__device__ __forceinline__ float resid(float v) {
    return v - __bfloat162float(__float2bfloat16(v));
}
__device__ __forceinline__ void pack_granule(float f0, float f1, float f2, float f3,
                                             uint32_t* w) {
    __nv_bfloat16 h0,l0,h1,l1,h2,l2,h3,l3;
    split_bf16(f0,h0,l0); split_bf16(f1,h1,l1);
    split_bf16(f2,h2,l2); split_bf16(f3,h3,l3);
    __nv_bfloat162 t;
    t.x=h0; t.y=h1; w[0] = *(uint32_t*)&t;
    t.x=h2; t.y=h3; w[1] = *(uint32_t*)&t;
    t.x=l0; t.y=l1; w[2] = *(uint32_t*)&t;
    t.x=l2; t.y=l3; w[3] = *(uint32_t*)&t;
}

// ------------------------------ prep kernels --------------------------------
__global__ void __launch_bounds__(256) k_prep_xc(const float* __restrict__ x) {
    int gid = blockIdx.x * 256 + threadIdx.x;
    int lc = gid & 3, g = (gid >> 2) % 48;
    int m = gid / 192;
    const float* xr = x + (size_t)m * 768 + g * 16 + lc * 2;
    uint32_t w[4];
    pack_granule(xr[0], xr[1], xr[8], xr[9], w);
    *(uint4*)(g_xc + (size_t)m * 3072 + g * 64 + lc * 16) = *(uint4*)w;
}

__global__ void __launch_bounds__(256) k_prep_wqc(const float* __restrict__ W) {
    int gid = blockIdx.x * 256 + threadIdx.x;
    int lc = gid & 3, g = (gid >> 2) % 48;
    int n = gid / 192;
    int h = n / 192, j = n % 192;
    const float* wb = W + ((size_t)h * 768 + g * 16 + lc * 2) * 192 + j;
    uint32_t w[4];
    pack_granule(wb[0], wb[192], wb[8*192], wb[9*192], w);
    *(uint4*)(g_wqc + (size_t)n * 3072 + g * 64 + lc * 16) = *(uint4*)w;
}

__global__ void __launch_bounds__(256) k_prep_wccT() {
    int gid = blockIdx.x * 256 + threadIdx.x;
    int lc = gid & 3, g = (gid >> 2) % 48;
    int n = gid / 192;
    int k0 = g * 16 + lc * 2;
    uint32_t w[4];
    pack_granule(g_wcomb[(size_t)k0*768 + n],     g_wcomb[(size_t)(k0+1)*768 + n],
                 g_wcomb[(size_t)(k0+8)*768 + n], g_wcomb[(size_t)(k0+9)*768 + n], w);
    *(uint4*)(g_wcc + (size_t)n * 3072 + g * 64 + lc * 16) = *(uint4*)w;
}

// zero g_wcomb + init g_bcomb = bproj
__global__ void __launch_bounds__(256) k_binit(const float* __restrict__ bproj) {
    int idx = blockIdx.x * 256 + threadIdx.x;
    if (idx < C_*C_) g_wcomb[idx] = 0.0f;
    int j = idx - C_*C_;
    if (j >= 0 && j < C_) g_bcomb[j] = bproj[j];
}

__global__ void __launch_bounds__(256) k_bcomb(const float* __restrict__ bph,
                                               const float* __restrict__ Wproj) {
    int r0 = blockIdx.x * 32;
    int t = threadIdx.x;
    float a0 = 0.f, a1 = 0.f, a2 = 0.f;
    for (int rr = 0; rr < 32; ++rr) {
        int r = r0 + rr;
        float bv = bph[r];
        const float* wr = Wproj + (size_t)r * C_;
        a0 = fmaf(bv, wr[t],       a0);
        a1 = fmaf(bv, wr[t + 256], a1);
        a2 = fmaf(bv, wr[t + 512], a2);
    }
    atomicAdd(&g_bcomb[t],       a0);
    atomicAdd(&g_bcomb[t + 256], a1);
    atomicAdd(&g_bcomb[t + 512], a2);
}

// ------- Wcomb precompute: fp32, 4-way K-split, atomic accumulate -----------
__global__ void __launch_bounds__(256) sgemm64ks(
    const float* __restrict__ A, const float* __restrict__ Bm,
    float* __restrict__ Cm)
{
    __shared__ float As[16][68];
    __shared__ float Bs[16][68];
    const int z = blockIdx.z;
    const float* Ab = A  + (size_t)z * 64 * C_;
    const float* Bb = Bm + (size_t)z * C_ * C_;
    float*       Cb = Cm + (size_t)z * 64 * C_;
    const int tid = threadIdx.x;
    const int tx = tid % 16, ty = tid / 16;
    const int n0 = blockIdx.y * 64;
    const int kbeg = blockIdx.x * 192, kend = kbeg + 192;
    float acc[4][4] = {};
    for (int kt = kbeg; kt < kend; kt += 16) {
        {
            int m = tid / 4, kq = (tid % 4) * 4;
            float4 v = *(const float4*)(Ab + (size_t)m*C_ + kt + kq);
            As[kq+0][m] = v.x; As[kq+1][m] = v.y; As[kq+2][m] = v.z; As[kq+3][m] = v.w;
        }
        {
            int kk = tid / 16, nn = (tid % 16) * 4;
            *(float4*)&Bs[kk][nn] = *(const float4*)(Bb + (size_t)(kt+kk)*C_ + n0 + nn);
        }
        __syncthreads();
        #pragma unroll
        for (int k = 0; k < 16; ++k) {
            float a[4], b[4];
            #pragma unroll
            for (int i = 0; i < 4; ++i) a[i] = As[k][ty*4+i];
            *(float4*)b = *(const float4*)&Bs[k][tx*4];
            #pragma unroll
            for (int i = 0; i < 4; ++i)
                #pragma unroll
                for (int j = 0; j < 4; ++j)
                    acc[i][j] = fmaf(a[i], b[j], acc[i][j]);
        }
        __syncthreads();
    }
    #pragma unroll
    for (int i = 0; i < 4; ++i) {
        int m = ty*4 + i;
        #pragma unroll
        for (int j = 0; j < 4; ++j)
            atomicAdd(&Cb[(size_t)m*C_ + n0 + tx*4 + j], acc[i][j]);
    }
}

// ------------------- HMMA bf16-split GEMM (combined v4 layout) --------------
// CSTR=192B = 48 words == 16 (mod 32): LDS.128 phases (lr in {0,1} x lc 0..3)
// cover all 32 banks -> conflict-free. (Verified: 144B stride regressed.)
#define CSTR 192
#define CTILE (128*CSTR)
#define CSTAGE (2*CTILE)
#define HM_SMEM (2*CSTAGE)    // 98304

template<int EPI>
__global__ void __launch_bounds__(256, 2) hmma_gemm(
    const uint8_t* __restrict__ Ac, const uint8_t* __restrict__ Bc,
    float* __restrict__ Cout, const float* __restrict__ bias)
{
    extern __shared__ char smem[];
    const uint32_t sbase = smem_u32(smem);
    const int tid = threadIdx.x;
    const int wid = tid >> 5, ln = tid & 31;
    const int n0 = blockIdx.x * 128, m0 = blockIdx.y * 128;
    const int wm = wid & 3, wn = wid >> 2;
    const int mrow = wm * 32, ncol = wn * 64;
    const int lr = ln >> 2, lc = ln & 3;

    const uint8_t* gA = Ac + (size_t)m0 * 3072;
    const uint8_t* gB = Bc + (size_t)n0 * 3072;

    auto load_chunk = [&](int kc, int stage) {
        uint32_t sb = sbase + stage * CSTAGE;
        const uint8_t* pA = gA + kc * 128;
        const uint8_t* pB = gB + kc * 128;
        #pragma unroll
        for (int i = 0; i < 4; ++i) {
            int gid = tid + i * 256;
            int r = gid >> 3, c = gid & 7;
            asm volatile("cp.async.cg.shared.global [%0], [%1], 16;"
                :: "r"(sb + r*CSTR + c*16), "l"(pA + (size_t)r*3072 + c*16));
        }
        #pragma unroll
        for (int i = 0; i < 4; ++i) {
            int gid = tid + i * 256;
            int r = gid >> 3, c = gid & 7;
            asm volatile("cp.async.cg.shared.global [%0], [%1], 16;"
                :: "r"(sb + CTILE + r*CSTR + c*16), "l"(pB + (size_t)r*3072 + c*16));
        }
        asm volatile("cp.async.commit_group;");
    };

    float acc[2][8][4] = {};
    load_chunk(0, 0);
    for (int c = 0; c < 24; ++c) {
        int s = c & 1;
        asm volatile("cp.async.wait_group 0;");
        __syncthreads();                 // also protects stage s^1 reuse below
        if (c + 1 < 24) load_chunk(c + 1, s ^ 1);

        uint32_t sA = sbase + s * CSTAGE;
        uint32_t sB = sA + CTILE;

        #pragma unroll
        for (int ks = 0; ks < 2; ++ks) {
            uint32_t aH[2][4], aL[2][4];
            #pragma unroll
            for (int mt = 0; mt < 2; ++mt) {
                uint32_t base = sA + (uint32_t)((mrow + mt*16 + lr)*CSTR + ks*64 + lc*16);
                uint32_t x0,y0,z0,w0, x1,y1,z1,w1;
                lds128(base,          x0,y0,z0,w0);
                lds128(base + 8*CSTR, x1,y1,z1,w1);
                aH[mt][0]=x0; aH[mt][1]=x1; aH[mt][2]=y0; aH[mt][3]=y1;
                aL[mt][0]=z0; aL[mt][1]=z1; aL[mt][2]=w0; aL[mt][3]=w1;
            }
            #pragma unroll
            for (int nt = 0; nt < 8; ++nt) {
                uint32_t bb = sB + (uint32_t)((ncol + nt*8 + lr)*CSTR + ks*64 + lc*16);
                uint32_t bh0,bh1,bl0,bl1;
                lds128(bb, bh0,bh1,bl0,bl1);
                #pragma unroll
                for (int mt = 0; mt < 2; ++mt) {
                    mma_bf16(acc[mt][nt], aH[mt], bh0, bh1);
                    mma_bf16(acc[mt][nt], aH[mt], bl0, bl1);
                    mma_bf16(acc[mt][nt], aL[mt], bh0, bh1);
                }
            }
        }
        // no trailing sync: next iteration's barrier protects buffer reuse
    }

    // ------------------------------- epilogue --------------------------------
    #pragma unroll
    for (int mt = 0; mt < 2; ++mt) {
        int m = m0 + mrow + mt*16 + lr;
        #pragma unroll
        for (int nt = 0; nt < 8; ++nt) {
            int n = n0 + ncol + nt*8 + lc*2;
            float b0 = bias[n], b1 = bias[n+1];
            float* ac = acc[mt][nt];
            if (EPI == 0) {
                float2 v0 = {ac[0] + b0, ac[1] + b1};
                float2 v1 = {ac[2] + b0, ac[3] + b1};
                *(float2*)(Cout + (size_t)m * C_ + n) = v0;
                *(float2*)(Cout + (size_t)(m+8) * C_ + n) = v1;
            } else {
                int h = n / 192, r = n % 192;
                int blk = r >> 6, roff = r & 63;
                float sc = (blk == 0) ? QSCALE : 1.0f;
                __nv_bfloat16* dhi = (blk == 0) ? g_qhi : ((blk == 1) ? g_khi : g_vhi);
                __nv_bfloat16* dlo = (blk == 0) ? g_qlo : ((blk == 1) ? g_klo : g_vlo);
                #pragma unroll
                for (int rr = 0; rr < 2; ++rr) {
                    int mm = m + rr*8;
                    int b_ = mm >> 9, t_ = mm & 511;
                    size_t o = (((size_t)b_ * H_ + h) * T_ + t_) * 64 + roff;
                    float v0 = (ac[rr*2+0] + b0) * sc;
                    float v1 = (ac[rr*2+1] + b1) * sc;
                    __nv_bfloat16 h0,h1,l0,l1;
                    split_bf16(v0,h0,l0); split_bf16(v1,h1,l1);
                    __nv_bfloat162 ph; ph.x=h0; ph.y=h1;
                    __nv_bfloat162 pl; pl.x=l0; pl.y=l1;
                    *(__nv_bfloat162*)(dhi + o) = ph;
                    *(__nv_bfloat162*)(dlo + o) = pl;
                }
            }
        }
    }
}

// ------------------------ V transpose: [s][d] -> [d][s] ----------------------
__global__ void __launch_bounds__(256) k_vT() {
    __shared__ __nv_bfloat16 thi[64][72];
    __shared__ __nv_bfloat16 tlo[64][72];
    const int s0 = blockIdx.x * 64;
    const int bh = blockIdx.y;
    const int tid = threadIdx.x;
    const int r = tid >> 2, cs = (tid & 3) * 16;
    const size_t sbase = ((size_t)bh * T_ + s0 + r) * 64 + cs;
    #pragma unroll
    for (int j = 0; j < 2; ++j) {
        *(uint4*)&thi[r][cs + j*8] = *(const uint4*)(g_vhi + sbase + j*8);
        *(uint4*)&tlo[r][cs + j*8] = *(const uint4*)(g_vlo + sbase + j*8);
    }
    __syncthreads();
    const int d = tid >> 2, ss = (tid & 3) * 16;
    const size_t dbase = ((size_t)bh * 64 + d) * T_ + s0 + ss;
    #pragma unroll
    for (int j = 0; j < 2; ++j) {
        uint32_t ph[4], pl[4];
        #pragma unroll
        for (int q = 0; q < 4; ++q) {
            int s = ss + j*8 + q*2;
            __nv_bfloat162 a; a.x = thi[s][d]; a.y = thi[s+1][d];
            ph[q] = *(uint32_t*)&a;
            __nv_bfloat162 b2; b2.x = tlo[s][d]; b2.y = tlo[s+1][d];
            pl[q] = *(uint32_t*)&b2;
        }
        *(uint4*)(g_vthi + dbase + j*8) = *(uint4*)ph;
        *(uint4*)(g_vtlo + dbase + j*8) = *(uint4*)pl;
    }
}

// --------------------------- HMMA fused attention ----------------------------
#define KSTR 144u
#define QSTR 144u
#define VTSTR 1040u
#define SM_K 0u
#define SM_KLO 73728u
#define SM_VT 0u
#define SM_VTLO 66560u
#define SM_Q 147456u
#define SM_QLO 156672u
#define SM_OBUF 147456u
#define OSTRF 72
#define SM_EXM 165888u
#define SM_EXS 166912u
#define ATTN_SMEM 167936

__global__ void __launch_bounds__(512) attn_k(float* __restrict__ probs)
{
    extern __shared__ char smem[];
    const uint32_t sb = smem_u32(smem);
    const int tid = threadIdx.x;
    const int wid = tid >> 5, ln = tid & 31;
    const int wm = wid & 3, wq = wid >> 2;
    const int b = blockIdx.z, h = blockIdx.y, t0 = blockIdx.x * 64;
    const int bh = b * H_ + h;
    const int lr = ln >> 2, lc = ln & 3;

    // ---- load K (full 512) + Q (64 rows), hi/lo ----
    {
        const __nv_bfloat16* khi = g_khi + (size_t)bh * T_ * 64;
        const __nv_bfloat16* klo = g_klo + (size_t)bh * T_ * 64;
        #pragma unroll
        for (int i = 0; i < 8; ++i) {
            int idx = tid + i * 512;
            int r = idx >> 3, sg = idx & 7;
            asm volatile("cp.async.cg.shared.global [%0], [%1], 16;"
                :: "r"(sb + SM_K + r*KSTR + sg*16), "l"(khi + (size_t)r*64 + sg*8));
        }
        #pragma unroll
        for (int i = 0; i < 8; ++i) {
            int idx = tid + i * 512;
            int r = idx >> 3, sg = idx & 7;
            asm volatile("cp.async.cg.shared.global [%0], [%1], 16;"
                :: "r"(sb + SM_KLO + r*KSTR + sg*16), "l"(klo + (size_t)r*64 + sg*8));
        }
        const __nv_bfloat16* qhi = g_qhi + ((size_t)bh * T_ + t0) * 64;
        const __nv_bfloat16* qlo = g_qlo + ((size_t)bh * T_ + t0) * 64;
        {
            int r = tid >> 3, sg = tid & 7;
            asm volatile("cp.async.cg.shared.global [%0], [%1], 16;"
                :: "r"(sb + SM_Q + r*QSTR + sg*16), "l"(qhi + (size_t)r*64 + sg*8));
            asm volatile("cp.async.cg.shared.global [%0], [%1], 16;"
                :: "r"(sb + SM_QLO + r*QSTR + sg*16), "l"(qlo + (size_t)r*64 + sg*8));
        }
        asm volatile("cp.async.commit_group;");
        asm volatile("cp.async.wait_group 0;");
    }
    __syncthreads();

    // ---- Q fragments ----
    uint32_t aH[4][4], aL[4][4];
    {
        const int row = wm * 16 + lr;
        #pragma unroll
        for (int ks = 0; ks < 4; ++ks) {
            uint32_t off = row * QSTR + ks * 32 + lc * 4;
            aH[ks][0] = lds32(sb + SM_Q + off);
            aH[ks][1] = lds32(sb + SM_Q + off + 8*QSTR);
            aH[ks][2] = lds32(sb + SM_Q + off + 16);
            aH[ks][3] = lds32(sb + SM_Q + off + 8*QSTR + 16);
            aL[ks][0] = lds32(sb + SM_QLO + off);
            aL[ks][1] = lds32(sb + SM_QLO + off + 8*QSTR);
            aL[ks][2] = lds32(sb + SM_QLO + off + 16);
            aL[ks][3] = lds32(sb + SM_QLO + off + 8*QSTR + 16);
        }
    }

    // ---- S = Q K^T ----
    float acc[16][4];
    #pragma unroll
    for (int nt = 0; nt < 16; ++nt) { acc[nt][0]=acc[nt][1]=acc[nt][2]=acc[nt][3]=0.f; }
    #pragma unroll
    for (int nt = 0; nt < 16; ++nt) {
        uint32_t krow = (uint32_t)(wq * 128 + nt * 8 + lr);
        #pragma unroll
        for (int ks = 0; ks < 4; ++ks) {
            uint32_t boff = krow * KSTR + ks * 32 + lc * 4;
            uint32_t bh0 = lds32(sb + SM_K + boff);
            uint32_t bh1 = lds32(sb + SM_K + boff + 16);
            uint32_t bl0 = lds32(sb + SM_KLO + boff);
            uint32_t bl1 = lds32(sb + SM_KLO + boff + 16);
            mma_bf16(acc[nt], aH[ks], bh0, bh1);
            mma_bf16(acc[nt], aH[ks], bl0, bl1);
            mma_bf16(acc[nt], aL[ks], bh0, bh1);
        }
    }

    // ---- softmax over 512 keys ----
    const int row0 = wm * 16 + lr;
    {
        float mx0 = -1e30f, mx1 = -1e30f;
        #pragma unroll
        for (int nt = 0; nt < 16; ++nt) {
            mx0 = fmaxf(mx0, fmaxf(acc[nt][0], acc[nt][1]));
            mx1 = fmaxf(mx1, fmaxf(acc[nt][2], acc[nt][3]));
        }
        mx0 = fmaxf(mx0, __shfl_xor_sync(0xffffffffu, mx0, 1));
        mx0 = fmaxf(mx0, __shfl_xor_sync(0xffffffffu, mx0, 2));
        mx1 = fmaxf(mx1, __shfl_xor_sync(0xffffffffu, mx1, 1));
        mx1 = fmaxf(mx1, __shfl_xor_sync(0xffffffffu, mx1, 2));
        float* exm = (float*)(smem + SM_EXM);
        if (lc == 0) { exm[wq*64 + row0] = mx0; exm[wq*64 + row0 + 8] = mx1; }
        __syncthreads();     // all warps past S MMAs -> K region dead

        // ---- prefetch VT into K region ----
        {
            const __nv_bfloat16* vthi = g_vthi + (size_t)bh * 64 * T_;
            const __nv_bfloat16* vtlo = g_vtlo + (size_t)bh * 64 * T_;
            #pragma unroll
            for (int i = 0; i < 8; ++i) {
                int idx = tid + i * 512;
                int d = idx >> 6, sg = idx & 63;
                asm volatile("cp.async.cg.shared.global [%0], [%1], 16;"
                    :: "r"(sb + SM_VT + d*VTSTR + sg*16), "l"(vthi + (size_t)d*T_ + sg*8));
            }
            #pragma unroll
            for (int i = 0; i < 8; ++i) {
                int idx = tid + i * 512;
                int d = idx >> 6, sg = idx & 63;
                asm volatile("cp.async.cg.shared.global [%0], [%1], 16;"
                    :: "r"(sb + SM_VTLO + d*VTSTR + sg*16), "l"(vtlo + (size_t)d*T_ + sg*8));
            }
            asm volatile("cp.async.commit_group;");
        }

        float m0 = fmaxf(fmaxf(exm[row0],      exm[64+row0]),
                         fmaxf(exm[128+row0],  exm[192+row0]));
        float m1 = fmaxf(fmaxf(exm[row0+8],    exm[64+row0+8]),
                         fmaxf(exm[128+row0+8],exm[192+row0+8]));
        float s0 = 0.f, s1 = 0.f;
        #pragma unroll
        for (int nt = 0; nt < 16; ++nt) {
            acc[nt][0] = __expf(acc[nt][0] - m0); s0 += acc[nt][0];
            acc[nt][1] = __expf(acc[nt][1] - m0); s0 += acc[nt][1];
            acc[nt][2] = __expf(acc[nt][2] - m1); s1 += acc[nt][2];
            acc[nt][3] = __expf(acc[nt][3] - m1); s1 += acc[nt][3];
        }
        s0 += __shfl_xor_sync(0xffffffffu, s0, 1);
        s0 += __shfl_xor_sync(0xffffffffu, s0, 2);
        s1 += __shfl_xor_sync(0xffffffffu, s1, 1);
        s1 += __shfl_xor_sync(0xffffffffu, s1, 2);
        float* exs = (float*)(smem + SM_EXS);
        if (lc == 0) { exs[wq*64 + row0] = s0; exs[wq*64 + row0 + 8] = s1; }
        __syncthreads();
        float inv0 = 1.0f / (exs[row0] + exs[64+row0] + exs[128+row0] + exs[192+row0]);
        float inv1 = 1.0f / (exs[row0+8] + exs[64+row0+8] + exs[128+row0+8] + exs[192+row0+8]);
        #pragma unroll
        for (int nt = 0; nt < 16; ++nt) {
            acc[nt][0] *= inv0; acc[nt][1] *= inv0;
            acc[nt][2] *= inv1; acc[nt][3] *= inv1;
        }
    }

    // ---- wait VT, then PV with probs stores interleaved ----
    asm volatile("cp.async.wait_group 0;");
    __syncthreads();

    float* p0 = probs + ((size_t)bh * T_ + t0 + row0) * 512 + wq*128 + lc*2;
    float* p1 = p0 + (size_t)8 * 512;

    float oacc[8][4];
    #pragma unroll
    for (int dn = 0; dn < 8; ++dn) { oacc[dn][0]=oacc[dn][1]=oacc[dn][2]=oacc[dn][3]=0.f; }
    #pragma unroll
    for (int kk = 0; kk < 8; ++kk) {
        uint32_t phi[4], plo[4];
        phi[0] = pack2(acc[2*kk][0],   acc[2*kk][1]);
        phi[1] = pack2(acc[2*kk][2],   acc[2*kk][3]);
        phi[2] = pack2(acc[2*kk+1][0], acc[2*kk+1][1]);
        phi[3] = pack2(acc[2*kk+1][2], acc[2*kk+1][3]);
        plo[0] = pack2(resid(acc[2*kk][0]),   resid(acc[2*kk][1]));
        plo[1] = pack2(resid(acc[2*kk][2]),   resid(acc[2*kk][3]));
        plo[2] = pack2(resid(acc[2*kk+1][0]), resid(acc[2*kk+1][1]));
        plo[3] = pack2(resid(acc[2*kk+1][2]), resid(acc[2*kk+1][3]));
        // interleaved probs stores (overlap STG with tensor work)
        {
            float2 v00 = {acc[2*kk][0],   acc[2*kk][1]};
            float2 v01 = {acc[2*kk][2],   acc[2*kk][3]};
            float2 v10 = {acc[2*kk+1][0], acc[2*kk+1][1]};
            float2 v11 = {acc[2*kk+1][2], acc[2*kk+1][3]};
            *(float2*)(p0 + (2*kk)*8)   = v00;
            *(float2*)(p1 + (2*kk)*8)   = v01;
            *(float2*)(p0 + (2*kk+1)*8) = v10;
            *(float2*)(p1 + (2*kk+1)*8) = v11;
        }
        uint32_t colV = (uint32_t)((wq*128 + kk*16 + lc*2) * 2);
        #pragma unroll
        for (int dn = 0; dn < 8; ++dn) {
            uint32_t vrow = (uint32_t)(dn*8 + lr);
            uint32_t offH = vrow * VTSTR + colV;
            uint32_t bh0 = lds32(sb + SM_VT + offH);
            uint32_t bh1 = lds32(sb + SM_VT + offH + 16);
            uint32_t bl0 = lds32(sb + SM_VTLO + offH);
            uint32_t bl1 = lds32(sb + SM_VTLO + offH + 16);
            mma_bf16(oacc[dn], phi, bh0, bh1);
            mma_bf16(oacc[dn], phi, bl0, bl1);
            mma_bf16(oacc[dn], plo, bh0, bh1);
        }
    }

    // ---- cross-warp reduce ----
    float* obuf = (float*)(smem + SM_OBUF);
    #pragma unroll
    for (int g = 0; g < 4; ++g) {
        if (wq == g) {
            #pragma unroll
            for (int dn = 0; dn < 8; ++dn) {
                int c = dn*8 + lc*2;
                float* b0 = obuf + row0 * OSTRF + c;
                float* b1 = obuf + (row0 + 8) * OSTRF + c;
                if (g == 0) {
                    b0[0] = oacc[dn][0]; b0[1] = oacc[dn][1];
                    b1[0] = oacc[dn][2]; b1[1] = oacc[dn][3];
                } else {
                    b0[0] += oacc[dn][0]; b0[1] += oacc[dn][1];
                    b1[0] += oacc[dn][2]; b1[1] += oacc[dn][3];
                }
            }
        }
        __syncthreads();
    }

    // ---- write O in combined layout for OUT gemm ----
    {
        int row = tid >> 3, s2 = tid & 7;
        const float* src = obuf + row * OSTRF;
        size_t rb = ((size_t)b * T_ + t0 + row) * 3072 + (size_t)h * 256;
        #pragma unroll
        for (int u = 0; u < 2; ++u) {
            int s = s2 * 2 + u;
            int g = s >> 2, lcx = s & 3;
            int k0 = g * 16 + lcx * 2;
            uint32_t w[4];
            pack_granule(src[k0], src[k0+1], src[k0+8], src[k0+9], w);
            *(uint4*)(g_oc + rb + g*64 + lcx*16) = *(uint4*)w;
        }
    }
}

// --------------------------------- launcher ---------------------------------
extern "C" void kernel_launch(void* const* d_in, const int* in_sizes, int n_in,
                              void* d_out, int out_size)
{
    const float* x     = (const float*)d_in[0];
    const float* Wqkv  = (const float*)d_in[1];
    const float* bqkv  = (const float*)d_in[2];
    const float* Wph   = (const float*)d_in[3];
    const float* bph   = (const float*)d_in[4];
    const float* Wproj = (const float*)d_in[5];
    const float* bproj = (const float*)d_in[6];
    float* out = (float*)d_out;
    float* sa_out = out;
    float* probs  = out + (size_t)BT_*C_;

    uint8_t *xc_p, *wqc_p, *oc_p, *wcc_p;
    float *wcomb_p, *bcomb_p;
    cudaGetSymbolAddress((void**)&xc_p,   g_xc);
    cudaGetSymbolAddress((void**)&wqc_p,  g_wqc);
    cudaGetSymbolAddress((void**)&oc_p,   g_oc);
    cudaGetSymbolAddress((void**)&wcc_p,  g_wcc);
    cudaGetSymbolAddress((void**)&wcomb_p, g_wcomb);
    cudaGetSymbolAddress((void**)&bcomb_p, g_bcomb);

    static int attrs_set = 0;
    if (!attrs_set) {
        cudaFuncSetAttribute(hmma_gemm<0>, cudaFuncAttributeMaxDynamicSharedMemorySize, HM_SMEM);
        cudaFuncSetAttribute(hmma_gemm<1>, cudaFuncAttributeMaxDynamicSharedMemorySize, HM_SMEM);
        cudaFuncSetAttribute(attn_k, cudaFuncAttributeMaxDynamicSharedMemorySize, ATTN_SMEM);
        attrs_set = 1;
    }

    // 1-3: prep on QKV critical path (+ wcomb zero / bcomb init)
    k_prep_xc<<<BT_*192/256, 256>>>(x);
    k_prep_wqc<<<NQKV_*192/256, 256>>>(Wqkv);
    k_binit<<<(C_*C_ + C_ + 255)/256, 256>>>(bproj);

    // 4: QKV GEMM (profiled slot) -> q/k/v bf16 hi/lo
    hmma_gemm<1><<<dim3(NQKV_/128, BT_/128), 256, HM_SMEM>>>(
        xc_p, wqc_p, nullptr, bqkv);

    // 5-7: Wcomb chain (independent of attention)
    k_bcomb<<<288, 256>>>(bph, Wproj);
    sgemm64ks<<<dim3(4, 12, 12), 256>>>(Wph, Wproj, wcomb_p);
    k_prep_wccT<<<C_*192/256, 256>>>();

    // 8: V transpose
    k_vT<<<dim3(T_/64, B_*H_), 256>>>();

    // 9: fused attention -> probs + O(combined)
    attn_k<<<dim3(T_/64, H_, B_), 512, ATTN_SMEM>>>(probs);

    // 10: output GEMM + bcomb -> sa_out
    hmma_gemm<0><<<dim3(C_/128, BT_/128), 256, HM_SMEM>>>(
        oc_p, wcc_p, sa_out, bcomb_p);
}

// round 12
// speedup vs baseline: 1.5961x; 1.3472x over previous
#include <cuda_runtime.h>
#include <cuda_fp16.h>
#include <stdint.h>
#include <math.h>

#define H_   12
#define T_   512
#define D_   64
#define C_   768
#define B_   32
#define NQKV_ 2304
#define BT_  16384
#define BHTD_ ((size_t)B_*H_*T_*D_)
#define QSCALE 0.125f

// ------------- device-global scratch (no runtime alloc allowed) -------------
// combined granule: 16B = [hi(k),hi(k+1),hi(k+8),hi(k+9) | lo(same 4)]  (fp16)
__device__ __align__(16) uint8_t g_xc[(size_t)BT_*3072];
__device__ __align__(16) uint8_t g_wqc[(size_t)NQKV_*3072];
__device__ __align__(16) uint8_t g_oc[(size_t)BT_*3072];
__device__ __align__(16) uint8_t g_wcc[(size_t)C_*3072];
__device__ __align__(16) __half g_qhi[BHTD_];
__device__ __align__(16) __half g_qlo[BHTD_];
__device__ __align__(16) __half g_khi[BHTD_];
__device__ __align__(16) __half g_vhi[BHTD_];
__device__ __align__(16) __half g_vthi[BHTD_];   // [b,h,d,s]
__device__ __align__(16) float g_wcomb[C_*C_];
__device__ __align__(16) float g_bcomb[C_];

// ------------------------------ helpers -------------------------------------
__device__ __forceinline__ uint32_t smem_u32(const void* p) {
    uint32_t a;
    asm("{ .reg .u64 t; cvta.to.shared.u64 t, %1; cvt.u32.u64 %0, t; }"
        : "=r"(a) : "l"(p));
    return a;
}
__device__ __forceinline__ void mma_f16(float* c, const uint32_t* a,
                                        uint32_t b0, uint32_t b1) {
    asm volatile(
        "mma.sync.aligned.m16n8k16.row.col.f32.f16.f16.f32 "
        "{%0,%1,%2,%3}, {%4,%5,%6,%7}, {%8,%9}, {%0,%1,%2,%3};"
        : "+f"(c[0]), "+f"(c[1]), "+f"(c[2]), "+f"(c[3])
        : "r"(a[0]), "r"(a[1]), "r"(a[2]), "r"(a[3]), "r"(b0), "r"(b1));
}
__device__ __forceinline__ uint32_t lds32(uint32_t a) {
    uint32_t v;
    asm volatile("ld.shared.b32 %0, [%1];" : "=r"(v) : "r"(a));
    return v;
}
__device__ __forceinline__ void lds128(uint32_t a, uint32_t& x, uint32_t& y,
                                       uint32_t& z, uint32_t& w) {
    asm volatile("ld.shared.v4.b32 {%0,%1,%2,%3}, [%4];"
                 : "=r"(x), "=r"(y), "=r"(z), "=r"(w) : "r"(a));
}
__device__ __forceinline__ void split_h(float v, __half& h, __half& l) {
    h = __float2half_rn(v);
    l = __float2half_rn(v - __half2float(h));
}
__device__ __forceinline__ uint32_t pack2h(float a, float b) {
    __half2 t = __floats2half2_rn(a, b);
    return *(uint32_t*)&t;
}
__device__ __forceinline__ float residh(float v) {
    return v - __half2float(__float2half_rn(v));
}
__device__ __forceinline__ void pack_granule(float f0, float f1, float f2, float f3,
                                             uint32_t* w) {
    __half h0,l0,h1,l1,h2,l2,h3,l3;
    split_h(f0,h0,l0); split_h(f1,h1,l1);
    split_h(f2,h2,l2); split_h(f3,h3,l3);
    __half2 t;
    t.x=h0; t.y=h1; w[0] = *(uint32_t*)&t;
    t.x=h2; t.y=h3; w[1] = *(uint32_t*)&t;
    t.x=l0; t.y=l1; w[2] = *(uint32_t*)&t;
    t.x=l2; t.y=l3; w[3] = *(uint32_t*)&t;
}

// ------------------------------ prep kernels --------------------------------
__global__ void __launch_bounds__(256) k_prep_xc(const float* __restrict__ x) {
    int gid = blockIdx.x * 256 + threadIdx.x;
    int lc = gid & 3, g = (gid >> 2) % 48;
    int m = gid / 192;
    const float* xr = x + (size_t)m * 768 + g * 16 + lc * 2;
    uint32_t w[4];
    pack_granule(xr[0], xr[1], xr[8], xr[9], w);
    *(uint4*)(g_xc + (size_t)m * 3072 + g * 64 + lc * 16) = *(uint4*)w;
}

__global__ void __launch_bounds__(256) k_prep_wqc(const float* __restrict__ W) {
    int gid = blockIdx.x * 256 + threadIdx.x;
    int lc = gid & 3, g = (gid >> 2) % 48;
    int n = gid / 192;
    int h = n / 192, j = n % 192;
    const float* wb = W + ((size_t)h * 768 + g * 16 + lc * 2) * 192 + j;
    uint32_t w[4];
    pack_granule(wb[0], wb[192], wb[8*192], wb[9*192], w);
    *(uint4*)(g_wqc + (size_t)n * 3072 + g * 64 + lc * 16) = *(uint4*)w;
}

__global__ void __launch_bounds__(256) k_prep_wccT() {
    int gid = blockIdx.x * 256 + threadIdx.x;
    int lc = gid & 3, g = (gid >> 2) % 48;
    int n = gid / 192;
    int k0 = g * 16 + lc * 2;
    uint32_t w[4];
    pack_granule(g_wcomb[(size_t)k0*768 + n],     g_wcomb[(size_t)(k0+1)*768 + n],
                 g_wcomb[(size_t)(k0+8)*768 + n], g_wcomb[(size_t)(k0+9)*768 + n], w);
    *(uint4*)(g_wcc + (size_t)n * 3072 + g * 64 + lc * 16) = *(uint4*)w;
}

// zero g_wcomb + init g_bcomb = bproj
__global__ void __launch_bounds__(256) k_binit(const float* __restrict__ bproj) {
    int idx = blockIdx.x * 256 + threadIdx.x;
    if (idx < C_*C_) g_wcomb[idx] = 0.0f;
    int j = idx - C_*C_;
    if (j >= 0 && j < C_) g_bcomb[j] = bproj[j];
}

__global__ void __launch_bounds__(256) k_bcomb(const float* __restrict__ bph,
                                               const float* __restrict__ Wproj) {
    int r0 = blockIdx.x * 32;
    int t = threadIdx.x;
    float a0 = 0.f, a1 = 0.f, a2 = 0.f;
    for (int rr = 0; rr < 32; ++rr) {
        int r = r0 + rr;
        float bv = bph[r];
        const float* wr = Wproj + (size_t)r * C_;
        a0 = fmaf(bv, wr[t],       a0);
        a1 = fmaf(bv, wr[t + 256], a1);
        a2 = fmaf(bv, wr[t + 512], a2);
    }
    atomicAdd(&g_bcomb[t],       a0);
    atomicAdd(&g_bcomb[t + 256], a1);
    atomicAdd(&g_bcomb[t + 512], a2);
}

// ------- Wcomb precompute: fp32, 4-way K-split, atomic accumulate -----------
__global__ void __launch_bounds__(256) sgemm64ks(
    const float* __restrict__ A, const float* __restrict__ Bm,
    float* __restrict__ Cm)
{
    __shared__ float As[16][68];
    __shared__ float Bs[16][68];
    const int z = blockIdx.z;
    const float* Ab = A  + (size_t)z * 64 * C_;
    const float* Bb = Bm + (size_t)z * C_ * C_;
    float*       Cb = Cm + (size_t)z * 64 * C_;
    const int tid = threadIdx.x;
    const int tx = tid % 16, ty = tid / 16;
    const int n0 = blockIdx.y * 64;
    const int kbeg = blockIdx.x * 192, kend = kbeg + 192;
    float acc[4][4] = {};
    for (int kt = kbeg; kt < kend; kt += 16) {
        {
            int m = tid / 4, kq = (tid % 4) * 4;
            float4 v = *(const float4*)(Ab + (size_t)m*C_ + kt + kq);
            As[kq+0][m] = v.x; As[kq+1][m] = v.y; As[kq+2][m] = v.z; As[kq+3][m] = v.w;
        }
        {
            int kk = tid / 16, nn = (tid % 16) * 4;
            *(float4*)&Bs[kk][nn] = *(const float4*)(Bb + (size_t)(kt+kk)*C_ + n0 + nn);
        }
        __syncthreads();
        #pragma unroll
        for (int k = 0; k < 16; ++k) {
            float a[4], b[4];
            #pragma unroll
            for (int i = 0; i < 4; ++i) a[i] = As[k][ty*4+i];
            *(float4*)b = *(const float4*)&Bs[k][tx*4];
            #pragma unroll
            for (int i = 0; i < 4; ++i)
                #pragma unroll
                for (int j = 0; j < 4; ++j)
                    acc[i][j] = fmaf(a[i], b[j], acc[i][j]);
        }
        __syncthreads();
    }
    #pragma unroll
    for (int i = 0; i < 4; ++i) {
        int m = ty*4 + i;
        #pragma unroll
        for (int j = 0; j < 4; ++j)
            atomicAdd(&Cb[(size_t)m*C_ + n0 + tx*4 + j], acc[i][j]);
    }
}

// ------------------- HMMA fp16 2-term GEMM (combined v4 layout) -------------
// CSTR=192B conflict-free (measured). D = (Ah+Al)·Bh: 64 MMAs/warp-chunk.
#define CSTR 192
#define CTILE (128*CSTR)
#define CSTAGE (2*CTILE)
#define HM_SMEM (2*CSTAGE)    // 98304

template<int EPI>
__global__ void __launch_bounds__(256, 2) hmma_gemm(
    const uint8_t* __restrict__ Ac, const uint8_t* __restrict__ Bc,
    float* __restrict__ Cout, const float* __restrict__ bias)
{
    extern __shared__ char smem[];
    const uint32_t sbase = smem_u32(smem);
    const int tid = threadIdx.x;
    const int wid = tid >> 5, ln = tid & 31;
    const int n0 = blockIdx.x * 128, m0 = blockIdx.y * 128;
    const int wm = wid & 3, wn = wid >> 2;
    const int mrow = wm * 32, ncol = wn * 64;
    const int lr = ln >> 2, lc = ln & 3;

    const uint8_t* gA = Ac + (size_t)m0 * 3072;
    const uint8_t* gB = Bc + (size_t)n0 * 3072;

    auto load_chunk = [&](int kc, int stage) {
        uint32_t sb = sbase + stage * CSTAGE;
        const uint8_t* pA = gA + kc * 128;
        const uint8_t* pB = gB + kc * 128;
        #pragma unroll
        for (int i = 0; i < 4; ++i) {
            int gid = tid + i * 256;
            int r = gid >> 3, c = gid & 7;
            asm volatile("cp.async.cg.shared.global [%0], [%1], 16;"
                :: "r"(sb + r*CSTR + c*16), "l"(pA + (size_t)r*3072 + c*16));
        }
        #pragma unroll
        for (int i = 0; i < 4; ++i) {
            int gid = tid + i * 256;
            int r = gid >> 3, c = gid & 7;
            asm volatile("cp.async.cg.shared.global [%0], [%1], 16;"
                :: "r"(sb + CTILE + r*CSTR + c*16), "l"(pB + (size_t)r*3072 + c*16));
        }
        asm volatile("cp.async.commit_group;");
    };

    float acc[2][8][4] = {};
    load_chunk(0, 0);
    for (int c = 0; c < 24; ++c) {
        int s = c & 1;
        asm volatile("cp.async.wait_group 0;");
        __syncthreads();                 // also protects stage s^1 reuse below
        if (c + 1 < 24) load_chunk(c + 1, s ^ 1);

        uint32_t sA = sbase + s * CSTAGE;
        uint32_t sB = sA + CTILE;

        #pragma unroll
        for (int ks = 0; ks < 2; ++ks) {
            uint32_t aH[2][4], aL[2][4];
            #pragma unroll
            for (int mt = 0; mt < 2; ++mt) {
                uint32_t base = sA + (uint32_t)((mrow + mt*16 + lr)*CSTR + ks*64 + lc*16);
                uint32_t x0,y0,z0,w0, x1,y1,z1,w1;
                lds128(base,          x0,y0,z0,w0);
                lds128(base + 8*CSTR, x1,y1,z1,w1);
                aH[mt][0]=x0; aH[mt][1]=x1; aH[mt][2]=y0; aH[mt][3]=y1;
                aL[mt][0]=z0; aL[mt][1]=z1; aL[mt][2]=w0; aL[mt][3]=w1;
            }
            #pragma unroll
            for (int nt = 0; nt < 8; ++nt) {
                uint32_t bb = sB + (uint32_t)((ncol + nt*8 + lr)*CSTR + ks*64 + lc*16);
                uint32_t bh0,bh1,bl0,bl1;
                lds128(bb, bh0,bh1,bl0,bl1);
                #pragma unroll
                for (int mt = 0; mt < 2; ++mt) {
                    mma_f16(acc[mt][nt], aH[mt], bh0, bh1);
                    mma_f16(acc[mt][nt], aL[mt], bh0, bh1);
                }
            }
        }
        // no trailing sync: next iteration's barrier protects buffer reuse
    }

    // ------------------------------- epilogue --------------------------------
    #pragma unroll
    for (int mt = 0; mt < 2; ++mt) {
        int m = m0 + mrow + mt*16 + lr;
        #pragma unroll
        for (int nt = 0; nt < 8; ++nt) {
            int n = n0 + ncol + nt*8 + lc*2;
            float b0 = bias[n], b1 = bias[n+1];
            float* ac = acc[mt][nt];
            if (EPI == 0) {
                float2 v0 = {ac[0] + b0, ac[1] + b1};
                float2 v1 = {ac[2] + b0, ac[3] + b1};
                *(float2*)(Cout + (size_t)m * C_ + n) = v0;
                *(float2*)(Cout + (size_t)(m+8) * C_ + n) = v1;
            } else {
                int h = n / 192, r = n % 192;
                int blk = r >> 6, roff = r & 63;
                #pragma unroll
                for (int rr = 0; rr < 2; ++rr) {
                    int mm = m + rr*8;
                    int b_ = mm >> 9, t_ = mm & 511;
                    size_t o = (((size_t)b_ * H_ + h) * T_ + t_) * 64 + roff;
                    if (blk == 0) {
                        float v0 = (ac[rr*2+0] + b0) * QSCALE;
                        float v1 = (ac[rr*2+1] + b1) * QSCALE;
                        __half h0,h1,l0,l1;
                        split_h(v0,h0,l0); split_h(v1,h1,l1);
                        __half2 ph; ph.x=h0; ph.y=h1;
                        __half2 pl; pl.x=l0; pl.y=l1;
                        *(__half2*)(g_qhi + o) = ph;
                        *(__half2*)(g_qlo + o) = pl;
                    } else {
                        __half* dst = (blk == 1) ? g_khi : g_vhi;
                        __half2 ph = __floats2half2_rn(ac[rr*2+0] + b0, ac[rr*2+1] + b1);
                        *(__half2*)(dst + o) = ph;
                    }
                }
            }
        }
    }
}

// ------------------------ V transpose: [s][d] -> [d][s] ----------------------
__global__ void __launch_bounds__(256) k_vT() {
    __shared__ __half thi[64][72];
    const int s0 = blockIdx.x * 64;
    const int bh = blockIdx.y;
    const int tid = threadIdx.x;
    const int r = tid >> 2, cs = (tid & 3) * 16;
    const size_t sbase = ((size_t)bh * T_ + s0 + r) * 64 + cs;
    #pragma unroll
    for (int j = 0; j < 2; ++j)
        *(uint4*)&thi[r][cs + j*8] = *(const uint4*)(g_vhi + sbase + j*8);
    __syncthreads();
    const int d = tid >> 2, ss = (tid & 3) * 16;
    const size_t dbase = ((size_t)bh * 64 + d) * T_ + s0 + ss;
    #pragma unroll
    for (int j = 0; j < 2; ++j) {
        uint32_t ph[4];
        #pragma unroll
        for (int q = 0; q < 4; ++q) {
            int s = ss + j*8 + q*2;
            __half2 a; a.x = thi[s][d]; a.y = thi[s+1][d];
            ph[q] = *(uint32_t*)&a;
        }
        *(uint4*)(g_vthi + dbase + j*8) = *(uint4*)ph;
    }
}

// --------------------------- HMMA fused attention ----------------------------
// K/VT single-fp16 (B-side); Q split hi/lo (A-side). 94 KB smem.
#define KSTR 144u
#define QSTR 144u
#define VTSTR 1040u
#define SM_K 0u            // 512*144 = 73728
#define SM_VT 0u           // 64*1040 = 66560 (overlays K)
#define SM_Q 73728u        // 64*144 = 9216
#define SM_QLO 82944u      // 9216
#define SM_OBUF 73728u     // 18432 (overlays Q after fragments in regs)
#define OSTRF 72
#define SM_EXM 92160u
#define SM_EXS 93184u
#define ATTN_SMEM 94208

__global__ void __launch_bounds__(512) attn_k(float* __restrict__ probs)
{
    extern __shared__ char smem[];
    const uint32_t sb = smem_u32(smem);
    const int tid = threadIdx.x;
    const int wid = tid >> 5, ln = tid & 31;
    const int wm = wid & 3, wq = wid >> 2;
    const int b = blockIdx.z, h = blockIdx.y, t0 = blockIdx.x * 64;
    const int bh = b * H_ + h;
    const int lr = ln >> 2, lc = ln & 3;

    // ---- load K (512 rows, hi only) + Q (64 rows, hi+lo) ----
    {
        const __half* khi = g_khi + (size_t)bh * T_ * 64;
        #pragma unroll
        for (int i = 0; i < 8; ++i) {
            int idx = tid + i * 512;
            int r = idx >> 3, sg = idx & 7;
            asm volatile("cp.async.cg.shared.global [%0], [%1], 16;"
                :: "r"(sb + SM_K + r*KSTR + sg*16), "l"(khi + (size_t)r*64 + sg*8));
        }
        const __half* qhi = g_qhi + ((size_t)bh * T_ + t0) * 64;
        const __half* qlo = g_qlo + ((size_t)bh * T_ + t0) * 64;
        {
            int r = tid >> 3, sg = tid & 7;
            asm volatile("cp.async.cg.shared.global [%0], [%1], 16;"
                :: "r"(sb + SM_Q + r*QSTR + sg*16), "l"(qhi + (size_t)r*64 + sg*8));
            asm volatile("cp.async.cg.shared.global [%0], [%1], 16;"
                :: "r"(sb + SM_QLO + r*QSTR + sg*16), "l"(qlo + (size_t)r*64 + sg*8));
        }
        asm volatile("cp.async.commit_group;");
        asm volatile("cp.async.wait_group 0;");
    }
    __syncthreads();

    // ---- Q fragments ----
    uint32_t aH[4][4], aL[4][4];
    {
        const int row = wm * 16 + lr;
        #pragma unroll
        for (int ks = 0; ks < 4; ++ks) {
            uint32_t off = row * QSTR + ks * 32 + lc * 4;
            aH[ks][0] = lds32(sb + SM_Q + off);
            aH[ks][1] = lds32(sb + SM_Q + off + 8*QSTR);
            aH[ks][2] = lds32(sb + SM_Q + off + 16);
            aH[ks][3] = lds32(sb + SM_Q + off + 8*QSTR + 16);
            aL[ks][0] = lds32(sb + SM_QLO + off);
            aL[ks][1] = lds32(sb + SM_QLO + off + 8*QSTR);
            aL[ks][2] = lds32(sb + SM_QLO + off + 16);
            aL[ks][3] = lds32(sb + SM_QLO + off + 8*QSTR + 16);
        }
    }

    // ---- S = Q K^T  (2 MMAs per step) ----
    float acc[16][4];
    #pragma unroll
    for (int nt = 0; nt < 16; ++nt) { acc[nt][0]=acc[nt][1]=acc[nt][2]=acc[nt][3]=0.f; }
    #pragma unroll
    for (int nt = 0; nt < 16; ++nt) {
        uint32_t krow = (uint32_t)(wq * 128 + nt * 8 + lr);
        #pragma unroll
        for (int ks = 0; ks < 4; ++ks) {
            uint32_t boff = krow * KSTR + ks * 32 + lc * 4;
            uint32_t bh0 = lds32(sb + SM_K + boff);
            uint32_t bh1 = lds32(sb + SM_K + boff + 16);
            mma_f16(acc[nt], aH[ks], bh0, bh1);
            mma_f16(acc[nt], aL[ks], bh0, bh1);
        }
    }

    // ---- softmax over 512 keys ----
    const int row0 = wm * 16 + lr;
    {
        float mx0 = -1e30f, mx1 = -1e30f;
        #pragma unroll
        for (int nt = 0; nt < 16; ++nt) {
            mx0 = fmaxf(mx0, fmaxf(acc[nt][0], acc[nt][1]));
            mx1 = fmaxf(mx1, fmaxf(acc[nt][2], acc[nt][3]));
        }
        mx0 = fmaxf(mx0, __shfl_xor_sync(0xffffffffu, mx0, 1));
        mx0 = fmaxf(mx0, __shfl_xor_sync(0xffffffffu, mx0, 2));
        mx1 = fmaxf(mx1, __shfl_xor_sync(0xffffffffu, mx1, 1));
        mx1 = fmaxf(mx1, __shfl_xor_sync(0xffffffffu, mx1, 2));
        float* exm = (float*)(smem + SM_EXM);
        if (lc == 0) { exm[wq*64 + row0] = mx0; exm[wq*64 + row0 + 8] = mx1; }
        __syncthreads();     // all warps past S MMAs -> K region dead

        // ---- prefetch VT (hi only) into K region ----
        {
            const __half* vthi = g_vthi + (size_t)bh * 64 * T_;
            #pragma unroll
            for (int i = 0; i < 8; ++i) {
                int idx = tid + i * 512;
                int d = idx >> 6, sg = idx & 63;
                asm volatile("cp.async.cg.shared.global [%0], [%1], 16;"
                    :: "r"(sb + SM_VT + d*VTSTR + sg*16), "l"(vthi + (size_t)d*T_ + sg*8));
            }
            asm volatile("cp.async.commit_group;");
        }

        float m0 = fmaxf(fmaxf(exm[row0],      exm[64+row0]),
                         fmaxf(exm[128+row0],  exm[192+row0]));
        float m1 = fmaxf(fmaxf(exm[row0+8],    exm[64+row0+8]),
                         fmaxf(exm[128+row0+8],exm[192+row0+8]));
        float s0 = 0.f, s1 = 0.f;
        #pragma unroll
        for (int nt = 0; nt < 16; ++nt) {
            acc[nt][0] = __expf(acc[nt][0] - m0); s0 += acc[nt][0];
            acc[nt][1] = __expf(acc[nt][1] - m0); s0 += acc[nt][1];
            acc[nt][2] = __expf(acc[nt][2] - m1); s1 += acc[nt][2];
            acc[nt][3] = __expf(acc[nt][3] - m1); s1 += acc[nt][3];
        }
        s0 += __shfl_xor_sync(0xffffffffu, s0, 1);
        s0 += __shfl_xor_sync(0xffffffffu, s0, 2);
        s1 += __shfl_xor_sync(0xffffffffu, s1, 1);
        s1 += __shfl_xor_sync(0xffffffffu, s1, 2);
        float* exs = (float*)(smem + SM_EXS);
        if (lc == 0) { exs[wq*64 + row0] = s0; exs[wq*64 + row0 + 8] = s1; }
        __syncthreads();
        float inv0 = 1.0f / (exs[row0] + exs[64+row0] + exs[128+row0] + exs[192+row0]);
        float inv1 = 1.0f / (exs[row0+8] + exs[64+row0+8] + exs[128+row0+8] + exs[192+row0+8]);
        #pragma unroll
        for (int nt = 0; nt < 16; ++nt) {
            acc[nt][0] *= inv0; acc[nt][1] *= inv0;
            acc[nt][2] *= inv1; acc[nt][3] *= inv1;
        }
    }

    // ---- wait VT, then PV with probs stores interleaved ----
    asm volatile("cp.async.wait_group 0;");
    __syncthreads();

    float* p0 = probs + ((size_t)bh * T_ + t0 + row0) * 512 + wq*128 + lc*2;
    float* p1 = p0 + (size_t)8 * 512;

    float oacc[8][4];
    #pragma unroll
    for (int dn = 0; dn < 8; ++dn) { oacc[dn][0]=oacc[dn][1]=oacc[dn][2]=oacc[dn][3]=0.f; }
    #pragma unroll
    for (int kk = 0; kk < 8; ++kk) {
        uint32_t phi[4], plo[4];
        phi[0] = pack2h(acc[2*kk][0],   acc[2*kk][1]);
        phi[1] = pack2h(acc[2*kk][2],   acc[2*kk][3]);
        phi[2] = pack2h(acc[2*kk+1][0], acc[2*kk+1][1]);
        phi[3] = pack2h(acc[2*kk+1][2], acc[2*kk+1][3]);
        plo[0] = pack2h(residh(acc[2*kk][0]),   residh(acc[2*kk][1]));
        plo[1] = pack2h(residh(acc[2*kk][2]),   residh(acc[2*kk][3]));
        plo[2] = pack2h(residh(acc[2*kk+1][0]), residh(acc[2*kk+1][1]));
        plo[3] = pack2h(residh(acc[2*kk+1][2]), residh(acc[2*kk+1][3]));
        // interleaved probs stores (overlap STG with tensor work)
        {
            float2 v00 = {acc[2*kk][0],   acc[2*kk][1]};
            float2 v01 = {acc[2*kk][2],   acc[2*kk][3]};
            float2 v10 = {acc[2*kk+1][0], acc[2*kk+1][1]};
            float2 v11 = {acc[2*kk+1][2], acc[2*kk+1][3]};
            *(float2*)(p0 + (2*kk)*8)   = v00;
            *(float2*)(p1 + (2*kk)*8)   = v01;
            *(float2*)(p0 + (2*kk+1)*8) = v10;
            *(float2*)(p1 + (2*kk+1)*8) = v11;
        }
        uint32_t colV = (uint32_t)((wq*128 + kk*16 + lc*2) * 2);
        #pragma unroll
        for (int dn = 0; dn < 8; ++dn) {
            uint32_t vrow = (uint32_t)(dn*8 + lr);
            uint32_t offH = vrow * VTSTR + colV;
            uint32_t bh0 = lds32(sb + SM_VT + offH);
            uint32_t bh1 = lds32(sb + SM_VT + offH + 16);
            mma_f16(oacc[dn], phi, bh0, bh1);
            mma_f16(oacc[dn], plo, bh0, bh1);
        }
    }

    // ---- cross-warp reduce ----
    float* obuf = (float*)(smem + SM_OBUF);
    #pragma unroll
    for (int g = 0; g < 4; ++g) {
        if (wq == g) {
            #pragma unroll
            for (int dn = 0; dn < 8; ++dn) {
                int c = dn*8 + lc*2;
                float* b0 = obuf + row0 * OSTRF + c;
                float* b1 = obuf + (row0 + 8) * OSTRF + c;
                if (g == 0) {
                    b0[0] = oacc[dn][0]; b0[1] = oacc[dn][1];
                    b1[0] = oacc[dn][2]; b1[1] = oacc[dn][3];
                } else {
                    b0[0] += oacc[dn][0]; b0[1] += oacc[dn][1];
                    b1[0] += oacc[dn][2]; b1[1] += oacc[dn][3];
                }
            }
        }
        __syncthreads();
    }

    // ---- write O in combined layout for OUT gemm ----
    {
        int row = tid >> 3, s2 = tid & 7;
        const float* src = obuf + row * OSTRF;
        size_t rb = ((size_t)b * T_ + t0 + row) * 3072 + (size_t)h * 256;
        #pragma unroll
        for (int u = 0; u < 2; ++u) {
            int s = s2 * 2 + u;
            int g = s >> 2, lcx = s & 3;
            int k0 = g * 16 + lcx * 2;
            uint32_t w[4];
            pack_granule(src[k0], src[k0+1], src[k0+8], src[k0+9], w);
            *(uint4*)(g_oc + rb + g*64 + lcx*16) = *(uint4*)w;
        }
    }
}

// --------------------------------- launcher ---------------------------------
extern "C" void kernel_launch(void* const* d_in, const int* in_sizes, int n_in,
                              void* d_out, int out_size)
{
    const float* x     = (const float*)d_in[0];
    const float* Wqkv  = (const float*)d_in[1];
    const float* bqkv  = (const float*)d_in[2];
    const float* Wph   = (const float*)d_in[3];
    const float* bph   = (const float*)d_in[4];
    const float* Wproj = (const float*)d_in[5];
    const float* bproj = (const float*)d_in[6];
    float* out = (float*)d_out;
    float* sa_out = out;
    float* probs  = out + (size_t)BT_*C_;

    uint8_t *xc_p, *wqc_p, *oc_p, *wcc_p;
    float *wcomb_p, *bcomb_p;
    cudaGetSymbolAddress((void**)&xc_p,   g_xc);
    cudaGetSymbolAddress((void**)&wqc_p,  g_wqc);
    cudaGetSymbolAddress((void**)&oc_p,   g_oc);
    cudaGetSymbolAddress((void**)&wcc_p,  g_wcc);
    cudaGetSymbolAddress((void**)&wcomb_p, g_wcomb);
    cudaGetSymbolAddress((void**)&bcomb_p, g_bcomb);

    static int attrs_set = 0;
    if (!attrs_set) {
        cudaFuncSetAttribute(hmma_gemm<0>, cudaFuncAttributeMaxDynamicSharedMemorySize, HM_SMEM);
        cudaFuncSetAttribute(hmma_gemm<1>, cudaFuncAttributeMaxDynamicSharedMemorySize, HM_SMEM);
        cudaFuncSetAttribute(attn_k, cudaFuncAttributeMaxDynamicSharedMemorySize, ATTN_SMEM);
        attrs_set = 1;
    }

    // 1-3: prep on QKV critical path (+ wcomb zero / bcomb init)
    k_prep_xc<<<BT_*192/256, 256>>>(x);
    k_prep_wqc<<<NQKV_*192/256, 256>>>(Wqkv);
    k_binit<<<(C_*C_ + C_ + 255)/256, 256>>>(bproj);

    // 4: QKV GEMM (profiled slot) -> q hi/lo, k/v hi
    hmma_gemm<1><<<dim3(NQKV_/128, BT_/128), 256, HM_SMEM>>>(
        xc_p, wqc_p, nullptr, bqkv);

    // 5-7: Wcomb chain (independent of attention)
    k_bcomb<<<288, 256>>>(bph, Wproj);
    sgemm64ks<<<dim3(4, 12, 12), 256>>>(Wph, Wproj, wcomb_p);
    k_prep_wccT<<<C_*192/256, 256>>>();

    // 8: V transpose
    k_vT<<<dim3(T_/64, B_*H_), 256>>>();

    // 9: fused attention -> probs + O(combined)
    attn_k<<<dim3(T_/64, H_, B_), 512, ATTN_SMEM>>>(probs);

    // 10: output GEMM + bcomb -> sa_out
    hmma_gemm<0><<<dim3(C_/128, BT_/128), 256, HM_SMEM>>>(
        oc_p, wcc_p, sa_out, bcomb_p);
}

// round 13
// speedup vs baseline: 1.6413x; 1.0283x over previous
#include <cuda_runtime.h>
#include <cuda_fp16.h>
#include <stdint.h>
#include <math.h>

#define H_   12
#define T_   512
#define D_   64
#define C_   768
#define B_   32
#define NQKV_ 2304
#define BT_  16384
#define BHTD_ ((size_t)B_*H_*T_*D_)
#define QSCALE 0.125f

// ------------- device-global scratch (no runtime alloc allowed) -------------
// combined granule: 16B = [hi(k),hi(k+1),hi(k+8),hi(k+9) | lo(same 4)]  (fp16)
__device__ __align__(16) uint8_t g_xc[(size_t)BT_*3072];
__device__ __align__(16) uint8_t g_wqc[(size_t)NQKV_*3072];
__device__ __align__(16) uint8_t g_oc[(size_t)BT_*3072];
__device__ __align__(16) uint8_t g_wcc[(size_t)C_*3072];
__device__ __align__(16) __half g_qhi[BHTD_];
__device__ __align__(16) __half g_qlo[BHTD_];
__device__ __align__(16) __half g_khi[BHTD_];
__device__ __align__(16) __half g_vhi[BHTD_];
__device__ __align__(16) __half g_vthi[BHTD_];   // [b,h,d,s]
__device__ __align__(16) float g_wcomb[C_*C_];
__device__ __align__(16) float g_bcomb[C_];

// ------------------------------ helpers -------------------------------------
__device__ __forceinline__ uint32_t smem_u32(const void* p) {
    uint32_t a;
    asm("{ .reg .u64 t; cvta.to.shared.u64 t, %1; cvt.u32.u64 %0, t; }"
        : "=r"(a) : "l"(p));
    return a;
}
__device__ __forceinline__ void mma_f16(float* c, const uint32_t* a,
                                        uint32_t b0, uint32_t b1) {
    asm volatile(
        "mma.sync.aligned.m16n8k16.row.col.f32.f16.f16.f32 "
        "{%0,%1,%2,%3}, {%4,%5,%6,%7}, {%8,%9}, {%0,%1,%2,%3};"
        : "+f"(c[0]), "+f"(c[1]), "+f"(c[2]), "+f"(c[3])
        : "r"(a[0]), "r"(a[1]), "r"(a[2]), "r"(a[3]), "r"(b0), "r"(b1));
}
__device__ __forceinline__ uint32_t lds32(uint32_t a) {
    uint32_t v;
    asm volatile("ld.shared.b32 %0, [%1];" : "=r"(v) : "r"(a));
    return v;
}
__device__ __forceinline__ void lds64(uint32_t a, uint32_t& x, uint32_t& y) {
    asm volatile("ld.shared.v2.b32 {%0,%1}, [%2];" : "=r"(x), "=r"(y) : "r"(a));
}
__device__ __forceinline__ void lds128(uint32_t a, uint32_t& x, uint32_t& y,
                                       uint32_t& z, uint32_t& w) {
    asm volatile("ld.shared.v4.b32 {%0,%1,%2,%3}, [%4];"
                 : "=r"(x), "=r"(y), "=r"(z), "=r"(w) : "r"(a));
}
__device__ __forceinline__ void split_h(float v, __half& h, __half& l) {
    h = __float2half_rn(v);
    l = __float2half_rn(v - __half2float(h));
}
__device__ __forceinline__ uint32_t pack2h(float a, float b) {
    __half2 t = __floats2half2_rn(a, b);
    return *(uint32_t*)&t;
}
__device__ __forceinline__ void pack_granule(float f0, float f1, float f2, float f3,
                                             uint32_t* w) {
    __half h0,l0,h1,l1,h2,l2,h3,l3;
    split_h(f0,h0,l0); split_h(f1,h1,l1);
    split_h(f2,h2,l2); split_h(f3,h3,l3);
    __half2 t;
    t.x=h0; t.y=h1; w[0] = *(uint32_t*)&t;
    t.x=h2; t.y=h3; w[1] = *(uint32_t*)&t;
    t.x=l0; t.y=l1; w[2] = *(uint32_t*)&t;
    t.x=l2; t.y=l3; w[3] = *(uint32_t*)&t;
}

// ------------------------------ prep kernels --------------------------------
__global__ void __launch_bounds__(256) k_prep_xc(const float* __restrict__ x) {
    int gid = blockIdx.x * 256 + threadIdx.x;
    int lc = gid & 3, g = (gid >> 2) % 48;
    int m = gid / 192;
    const float* xr = x + (size_t)m * 768 + g * 16 + lc * 2;
    uint32_t w[4];
    pack_granule(xr[0], xr[1], xr[8], xr[9], w);
    *(uint4*)(g_xc + (size_t)m * 3072 + g * 64 + lc * 16) = *(uint4*)w;
}

__global__ void __launch_bounds__(256) k_prep_wqc(const float* __restrict__ W) {
    int gid = blockIdx.x * 256 + threadIdx.x;
    int lc = gid & 3, g = (gid >> 2) % 48;
    int n = gid / 192;
    int h = n / 192, j = n % 192;
    const float* wb = W + ((size_t)h * 768 + g * 16 + lc * 2) * 192 + j;
    uint32_t w[4];
    pack_granule(wb[0], wb[192], wb[8*192], wb[9*192], w);
    *(uint4*)(g_wqc + (size_t)n * 3072 + g * 64 + lc * 16) = *(uint4*)w;
}

__global__ void __launch_bounds__(256) k_prep_wccT() {
    int gid = blockIdx.x * 256 + threadIdx.x;
    int lc = gid & 3, g = (gid >> 2) % 48;
    int n = gid / 192;
    int k0 = g * 16 + lc * 2;
    uint32_t w[4];
    pack_granule(g_wcomb[(size_t)k0*768 + n],     g_wcomb[(size_t)(k0+1)*768 + n],
                 g_wcomb[(size_t)(k0+8)*768 + n], g_wcomb[(size_t)(k0+9)*768 + n], w);
    *(uint4*)(g_wcc + (size_t)n * 3072 + g * 64 + lc * 16) = *(uint4*)w;
}

// zero g_wcomb + init g_bcomb = bproj
__global__ void __launch_bounds__(256) k_binit(const float* __restrict__ bproj) {
    int idx = blockIdx.x * 256 + threadIdx.x;
    if (idx < C_*C_) g_wcomb[idx] = 0.0f;
    int j = idx - C_*C_;
    if (j >= 0 && j < C_) g_bcomb[j] = bproj[j];
}

__global__ void __launch_bounds__(256) k_bcomb(const float* __restrict__ bph,
                                               const float* __restrict__ Wproj) {
    int r0 = blockIdx.x * 32;
    int t = threadIdx.x;
    float a0 = 0.f, a1 = 0.f, a2 = 0.f;
    for (int rr = 0; rr < 32; ++rr) {
        int r = r0 + rr;
        float bv = bph[r];
        const float* wr = Wproj + (size_t)r * C_;
        a0 = fmaf(bv, wr[t],       a0);
        a1 = fmaf(bv, wr[t + 256], a1);
        a2 = fmaf(bv, wr[t + 512], a2);
    }
    atomicAdd(&g_bcomb[t],       a0);
    atomicAdd(&g_bcomb[t + 256], a1);
    atomicAdd(&g_bcomb[t + 512], a2);
}

// ------- Wcomb precompute: fp32, 4-way K-split, atomic accumulate -----------
__global__ void __launch_bounds__(256) sgemm64ks(
    const float* __restrict__ A, const float* __restrict__ Bm,
    float* __restrict__ Cm)
{
    __shared__ float As[16][68];
    __shared__ float Bs[16][68];
    const int z = blockIdx.z;
    const float* Ab = A  + (size_t)z * 64 * C_;
    const float* Bb = Bm + (size_t)z * C_ * C_;
    float*       Cb = Cm + (size_t)z * 64 * C_;
    const int tid = threadIdx.x;
    const int tx = tid % 16, ty = tid / 16;
    const int n0 = blockIdx.y * 64;
    const int kbeg = blockIdx.x * 192, kend = kbeg + 192;
    float acc[4][4] = {};
    for (int kt = kbeg; kt < kend; kt += 16) {
        {
            int m = tid / 4, kq = (tid % 4) * 4;
            float4 v = *(const float4*)(Ab + (size_t)m*C_ + kt + kq);
            As[kq+0][m] = v.x; As[kq+1][m] = v.y; As[kq+2][m] = v.z; As[kq+3][m] = v.w;
        }
        {
            int kk = tid / 16, nn = (tid % 16) * 4;
            *(float4*)&Bs[kk][nn] = *(const float4*)(Bb + (size_t)(kt+kk)*C_ + n0 + nn);
        }
        __syncthreads();
        #pragma unroll
        for (int k = 0; k < 16; ++k) {
            float a[4], b[4];
            #pragma unroll
            for (int i = 0; i < 4; ++i) a[i] = As[k][ty*4+i];
            *(float4*)b = *(const float4*)&Bs[k][tx*4];
            #pragma unroll
            for (int i = 0; i < 4; ++i)
                #pragma unroll
                for (int j = 0; j < 4; ++j)
                    acc[i][j] = fmaf(a[i], b[j], acc[i][j]);
        }
        __syncthreads();
    }
    #pragma unroll
    for (int i = 0; i < 4; ++i) {
        int m = ty*4 + i;
        #pragma unroll
        for (int j = 0; j < 4; ++j)
            atomicAdd(&Cb[(size_t)m*C_ + n0 + tx*4 + j], acc[i][j]);
    }
}

// ------------- HMMA fp16 2-term GEMM, 64x128 tile, 3 CTAs/SM ----------------
// A: combined granules (hi+lo), stride 192 (conflict-free, measured).
// B: hi-only 8B granules, stride 64 + 32B XOR swizzle on (row&2):
//   phase rows (lr 0-3) land on word windows 0-7 / 16-23 / 8-15 / 24-31.
#define ASTR 192
#define ATILE (64*ASTR)       // 12288
#define BSTR 64
#define BTILE (128*BSTR)      // 8192
#define GSTAGE (ATILE+BTILE)  // 20480
#define HM_SMEM (2*GSTAGE)    // 40960

template<int EPI>
__global__ void __launch_bounds__(256, 3) hmma_gemm(
    const uint8_t* __restrict__ Ac, const uint8_t* __restrict__ Bc,
    float* __restrict__ Cout, const float* __restrict__ bias)
{
    extern __shared__ char smem[];
    const uint32_t sbase = smem_u32(smem);
    const int tid = threadIdx.x;
    const int wid = tid >> 5, ln = tid & 31;
    const int n0 = blockIdx.x * 128, m0 = blockIdx.y * 64;
    const int wm = wid & 1, wn = wid >> 1;      // 2 x 4 warp grid
    const int mrow = wm * 32, ncol = wn * 32;
    const int lr = ln >> 2, lc = ln & 3;
    const int lrb = (lr >> 1) & 1;

    const uint8_t* gA = Ac + (size_t)m0 * 3072;
    const uint8_t* gB = Bc + (size_t)n0 * 3072;

    auto load_chunk = [&](int kc, int stage) {
        uint32_t sb = sbase + stage * GSTAGE;
        const uint8_t* pA = gA + kc * 128;
        #pragma unroll
        for (int i = 0; i < 2; ++i) {
            int gid = tid + i * 256;            // 0..511
            int r = gid >> 3, c = gid & 7;
            asm volatile("cp.async.cg.shared.global [%0], [%1], 16;"
                :: "r"(sb + r*ASTR + c*16), "l"(pA + (size_t)r*3072 + c*16));
        }
        const uint8_t* pB = gB + kc * 128;
        uint32_t bb = sb + ATILE;
        #pragma unroll
        for (int i = 0; i < 4; ++i) {
            int gid = tid + i * 256;            // 0..1023
            int r = gid >> 3, c = gid & 7;      // c = gg*4 + lcx
            int gg = c >> 2, lcx = c & 3;
            uint32_t doff = (uint32_t)(c*8) ^ (uint32_t)((r & 2) << 4);
            asm volatile("cp.async.ca.shared.global [%0], [%1], 8;"
                :: "r"(bb + r*BSTR + doff), "l"(pB + (size_t)r*3072 + gg*64 + lcx*16));
        }
        asm volatile("cp.async.commit_group;");
    };

    float acc[2][4][4] = {};
    load_chunk(0, 0);
    for (int c = 0; c < 24; ++c) {
        int s = c & 1;
        asm volatile("cp.async.wait_group 0;");
        __syncthreads();                 // also protects stage s^1 reuse below
        if (c + 1 < 24) load_chunk(c + 1, s ^ 1);

        uint32_t sA = sbase + s * GSTAGE;
        uint32_t aBr = sA + (uint32_t)((mrow + lr)*ASTR + lc*16);
        uint32_t bBr = sA + ATILE + (uint32_t)((ncol + lr)*BSTR + lc*8);

        #pragma unroll
        for (int ks = 0; ks < 2; ++ks) {
            const uint32_t ksB = (uint32_t)((ks ^ lrb) * 32);
            uint32_t aH[2][4], aL[2][4];
            #pragma unroll
            for (int mt = 0; mt < 2; ++mt) {
                uint32_t base = aBr + mt*16*ASTR + ks*64;
                uint32_t x0,y0,z0,w0, x1,y1,z1,w1;
                lds128(base,          x0,y0,z0,w0);
                lds128(base + 8*ASTR, x1,y1,z1,w1);
                aH[mt][0]=x0; aH[mt][1]=x1; aH[mt][2]=y0; aH[mt][3]=y1;
                aL[mt][0]=z0; aL[mt][1]=z1; aL[mt][2]=w0; aL[mt][3]=w1;
            }
            #pragma unroll
            for (int nt = 0; nt < 4; ++nt) {
                uint32_t b0, b1;
                lds64(bBr + nt*8*BSTR + ksB, b0, b1);
                #pragma unroll
                for (int mt = 0; mt < 2; ++mt) {
                    mma_f16(acc[mt][nt], aH[mt], b0, b1);
                    mma_f16(acc[mt][nt], aL[mt], b0, b1);
                }
            }
        }
        // no trailing sync: next iteration's barrier protects buffer reuse
    }

    // ------------------------------- epilogue --------------------------------
    if (EPI == 0) {
        #pragma unroll
        for (int mt = 0; mt < 2; ++mt) {
            int m = m0 + mrow + mt*16 + lr;
            #pragma unroll
            for (int nt = 0; nt < 4; ++nt) {
                int n = n0 + ncol + nt*8 + lc*2;
                float b0 = bias[n], b1 = bias[n+1];
                float* ac = acc[mt][nt];
                float2 v0 = {ac[0] + b0, ac[1] + b1};
                float2 v1 = {ac[2] + b0, ac[3] + b1};
                *(float2*)(Cout + (size_t)m * C_ + n) = v0;
                *(float2*)(Cout + (size_t)(m+8) * C_ + n) = v1;
            }
        }
    } else {
        const int nbase = n0 + ncol;                 // 32-aligned, single blk
        const int h = nbase / 192, rbase = nbase % 192;
        const int blk = rbase >> 6, roffb = rbase & 63;
        #pragma unroll
        for (int mt = 0; mt < 2; ++mt) {
            #pragma unroll
            for (int rr = 0; rr < 2; ++rr) {
                int mm = m0 + mrow + mt*16 + lr + rr*8;
                int b_ = mm >> 9, t_ = mm & 511;
                size_t obase = (((size_t)b_ * H_ + h) * T_ + t_) * 64;
                #pragma unroll
                for (int nt = 0; nt < 4; ++nt) {
                    int n = nbase + nt*8 + lc*2;
                    size_t o = obase + roffb + nt*8 + lc*2;
                    float v0 = acc[mt][nt][rr*2+0] + bias[n];
                    float v1 = acc[mt][nt][rr*2+1] + bias[n+1];
                    if (blk == 0) {
                        v0 *= QSCALE; v1 *= QSCALE;
                        __half h0,h1,l0,l1;
                        split_h(v0,h0,l0); split_h(v1,h1,l1);
                        __half2 ph; ph.x=h0; ph.y=h1;
                        __half2 pl; pl.x=l0; pl.y=l1;
                        *(__half2*)(g_qhi + o) = ph;
                        *(__half2*)(g_qlo + o) = pl;
                    } else {
                        __half* dst = (blk == 1) ? g_khi : g_vhi;
                        *(__half2*)(dst + o) = __floats2half2_rn(v0, v1);
                    }
                }
            }
        }
    }
}

// ------------------------ V transpose: [s][d] -> [d][s] ----------------------
__global__ void __launch_bounds__(256) k_vT() {
    __shared__ __half thi[64][72];
    const int s0 = blockIdx.x * 64;
    const int bh = blockIdx.y;
    const int tid = threadIdx.x;
    const int r = tid >> 2, cs = (tid & 3) * 16;
    const size_t sbase = ((size_t)bh * T_ + s0 + r) * 64 + cs;
    #pragma unroll
    for (int j = 0; j < 2; ++j)
        *(uint4*)&thi[r][cs + j*8] = *(const uint4*)(g_vhi + sbase + j*8);
    __syncthreads();
    const int d = tid >> 2, ss = (tid & 3) * 16;
    const size_t dbase = ((size_t)bh * 64 + d) * T_ + s0 + ss;
    #pragma unroll
    for (int j = 0; j < 2; ++j) {
        uint32_t ph[4];
        #pragma unroll
        for (int q = 0; q < 4; ++q) {
            int s = ss + j*8 + q*2;
            __half2 a; a.x = thi[s][d]; a.y = thi[s+1][d];
            ph[q] = *(uint32_t*)&a;
        }
        *(uint4*)(g_vthi + dbase + j*8) = *(uint4*)ph;
    }
}

// --------------------------- HMMA fused attention ----------------------------
// K/VT single-fp16 (B-side); Q split hi/lo (A-side); PV single-term (P hi).
#define KSTR 144u
#define QSTR 144u
#define VTSTR 1040u
#define SM_K 0u            // 512*144 = 73728
#define SM_VT 0u           // 64*1040 = 66560 (overlays K)
#define SM_Q 73728u        // 9216
#define SM_QLO 82944u      // 9216
#define SM_OBUF 73728u     // 18432 (overlays Q after fragments in regs)
#define OSTRF 72
#define SM_EXM 92160u
#define SM_EXS 93184u
#define ATTN_SMEM 94208

__global__ void __launch_bounds__(512) attn_k(float* __restrict__ probs)
{
    extern __shared__ char smem[];
    const uint32_t sb = smem_u32(smem);
    const int tid = threadIdx.x;
    const int wid = tid >> 5, ln = tid & 31;
    const int wm = wid & 3, wq = wid >> 2;
    const int b = blockIdx.z, h = blockIdx.y, t0 = blockIdx.x * 64;
    const int bh = b * H_ + h;
    const int lr = ln >> 2, lc = ln & 3;

    // ---- load K (512 rows, hi only) + Q (64 rows, hi+lo) ----
    {
        const __half* khi = g_khi + (size_t)bh * T_ * 64;
        #pragma unroll
        for (int i = 0; i < 8; ++i) {
            int idx = tid + i * 512;
            int r = idx >> 3, sg = idx & 7;
            asm volatile("cp.async.cg.shared.global [%0], [%1], 16;"
                :: "r"(sb + SM_K + r*KSTR + sg*16), "l"(khi + (size_t)r*64 + sg*8));
        }
        const __half* qhi = g_qhi + ((size_t)bh * T_ + t0) * 64;
        const __half* qlo = g_qlo + ((size_t)bh * T_ + t0) * 64;
        {
            int r = tid >> 3, sg = tid & 7;
            asm volatile("cp.async.cg.shared.global [%0], [%1], 16;"
                :: "r"(sb + SM_Q + r*QSTR + sg*16), "l"(qhi + (size_t)r*64 + sg*8));
            asm volatile("cp.async.cg.shared.global [%0], [%1], 16;"
                :: "r"(sb + SM_QLO + r*QSTR + sg*16), "l"(qlo + (size_t)r*64 + sg*8));
        }
        asm volatile("cp.async.commit_group;");
        asm volatile("cp.async.wait_group 0;");
    }
    __syncthreads();

    // ---- Q fragments ----
    uint32_t aH[4][4], aL[4][4];
    {
        const int row = wm * 16 + lr;
        #pragma unroll
        for (int ks = 0; ks < 4; ++ks) {
            uint32_t off = row * QSTR + ks * 32 + lc * 4;
            aH[ks][0] = lds32(sb + SM_Q + off);
            aH[ks][1] = lds32(sb + SM_Q + off + 8*QSTR);
            aH[ks][2] = lds32(sb + SM_Q + off + 16);
            aH[ks][3] = lds32(sb + SM_Q + off + 8*QSTR + 16);
            aL[ks][0] = lds32(sb + SM_QLO + off);
            aL[ks][1] = lds32(sb + SM_QLO + off + 8*QSTR);
            aL[ks][2] = lds32(sb + SM_QLO + off + 16);
            aL[ks][3] = lds32(sb + SM_QLO + off + 8*QSTR + 16);
        }
    }

    // ---- S = Q K^T  (2 MMAs per step) ----
    float acc[16][4];
    #pragma unroll
    for (int nt = 0; nt < 16; ++nt) { acc[nt][0]=acc[nt][1]=acc[nt][2]=acc[nt][3]=0.f; }
    #pragma unroll
    for (int nt = 0; nt < 16; ++nt) {
        uint32_t krow = (uint32_t)(wq * 128 + nt * 8 + lr);
        #pragma unroll
        for (int ks = 0; ks < 4; ++ks) {
            uint32_t boff = krow * KSTR + ks * 32 + lc * 4;
            uint32_t bh0 = lds32(sb + SM_K + boff);
            uint32_t bh1 = lds32(sb + SM_K + boff + 16);
            mma_f16(acc[nt], aH[ks], bh0, bh1);
            mma_f16(acc[nt], aL[ks], bh0, bh1);
        }
    }

    // ---- softmax over 512 keys ----
    const int row0 = wm * 16 + lr;
    {
        float mx0 = -1e30f, mx1 = -1e30f;
        #pragma unroll
        for (int nt = 0; nt < 16; ++nt) {
            mx0 = fmaxf(mx0, fmaxf(acc[nt][0], acc[nt][1]));
            mx1 = fmaxf(mx1, fmaxf(acc[nt][2], acc[nt][3]));
        }
        mx0 = fmaxf(mx0, __shfl_xor_sync(0xffffffffu, mx0, 1));
        mx0 = fmaxf(mx0, __shfl_xor_sync(0xffffffffu, mx0, 2));
        mx1 = fmaxf(mx1, __shfl_xor_sync(0xffffffffu, mx1, 1));
        mx1 = fmaxf(mx1, __shfl_xor_sync(0xffffffffu, mx1, 2));
        float* exm = (float*)(smem + SM_EXM);
        if (lc == 0) { exm[wq*64 + row0] = mx0; exm[wq*64 + row0 + 8] = mx1; }
        __syncthreads();     // all warps past S MMAs -> K region dead

        // ---- prefetch VT (hi only) into K region ----
        {
            const __half* vthi = g_vthi + (size_t)bh * 64 * T_;
            #pragma unroll
            for (int i = 0; i < 8; ++i) {
                int idx = tid + i * 512;
                int d = idx >> 6, sg = idx & 63;
                asm volatile("cp.async.cg.shared.global [%0], [%1], 16;"
                    :: "r"(sb + SM_VT + d*VTSTR + sg*16), "l"(vthi + (size_t)d*T_ + sg*8));
            }
            asm volatile("cp.async.commit_group;");
        }

        float m0 = fmaxf(fmaxf(exm[row0],      exm[64+row0]),
                         fmaxf(exm[128+row0],  exm[192+row0]));
        float m1 = fmaxf(fmaxf(exm[row0+8],    exm[64+row0+8]),
                         fmaxf(exm[128+row0+8],exm[192+row0+8]));
        float s0 = 0.f, s1 = 0.f;
        #pragma unroll
        for (int nt = 0; nt < 16; ++nt) {
            acc[nt][0] = __expf(acc[nt][0] - m0); s0 += acc[nt][0];
            acc[nt][1] = __expf(acc[nt][1] - m0); s0 += acc[nt][1];
            acc[nt][2] = __expf(acc[nt][2] - m1); s1 += acc[nt][2];
            acc[nt][3] = __expf(acc[nt][3] - m1); s1 += acc[nt][3];
        }
        s0 += __shfl_xor_sync(0xffffffffu, s0, 1);
        s0 += __shfl_xor_sync(0xffffffffu, s0, 2);
        s1 += __shfl_xor_sync(0xffffffffu, s1, 1);
        s1 += __shfl_xor_sync(0xffffffffu, s1, 2);
        float* exs = (float*)(smem + SM_EXS);
        if (lc == 0) { exs[wq*64 + row0] = s0; exs[wq*64 + row0 + 8] = s1; }
        __syncthreads();
        float inv0 = 1.0f / (exs[row0] + exs[64+row0] + exs[128+row0] + exs[192+row0]);
        float inv1 = 1.0f / (exs[row0+8] + exs[64+row0+8] + exs[128+row0+8] + exs[192+row0+8]);
        #pragma unroll
        for (int nt = 0; nt < 16; ++nt) {
            acc[nt][0] *= inv0; acc[nt][1] *= inv0;
            acc[nt][2] *= inv1; acc[nt][3] *= inv1;
        }
    }

    // ---- wait VT, then PV (single-term P) with probs stores interleaved ----
    asm volatile("cp.async.wait_group 0;");
    __syncthreads();

    float* p0 = probs + ((size_t)bh * T_ + t0 + row0) * 512 + wq*128 + lc*2;
    float* p1 = p0 + (size_t)8 * 512;

    float oacc[8][4];
    #pragma unroll
    for (int dn = 0; dn < 8; ++dn) { oacc[dn][0]=oacc[dn][1]=oacc[dn][2]=oacc[dn][3]=0.f; }
    #pragma unroll
    for (int kk = 0; kk < 8; ++kk) {
        uint32_t phi[4];
        phi[0] = pack2h(acc[2*kk][0],   acc[2*kk][1]);
        phi[1] = pack2h(acc[2*kk][2],   acc[2*kk][3]);
        phi[2] = pack2h(acc[2*kk+1][0], acc[2*kk+1][1]);
        phi[3] = pack2h(acc[2*kk+1][2], acc[2*kk+1][3]);
        // interleaved probs stores (overlap STG with tensor work)
        {
            float2 v00 = {acc[2*kk][0],   acc[2*kk][1]};
            float2 v01 = {acc[2*kk][2],   acc[2*kk][3]};
            float2 v10 = {acc[2*kk+1][0], acc[2*kk+1][1]};
            float2 v11 = {acc[2*kk+1][2], acc[2*kk+1][3]};
            *(float2*)(p0 + (2*kk)*8)   = v00;
            *(float2*)(p1 + (2*kk)*8)   = v01;
            *(float2*)(p0 + (2*kk+1)*8) = v10;
            *(float2*)(p1 + (2*kk+1)*8) = v11;
        }
        uint32_t colV = (uint32_t)((wq*128 + kk*16 + lc*2) * 2);
        #pragma unroll
        for (int dn = 0; dn < 8; ++dn) {
            uint32_t vrow = (uint32_t)(dn*8 + lr);
            uint32_t offH = vrow * VTSTR + colV;
            uint32_t bh0 = lds32(sb + SM_VT + offH);
            uint32_t bh1 = lds32(sb + SM_VT + offH + 16);
            mma_f16(oacc[dn], phi, bh0, bh1);
        }
    }

    // ---- cross-warp reduce ----
    float* obuf = (float*)(smem + SM_OBUF);
    #pragma unroll
    for (int g = 0; g < 4; ++g) {
        if (wq == g) {
            #pragma unroll
            for (int dn = 0; dn < 8; ++dn) {
                int c = dn*8 + lc*2;
                float* b0 = obuf + row0 * OSTRF + c;
                float* b1 = obuf + (row0 + 8) * OSTRF + c;
                if (g == 0) {
                    b0[0] = oacc[dn][0]; b0[1] = oacc[dn][1];
                    b1[0] = oacc[dn][2]; b1[1] = oacc[dn][3];
                } else {
                    b0[0] += oacc[dn][0]; b0[1] += oacc[dn][1];
                    b1[0] += oacc[dn][2]; b1[1] += oacc[dn][3];
                }
            }
        }
        __syncthreads();
    }

    // ---- write O in combined layout for OUT gemm ----
    {
        int row = tid >> 3, s2 = tid & 7;
        const float* src = obuf + row * OSTRF;
        size_t rb = ((size_t)b * T_ + t0 + row) * 3072 + (size_t)h * 256;
        #pragma unroll
        for (int u = 0; u < 2; ++u) {
            int s = s2 * 2 + u;
            int g = s >> 2, lcx = s & 3;
            int k0 = g * 16 + lcx * 2;
            uint32_t w[4];
            pack_granule(src[k0], src[k0+1], src[k0+8], src[k0+9], w);
            *(uint4*)(g_oc + rb + g*64 + lcx*16) = *(uint4*)w;
        }
    }
}

// --------------------------------- launcher ---------------------------------
extern "C" void kernel_launch(void* const* d_in, const int* in_sizes, int n_in,
                              void* d_out, int out_size)
{
    const float* x     = (const float*)d_in[0];
    const float* Wqkv  = (const float*)d_in[1];
    const float* bqkv  = (const float*)d_in[2];
    const float* Wph   = (const float*)d_in[3];
    const float* bph   = (const float*)d_in[4];
    const float* Wproj = (const float*)d_in[5];
    const float* bproj = (const float*)d_in[6];
    float* out = (float*)d_out;
    float* sa_out = out;
    float* probs  = out + (size_t)BT_*C_;

    uint8_t *xc_p, *wqc_p, *oc_p, *wcc_p;
    float *wcomb_p, *bcomb_p;
    cudaGetSymbolAddress((void**)&xc_p,   g_xc);
    cudaGetSymbolAddress((void**)&wqc_p,  g_wqc);
    cudaGetSymbolAddress((void**)&oc_p,   g_oc);
    cudaGetSymbolAddress((void**)&wcc_p,  g_wcc);
    cudaGetSymbolAddress((void**)&wcomb_p, g_wcomb);
    cudaGetSymbolAddress((void**)&bcomb_p, g_bcomb);

    static int attrs_set = 0;
    if (!attrs_set) {
        cudaFuncSetAttribute(hmma_gemm<0>, cudaFuncAttributeMaxDynamicSharedMemorySize, HM_SMEM);
        cudaFuncSetAttribute(hmma_gemm<1>, cudaFuncAttributeMaxDynamicSharedMemorySize, HM_SMEM);
        cudaFuncSetAttribute(attn_k, cudaFuncAttributeMaxDynamicSharedMemorySize, ATTN_SMEM);
        attrs_set = 1;
    }

    // 1-3: prep on QKV critical path (+ wcomb zero / bcomb init)
    k_prep_xc<<<BT_*192/256, 256>>>(x);
    k_prep_wqc<<<NQKV_*192/256, 256>>>(Wqkv);
    k_binit<<<(C_*C_ + C_ + 255)/256, 256>>>(bproj);

    // 4: QKV GEMM (profiled slot) -> q hi/lo, k/v hi
    hmma_gemm<1><<<dim3(NQKV_/128, BT_/64), 256, HM_SMEM>>>(
        xc_p, wqc_p, nullptr, bqkv);

    // 5-7: Wcomb chain (independent of attention)
    k_bcomb<<<288, 256>>>(bph, Wproj);
    sgemm64ks<<<dim3(4, 12, 12), 256>>>(Wph, Wproj, wcomb_p);
    k_prep_wccT<<<C_*192/256, 256>>>();

    // 8: V transpose
    k_vT<<<dim3(T_/64, B_*H_), 256>>>();

    // 9: fused attention -> probs + O(combined)
    attn_k<<<dim3(T_/64, H_, B_), 512, ATTN_SMEM>>>(probs);

    // 10: output GEMM + bcomb -> sa_out
    hmma_gemm<0><<<dim3(C_/128, BT_/64), 256, HM_SMEM>>>(
        oc_p, wcc_p, sa_out, bcomb_p);
}

// round 14
// speedup vs baseline: 2.0054x; 1.2218x over previous
#include <cuda_runtime.h>
#include <cuda_fp16.h>
#include <stdint.h>
#include <math.h>

#define H_   12
#define T_   512
#define D_   64
#define C_   768
#define B_   32
#define NQKV_ 2304
#define BT_  16384
#define BHTD_ ((size_t)B_*H_*T_*D_)
#define QSCALE 0.125f

// ------------- device-global scratch (no runtime alloc allowed) -------------
// hi-only granule: 8B = [h(k),h(k+1),h(k+8),h(k+9)] fp16; row = 48 groups x 32B
__device__ __align__(16) uint8_t g_xh[(size_t)BT_*1536];
__device__ __align__(16) uint8_t g_wqh[(size_t)NQKV_*1536];
__device__ __align__(16) uint8_t g_oh[(size_t)BT_*1536];
__device__ __align__(16) uint8_t g_wch[(size_t)C_*1536];
__device__ __align__(16) __half g_qhi[BHTD_];
__device__ __align__(16) __half g_khi[BHTD_];
__device__ __align__(16) __half g_vhi[BHTD_];
__device__ __align__(16) __half g_vthi[BHTD_];   // [b,h,d,s]
__device__ __align__(16) float g_wcomb[C_*C_];
__device__ __align__(16) float g_bcomb[C_];

// ------------------------------ helpers -------------------------------------
__device__ __forceinline__ uint32_t smem_u32(const void* p) {
    uint32_t a;
    asm("{ .reg .u64 t; cvta.to.shared.u64 t, %1; cvt.u32.u64 %0, t; }"
        : "=r"(a) : "l"(p));
    return a;
}
__device__ __forceinline__ void mma_f16(float* c, const uint32_t* a,
                                        uint32_t b0, uint32_t b1) {
    asm volatile(
        "mma.sync.aligned.m16n8k16.row.col.f32.f16.f16.f32 "
        "{%0,%1,%2,%3}, {%4,%5,%6,%7}, {%8,%9}, {%0,%1,%2,%3};"
        : "+f"(c[0]), "+f"(c[1]), "+f"(c[2]), "+f"(c[3])
        : "r"(a[0]), "r"(a[1]), "r"(a[2]), "r"(a[3]), "r"(b0), "r"(b1));
}
__device__ __forceinline__ uint32_t lds32(uint32_t a) {
    uint32_t v;
    asm volatile("ld.shared.b32 %0, [%1];" : "=r"(v) : "r"(a));
    return v;
}
__device__ __forceinline__ void lds64(uint32_t a, uint32_t& x, uint32_t& y) {
    asm volatile("ld.shared.v2.b32 {%0,%1}, [%2];" : "=r"(x), "=r"(y) : "r"(a));
}
__device__ __forceinline__ uint32_t pack2h(float a, float b) {
    __half2 t = __floats2half2_rn(a, b);
    return *(uint32_t*)&t;
}
// 8B hi-only granule from 4 fp32 (k, k+1, k+8, k+9)
__device__ __forceinline__ void pack_g8(float f0, float f1, float f2, float f3,
                                        uint32_t* w) {
    w[0] = pack2h(f0, f1);
    w[1] = pack2h(f2, f3);
}

// ------------------------------ prep kernels --------------------------------
__global__ void __launch_bounds__(256) k_prep_xh(const float* __restrict__ x) {
    int gid = blockIdx.x * 256 + threadIdx.x;     // BT*192 sub-granules
    int lc = gid & 3, g = (gid >> 2) % 48;
    int m = gid / 192;
    const float* xr = x + (size_t)m * 768 + g * 16 + lc * 2;
    uint32_t w[2];
    pack_g8(xr[0], xr[1], xr[8], xr[9], w);
    *(uint2*)(g_xh + (size_t)m * 1536 + g * 32 + lc * 8) = *(uint2*)w;
}

__global__ void __launch_bounds__(256) k_prep_wqh(const float* __restrict__ W) {
    int gid = blockIdx.x * 256 + threadIdx.x;
    int lc = gid & 3, g = (gid >> 2) % 48;
    int n = gid / 192;
    int h = n / 192, j = n % 192;
    const float* wb = W + ((size_t)h * 768 + g * 16 + lc * 2) * 192 + j;
    uint32_t w[2];
    pack_g8(wb[0], wb[192], wb[8*192], wb[9*192], w);
    *(uint2*)(g_wqh + (size_t)n * 1536 + g * 32 + lc * 8) = *(uint2*)w;
}

__global__ void __launch_bounds__(256) k_prep_wch() {
    int gid = blockIdx.x * 256 + threadIdx.x;
    int lc = gid & 3, g = (gid >> 2) % 48;
    int n = gid / 192;
    int k0 = g * 16 + lc * 2;
    uint32_t w[2];
    pack_g8(g_wcomb[(size_t)k0*768 + n],     g_wcomb[(size_t)(k0+1)*768 + n],
            g_wcomb[(size_t)(k0+8)*768 + n], g_wcomb[(size_t)(k0+9)*768 + n], w);
    *(uint2*)(g_wch + (size_t)n * 1536 + g * 32 + lc * 8) = *(uint2*)w;
}

// zero g_wcomb + init g_bcomb = bproj
__global__ void __launch_bounds__(256) k_binit(const float* __restrict__ bproj) {
    int idx = blockIdx.x * 256 + threadIdx.x;
    if (idx < C_*C_) g_wcomb[idx] = 0.0f;
    int j = idx - C_*C_;
    if (j >= 0 && j < C_) g_bcomb[j] = bproj[j];
}

__global__ void __launch_bounds__(256) k_bcomb(const float* __restrict__ bph,
                                               const float* __restrict__ Wproj) {
    int r0 = blockIdx.x * 32;
    int t = threadIdx.x;
    float a0 = 0.f, a1 = 0.f, a2 = 0.f;
    for (int rr = 0; rr < 32; ++rr) {
        int r = r0 + rr;
        float bv = bph[r];
        const float* wr = Wproj + (size_t)r * C_;
        a0 = fmaf(bv, wr[t],       a0);
        a1 = fmaf(bv, wr[t + 256], a1);
        a2 = fmaf(bv, wr[t + 512], a2);
    }
    atomicAdd(&g_bcomb[t],       a0);
    atomicAdd(&g_bcomb[t + 256], a1);
    atomicAdd(&g_bcomb[t + 512], a2);
}

// ------- Wcomb precompute: fp32, 4-way K-split, atomic accumulate -----------
__global__ void __launch_bounds__(256) sgemm64ks(
    const float* __restrict__ A, const float* __restrict__ Bm,
    float* __restrict__ Cm)
{
    __shared__ float As[16][68];
    __shared__ float Bs[16][68];
    const int z = blockIdx.z;
    const float* Ab = A  + (size_t)z * 64 * C_;
    const float* Bb = Bm + (size_t)z * C_ * C_;
    float*       Cb = Cm + (size_t)z * 64 * C_;
    const int tid = threadIdx.x;
    const int tx = tid % 16, ty = tid / 16;
    const int n0 = blockIdx.y * 64;
    const int kbeg = blockIdx.x * 192, kend = kbeg + 192;
    float acc[4][4] = {};
    for (int kt = kbeg; kt < kend; kt += 16) {
        {
            int m = tid / 4, kq = (tid % 4) * 4;
            float4 v = *(const float4*)(Ab + (size_t)m*C_ + kt + kq);
            As[kq+0][m] = v.x; As[kq+1][m] = v.y; As[kq+2][m] = v.z; As[kq+3][m] = v.w;
        }
        {
            int kk = tid / 16, nn = (tid % 16) * 4;
            *(float4*)&Bs[kk][nn] = *(const float4*)(Bb + (size_t)(kt+kk)*C_ + n0 + nn);
        }
        __syncthreads();
        #pragma unroll
        for (int k = 0; k < 16; ++k) {
            float a[4], b[4];
            #pragma unroll
            for (int i = 0; i < 4; ++i) a[i] = As[k][ty*4+i];
            *(float4*)b = *(const float4*)&Bs[k][tx*4];
            #pragma unroll
            for (int i = 0; i < 4; ++i)
                #pragma unroll
                for (int j = 0; j < 4; ++j)
                    acc[i][j] = fmaf(a[i], b[j], acc[i][j]);
        }
        __syncthreads();
    }
    #pragma unroll
    for (int i = 0; i < 4; ++i) {
        int m = ty*4 + i;
        #pragma unroll
        for (int j = 0; j < 4; ++j)
            atomicAdd(&Cb[(size_t)m*C_ + n0 + tx*4 + j], acc[i][j]);
    }
}

// --------------- HMMA fp16 single-term GEMM, 64x128 tile --------------------
// A and B hi-only 8B granules; smem rows 64B/chunk + 32B XOR swizzle on
// (row&2) (verified conflict-free for lds64 phases).
#define RSTR 64
#define ATILE (64*RSTR)       // 4096
#define BTILE (128*RSTR)      // 8192
#define GSTAGE (ATILE+BTILE)  // 12288
#define HM_SMEM (2*GSTAGE)    // 24576

template<int EPI>
__global__ void __launch_bounds__(256, 3) hmma_gemm(
    const uint8_t* __restrict__ Ac, const uint8_t* __restrict__ Bc,
    float* __restrict__ Cout, const float* __restrict__ bias)
{
    extern __shared__ char smem[];
    const uint32_t sbase = smem_u32(smem);
    const int tid = threadIdx.x;
    const int wid = tid >> 5, ln = tid & 31;
    const int n0 = blockIdx.x * 128, m0 = blockIdx.y * 64;
    const int wm = wid & 1, wn = wid >> 1;      // 2 x 4 warp grid
    const int mrow = wm * 32, ncol = wn * 32;
    const int lr = ln >> 2, lc = ln & 3;
    const int lrb = (lr >> 1) & 1;

    const uint8_t* gA = Ac + (size_t)m0 * 1536;
    const uint8_t* gB = Bc + (size_t)n0 * 1536;

    auto load_chunk = [&](int kc, int stage) {
        uint32_t sb = sbase + stage * GSTAGE;
        const uint8_t* pA = gA + kc * 64;       // 2 groups of 16 k = 64B/row
        #pragma unroll
        for (int i = 0; i < 2; ++i) {
            int gid = tid + i * 256;            // 0..511 : 64 rows x 8 grans
            int r = gid >> 3, c = gid & 7;
            int gg = c >> 2, lcx = c & 3;
            uint32_t doff = (uint32_t)(c*8) ^ (uint32_t)((r & 2) << 4);
            asm volatile("cp.async.ca.shared.global [%0], [%1], 8;"
                :: "r"(sb + r*RSTR + doff), "l"(pA + (size_t)r*1536 + gg*32 + lcx*8));
        }
        const uint8_t* pB = gB + kc * 64;
        uint32_t bb = sb + ATILE;
        #pragma unroll
        for (int i = 0; i < 4; ++i) {
            int gid = tid + i * 256;            // 0..1023 : 128 rows x 8 grans
            int r = gid >> 3, c = gid & 7;
            int gg = c >> 2, lcx = c & 3;
            uint32_t doff = (uint32_t)(c*8) ^ (uint32_t)((r & 2) << 4);
            asm volatile("cp.async.ca.shared.global [%0], [%1], 8;"
                :: "r"(bb + r*RSTR + doff), "l"(pB + (size_t)r*1536 + gg*32 + lcx*8));
        }
        asm volatile("cp.async.commit_group;");
    };

    float acc[2][4][4] = {};
    load_chunk(0, 0);
    for (int c = 0; c < 24; ++c) {
        int s = c & 1;
        asm volatile("cp.async.wait_group 0;");
        __syncthreads();                 // also protects stage s^1 reuse below
        if (c + 1 < 24) load_chunk(c + 1, s ^ 1);

        uint32_t sA = sbase + s * GSTAGE;
        uint32_t aBr = sA + (uint32_t)((mrow + lr)*RSTR + lc*8);
        uint32_t bBr = sA + ATILE + (uint32_t)((ncol + lr)*RSTR + lc*8);

        #pragma unroll
        for (int ks = 0; ks < 2; ++ks) {
            const uint32_t ksB = (uint32_t)((ks ^ lrb) * 32);
            uint32_t aF[2][4];
            #pragma unroll
            for (int mt = 0; mt < 2; ++mt) {
                uint32_t base = aBr + mt*16*RSTR + ksB;
                lds64(base,          aF[mt][0], aF[mt][2]);
                lds64(base + 8*RSTR, aF[mt][1], aF[mt][3]);
            }
            #pragma unroll
            for (int nt = 0; nt < 4; ++nt) {
                uint32_t b0, b1;
                lds64(bBr + nt*8*RSTR + ksB, b0, b1);
                #pragma unroll
                for (int mt = 0; mt < 2; ++mt)
                    mma_f16(acc[mt][nt], aF[mt], b0, b1);
            }
        }
        // no trailing sync: next iteration's barrier protects buffer reuse
    }

    // ------------------------------- epilogue --------------------------------
    if (EPI == 0) {
        #pragma unroll
        for (int mt = 0; mt < 2; ++mt) {
            int m = m0 + mrow + mt*16 + lr;
            #pragma unroll
            for (int nt = 0; nt < 4; ++nt) {
                int n = n0 + ncol + nt*8 + lc*2;
                float b0 = bias[n], b1 = bias[n+1];
                float* ac = acc[mt][nt];
                float2 v0 = {ac[0] + b0, ac[1] + b1};
                float2 v1 = {ac[2] + b0, ac[3] + b1};
                *(float2*)(Cout + (size_t)m * C_ + n) = v0;
                *(float2*)(Cout + (size_t)(m+8) * C_ + n) = v1;
            }
        }
    } else {
        const int nbase = n0 + ncol;                 // 32-aligned, single blk
        const int h = nbase / 192, rbase = nbase % 192;
        const int blk = rbase >> 6, roffb = rbase & 63;
        __half* dst = (blk == 0) ? g_qhi : ((blk == 1) ? g_khi : g_vhi);
        const float sc = (blk == 0) ? QSCALE : 1.0f;
        #pragma unroll
        for (int mt = 0; mt < 2; ++mt) {
            #pragma unroll
            for (int rr = 0; rr < 2; ++rr) {
                int mm = m0 + mrow + mt*16 + lr + rr*8;
                int b_ = mm >> 9, t_ = mm & 511;
                size_t obase = (((size_t)b_ * H_ + h) * T_ + t_) * 64;
                #pragma unroll
                for (int nt = 0; nt < 4; ++nt) {
                    int n = nbase + nt*8 + lc*2;
                    size_t o = obase + roffb + nt*8 + lc*2;
                    float v0 = (acc[mt][nt][rr*2+0] + bias[n])   * sc;
                    float v1 = (acc[mt][nt][rr*2+1] + bias[n+1]) * sc;
                    *(__half2*)(dst + o) = __floats2half2_rn(v0, v1);
                }
            }
        }
    }
}

// ------------------------ V transpose: [s][d] -> [d][s] ----------------------
__global__ void __launch_bounds__(256) k_vT() {
    __shared__ __half thi[64][72];
    const int s0 = blockIdx.x * 64;
    const int bh = blockIdx.y;
    const int tid = threadIdx.x;
    const int r = tid >> 2, cs = (tid & 3) * 16;
    const size_t sbase = ((size_t)bh * T_ + s0 + r) * 64 + cs;
    #pragma unroll
    for (int j = 0; j < 2; ++j)
        *(uint4*)&thi[r][cs + j*8] = *(const uint4*)(g_vhi + sbase + j*8);
    __syncthreads();
    const int d = tid >> 2, ss = (tid & 3) * 16;
    const size_t dbase = ((size_t)bh * 64 + d) * T_ + s0 + ss;
    #pragma unroll
    for (int j = 0; j < 2; ++j) {
        uint32_t ph[4];
        #pragma unroll
        for (int q = 0; q < 4; ++q) {
            int s = ss + j*8 + q*2;
            __half2 a; a.x = thi[s][d]; a.y = thi[s+1][d];
            ph[q] = *(uint32_t*)&a;
        }
        *(uint4*)(g_vthi + dbase + j*8) = *(uint4*)ph;
    }
}

// --------------------------- HMMA fused attention ----------------------------
// All operands single fp16. S: 1 MMA/step; PV: 1 MMA/step.
#define KSTR 144u
#define QSTR 144u
#define VTSTR 1040u
#define SM_K 0u            // 512*144 = 73728
#define SM_VT 0u           // 64*1040 = 66560 (overlays K)
#define SM_Q 73728u        // 9216
#define SM_OBUF 73728u     // 18432 (overlays Q after fragments in regs)
#define OSTRF 72
#define SM_EXM 92160u
#define SM_EXS 93184u
#define ATTN_SMEM 94208

__global__ void __launch_bounds__(512) attn_k(float* __restrict__ probs)
{
    extern __shared__ char smem[];
    const uint32_t sb = smem_u32(smem);
    const int tid = threadIdx.x;
    const int wid = tid >> 5, ln = tid & 31;
    const int wm = wid & 3, wq = wid >> 2;
    const int b = blockIdx.z, h = blockIdx.y, t0 = blockIdx.x * 64;
    const int bh = b * H_ + h;
    const int lr = ln >> 2, lc = ln & 3;

    // ---- load K (512 rows) + Q (64 rows) ----
    {
        const __half* khi = g_khi + (size_t)bh * T_ * 64;
        #pragma unroll
        for (int i = 0; i < 8; ++i) {
            int idx = tid + i * 512;
            int r = idx >> 3, sg = idx & 7;
            asm volatile("cp.async.cg.shared.global [%0], [%1], 16;"
                :: "r"(sb + SM_K + r*KSTR + sg*16), "l"(khi + (size_t)r*64 + sg*8));
        }
        const __half* qhi = g_qhi + ((size_t)bh * T_ + t0) * 64;
        {
            int r = tid >> 3, sg = tid & 7;
            asm volatile("cp.async.cg.shared.global [%0], [%1], 16;"
                :: "r"(sb + SM_Q + r*QSTR + sg*16), "l"(qhi + (size_t)r*64 + sg*8));
        }
        asm volatile("cp.async.commit_group;");
        asm volatile("cp.async.wait_group 0;");
    }
    __syncthreads();

    // ---- Q fragments ----
    uint32_t aH[4][4];
    {
        const int row = wm * 16 + lr;
        #pragma unroll
        for (int ks = 0; ks < 4; ++ks) {
            uint32_t off = row * QSTR + ks * 32 + lc * 4;
            aH[ks][0] = lds32(sb + SM_Q + off);
            aH[ks][1] = lds32(sb + SM_Q + off + 8*QSTR);
            aH[ks][2] = lds32(sb + SM_Q + off + 16);
            aH[ks][3] = lds32(sb + SM_Q + off + 8*QSTR + 16);
        }
    }

    // ---- S = Q K^T  (1 MMA per step) ----
    float acc[16][4];
    #pragma unroll
    for (int nt = 0; nt < 16; ++nt) { acc[nt][0]=acc[nt][1]=acc[nt][2]=acc[nt][3]=0.f; }
    #pragma unroll
    for (int nt = 0; nt < 16; ++nt) {
        uint32_t krow = (uint32_t)(wq * 128 + nt * 8 + lr);
        #pragma unroll
        for (int ks = 0; ks < 4; ++ks) {
            uint32_t boff = krow * KSTR + ks * 32 + lc * 4;
            uint32_t bh0 = lds32(sb + SM_K + boff);
            uint32_t bh1 = lds32(sb + SM_K + boff + 16);
            mma_f16(acc[nt], aH[ks], bh0, bh1);
        }
    }

    // ---- softmax over 512 keys ----
    const int row0 = wm * 16 + lr;
    {
        float mx0 = -1e30f, mx1 = -1e30f;
        #pragma unroll
        for (int nt = 0; nt < 16; ++nt) {
            mx0 = fmaxf(mx0, fmaxf(acc[nt][0], acc[nt][1]));
            mx1 = fmaxf(mx1, fmaxf(acc[nt][2], acc[nt][3]));
        }
        mx0 = fmaxf(mx0, __shfl_xor_sync(0xffffffffu, mx0, 1));
        mx0 = fmaxf(mx0, __shfl_xor_sync(0xffffffffu, mx0, 2));
        mx1 = fmaxf(mx1, __shfl_xor_sync(0xffffffffu, mx1, 1));
        mx1 = fmaxf(mx1, __shfl_xor_sync(0xffffffffu, mx1, 2));
        float* exm = (float*)(smem + SM_EXM);
        if (lc == 0) { exm[wq*64 + row0] = mx0; exm[wq*64 + row0 + 8] = mx1; }
        __syncthreads();     // all warps past S MMAs -> K region dead

        // ---- prefetch VT into K region ----
        {
            const __half* vthi = g_vthi + (size_t)bh * 64 * T_;
            #pragma unroll
            for (int i = 0; i < 8; ++i) {
                int idx = tid + i * 512;
                int d = idx >> 6, sg = idx & 63;
                asm volatile("cp.async.cg.shared.global [%0], [%1], 16;"
                    :: "r"(sb + SM_VT + d*VTSTR + sg*16), "l"(vthi + (size_t)d*T_ + sg*8));
            }
            asm volatile("cp.async.commit_group;");
        }

        float m0 = fmaxf(fmaxf(exm[row0],      exm[64+row0]),
                         fmaxf(exm[128+row0],  exm[192+row0]));
        float m1 = fmaxf(fmaxf(exm[row0+8],    exm[64+row0+8]),
                         fmaxf(exm[128+row0+8],exm[192+row0+8]));
        float s0 = 0.f, s1 = 0.f;
        #pragma unroll
        for (int nt = 0; nt < 16; ++nt) {
            acc[nt][0] = __expf(acc[nt][0] - m0); s0 += acc[nt][0];
            acc[nt][1] = __expf(acc[nt][1] - m0); s0 += acc[nt][1];
            acc[nt][2] = __expf(acc[nt][2] - m1); s1 += acc[nt][2];
            acc[nt][3] = __expf(acc[nt][3] - m1); s1 += acc[nt][3];
        }
        s0 += __shfl_xor_sync(0xffffffffu, s0, 1);
        s0 += __shfl_xor_sync(0xffffffffu, s0, 2);
        s1 += __shfl_xor_sync(0xffffffffu, s1, 1);
        s1 += __shfl_xor_sync(0xffffffffu, s1, 2);
        float* exs = (float*)(smem + SM_EXS);
        if (lc == 0) { exs[wq*64 + row0] = s0; exs[wq*64 + row0 + 8] = s1; }
        __syncthreads();
        float inv0 = 1.0f / (exs[row0] + exs[64+row0] + exs[128+row0] + exs[192+row0]);
        float inv1 = 1.0f / (exs[row0+8] + exs[64+row0+8] + exs[128+row0+8] + exs[192+row0+8]);
        #pragma unroll
        for (int nt = 0; nt < 16; ++nt) {
            acc[nt][0] *= inv0; acc[nt][1] *= inv0;
            acc[nt][2] *= inv1; acc[nt][3] *= inv1;
        }
    }

    // ---- wait VT, then PV with probs stores interleaved ----
    asm volatile("cp.async.wait_group 0;");
    __syncthreads();

    float* p0 = probs + ((size_t)bh * T_ + t0 + row0) * 512 + wq*128 + lc*2;
    float* p1 = p0 + (size_t)8 * 512;

    float oacc[8][4];
    #pragma unroll
    for (int dn = 0; dn < 8; ++dn) { oacc[dn][0]=oacc[dn][1]=oacc[dn][2]=oacc[dn][3]=0.f; }
    #pragma unroll
    for (int kk = 0; kk < 8; ++kk) {
        uint32_t phi[4];
        phi[0] = pack2h(acc[2*kk][0],   acc[2*kk][1]);
        phi[1] = pack2h(acc[2*kk][2],   acc[2*kk][3]);
        phi[2] = pack2h(acc[2*kk+1][0], acc[2*kk+1][1]);
        phi[3] = pack2h(acc[2*kk+1][2], acc[2*kk+1][3]);
        // interleaved probs stores (overlap STG with tensor work)
        {
            float2 v00 = {acc[2*kk][0],   acc[2*kk][1]};
            float2 v01 = {acc[2*kk][2],   acc[2*kk][3]};
            float2 v10 = {acc[2*kk+1][0], acc[2*kk+1][1]};
            float2 v11 = {acc[2*kk+1][2], acc[2*kk+1][3]};
            *(float2*)(p0 + (2*kk)*8)   = v00;
            *(float2*)(p1 + (2*kk)*8)   = v01;
            *(float2*)(p0 + (2*kk+1)*8) = v10;
            *(float2*)(p1 + (2*kk+1)*8) = v11;
        }
        uint32_t colV = (uint32_t)((wq*128 + kk*16 + lc*2) * 2);
        #pragma unroll
        for (int dn = 0; dn < 8; ++dn) {
            uint32_t vrow = (uint32_t)(dn*8 + lr);
            uint32_t offH = vrow * VTSTR + colV;
            uint32_t bh0 = lds32(sb + SM_VT + offH);
            uint32_t bh1 = lds32(sb + SM_VT + offH + 16);
            mma_f16(oacc[dn], phi, bh0, bh1);
        }
    }

    // ---- cross-warp reduce ----
    float* obuf = (float*)(smem + SM_OBUF);
    #pragma unroll
    for (int g = 0; g < 4; ++g) {
        if (wq == g) {
            #pragma unroll
            for (int dn = 0; dn < 8; ++dn) {
                int c = dn*8 + lc*2;
                float* b0 = obuf + row0 * OSTRF + c;
                float* b1 = obuf + (row0 + 8) * OSTRF + c;
                if (g == 0) {
                    b0[0] = oacc[dn][0]; b0[1] = oacc[dn][1];
                    b1[0] = oacc[dn][2]; b1[1] = oacc[dn][3];
                } else {
                    b0[0] += oacc[dn][0]; b0[1] += oacc[dn][1];
                    b1[0] += oacc[dn][2]; b1[1] += oacc[dn][3];
                }
            }
        }
        __syncthreads();
    }

    // ---- write O as hi-only 8B granules for OUT gemm ----
    {
        int row = tid >> 3, s2 = tid & 7;
        const float* src = obuf + row * OSTRF;
        size_t rb = ((size_t)b * T_ + t0 + row) * 1536 + (size_t)h * 128;
        #pragma unroll
        for (int u = 0; u < 2; ++u) {
            int s = s2 * 2 + u;
            int g = s >> 2, lcx = s & 3;
            int k0 = g * 16 + lcx * 2;
            uint32_t w[2];
            pack_g8(src[k0], src[k0+1], src[k0+8], src[k0+9], w);
            *(uint2*)(g_oh + rb + g*32 + lcx*8) = *(uint2*)w;
        }
    }
}

// --------------------------------- launcher ---------------------------------
extern "C" void kernel_launch(void* const* d_in, const int* in_sizes, int n_in,
                              void* d_out, int out_size)
{
    const float* x     = (const float*)d_in[0];
    const float* Wqkv  = (const float*)d_in[1];
    const float* bqkv  = (const float*)d_in[2];
    const float* Wph   = (const float*)d_in[3];
    const float* bph   = (const float*)d_in[4];
    const float* Wproj = (const float*)d_in[5];
    const float* bproj = (const float*)d_in[6];
    float* out = (float*)d_out;
    float* sa_out = out;
    float* probs  = out + (size_t)BT_*C_;

    uint8_t *xh_p, *wqh_p, *oh_p, *wch_p;
    float *wcomb_p, *bcomb_p;
    cudaGetSymbolAddress((void**)&xh_p,   g_xh);
    cudaGetSymbolAddress((void**)&wqh_p,  g_wqh);
    cudaGetSymbolAddress((void**)&oh_p,   g_oh);
    cudaGetSymbolAddress((void**)&wch_p,  g_wch);
    cudaGetSymbolAddress((void**)&wcomb_p, g_wcomb);
    cudaGetSymbolAddress((void**)&bcomb_p, g_bcomb);

    static int attrs_set = 0;
    if (!attrs_set) {
        cudaFuncSetAttribute(hmma_gemm<0>, cudaFuncAttributeMaxDynamicSharedMemorySize, HM_SMEM);
        cudaFuncSetAttribute(hmma_gemm<1>, cudaFuncAttributeMaxDynamicSharedMemorySize, HM_SMEM);
        cudaFuncSetAttribute(attn_k, cudaFuncAttributeMaxDynamicSharedMemorySize, ATTN_SMEM);
        attrs_set = 1;
    }

    // 1-3: prep on QKV critical path (+ wcomb zero / bcomb init)
    k_prep_xh<<<BT_*192/256, 256>>>(x);
    k_prep_wqh<<<NQKV_*192/256, 256>>>(Wqkv);
    k_binit<<<(C_*C_ + C_ + 255)/256, 256>>>(bproj);

    // 4: QKV GEMM (profiled slot) -> q/k/v fp16
    hmma_gemm<1><<<dim3(NQKV_/128, BT_/64), 256, HM_SMEM>>>(
        xh_p, wqh_p, nullptr, bqkv);

    // 5-7: Wcomb chain (independent of attention)
    k_bcomb<<<288, 256>>>(bph, Wproj);
    sgemm64ks<<<dim3(4, 12, 12), 256>>>(Wph, Wproj, wcomb_p);
    k_prep_wch<<<C_*192/256, 256>>>();

    // 8: V transpose
    k_vT<<<dim3(T_/64, B_*H_), 256>>>();

    // 9: fused attention -> probs + O(hi granules)
    attn_k<<<dim3(T_/64, H_, B_), 512, ATTN_SMEM>>>(probs);

    // 10: output GEMM + bcomb -> sa_out
    hmma_gemm<0><<<dim3(C_/128, BT_/64), 256, HM_SMEM>>>(
        oh_p, wch_p, sa_out, bcomb_p);
}

// round 15
// speedup vs baseline: 2.1823x; 1.0882x over previous
#include <cuda_runtime.h>
#include <cuda_fp16.h>
#include <stdint.h>
#include <math.h>

#define H_   12
#define T_   512
#define D_   64
#define C_   768
#define B_   32
#define NQKV_ 2304
#define BT_  16384
#define BHTD_ ((size_t)B_*H_*T_*D_)
#define QSCALE 0.125f

// ------------- device-global scratch (no runtime alloc allowed) -------------
// hi-only granule: 8B = [h(k),h(k+1),h(k+8),h(k+9)] fp16; row = 48 groups x 32B
__device__ __align__(16) uint8_t g_xh[(size_t)BT_*1536];
__device__ __align__(16) uint8_t g_wqh[(size_t)NQKV_*1536];
__device__ __align__(16) uint8_t g_oh[(size_t)BT_*1536];
__device__ __align__(16) uint8_t g_wch[(size_t)C_*1536];
__device__ __align__(16) __half g_qhi[BHTD_];
__device__ __align__(16) __half g_khi[BHTD_];
__device__ __align__(16) __half g_vhi[BHTD_];
__device__ __align__(16) __half g_vthi[BHTD_];   // [b,h,d,s]
__device__ __align__(16) float g_wcomb[C_*C_];
__device__ __align__(16) float g_bcomb[C_];

// ------------------------------ helpers -------------------------------------
__device__ __forceinline__ uint32_t smem_u32(const void* p) {
    uint32_t a;
    asm("{ .reg .u64 t; cvta.to.shared.u64 t, %1; cvt.u32.u64 %0, t; }"
        : "=r"(a) : "l"(p));
    return a;
}
__device__ __forceinline__ void mma_f16(float* c, const uint32_t* a,
                                        uint32_t b0, uint32_t b1) {
    asm volatile(
        "mma.sync.aligned.m16n8k16.row.col.f32.f16.f16.f32 "
        "{%0,%1,%2,%3}, {%4,%5,%6,%7}, {%8,%9}, {%0,%1,%2,%3};"
        : "+f"(c[0]), "+f"(c[1]), "+f"(c[2]), "+f"(c[3])
        : "r"(a[0]), "r"(a[1]), "r"(a[2]), "r"(a[3]), "r"(b0), "r"(b1));
}
__device__ __forceinline__ uint32_t lds32(uint32_t a) {
    uint32_t v;
    asm volatile("ld.shared.b32 %0, [%1];" : "=r"(v) : "r"(a));
    return v;
}
__device__ __forceinline__ void lds64(uint32_t a, uint32_t& x, uint32_t& y) {
    asm volatile("ld.shared.v2.b32 {%0,%1}, [%2];" : "=r"(x), "=r"(y) : "r"(a));
}
__device__ __forceinline__ uint32_t pack2h(float a, float b) {
    __half2 t = __floats2half2_rn(a, b);
    return *(uint32_t*)&t;
}
// 8B hi-only granule from 4 fp32 (k, k+1, k+8, k+9)
__device__ __forceinline__ void pack_g8(float f0, float f1, float f2, float f3,
                                        uint32_t* w) {
    w[0] = pack2h(f0, f1);
    w[1] = pack2h(f2, f3);
}

// ------------------------------ prep kernels --------------------------------
__global__ void __launch_bounds__(256) k_prep_xh(const float* __restrict__ x) {
    int gid = blockIdx.x * 256 + threadIdx.x;     // BT*192 sub-granules
    int lc = gid & 3, g = (gid >> 2) % 48;
    int m = gid / 192;
    const float* xr = x + (size_t)m * 768 + g * 16 + lc * 2;
    uint32_t w[2];
    pack_g8(xr[0], xr[1], xr[8], xr[9], w);
    *(uint2*)(g_xh + (size_t)m * 1536 + g * 32 + lc * 8) = *(uint2*)w;
}

__global__ void __launch_bounds__(256) k_prep_wqh(const float* __restrict__ W) {
    int gid = blockIdx.x * 256 + threadIdx.x;
    int lc = gid & 3, g = (gid >> 2) % 48;
    int n = gid / 192;
    int h = n / 192, j = n % 192;
    const float* wb = W + ((size_t)h * 768 + g * 16 + lc * 2) * 192 + j;
    uint32_t w[2];
    pack_g8(wb[0], wb[192], wb[8*192], wb[9*192], w);
    *(uint2*)(g_wqh + (size_t)n * 1536 + g * 32 + lc * 8) = *(uint2*)w;
}

__global__ void __launch_bounds__(256) k_prep_wch() {
    int gid = blockIdx.x * 256 + threadIdx.x;
    int lc = gid & 3, g = (gid >> 2) % 48;
    int n = gid / 192;
    int k0 = g * 16 + lc * 2;
    uint32_t w[2];
    pack_g8(g_wcomb[(size_t)k0*768 + n],     g_wcomb[(size_t)(k0+1)*768 + n],
            g_wcomb[(size_t)(k0+8)*768 + n], g_wcomb[(size_t)(k0+9)*768 + n], w);
    *(uint2*)(g_wch + (size_t)n * 1536 + g * 32 + lc * 8) = *(uint2*)w;
}

// zero g_wcomb + init g_bcomb = bproj
__global__ void __launch_bounds__(256) k_binit(const float* __restrict__ bproj) {
    int idx = blockIdx.x * 256 + threadIdx.x;
    if (idx < C_*C_) g_wcomb[idx] = 0.0f;
    int j = idx - C_*C_;
    if (j >= 0 && j < C_) g_bcomb[j] = bproj[j];
}

__global__ void __launch_bounds__(256) k_bcomb(const float* __restrict__ bph,
                                               const float* __restrict__ Wproj) {
    int r0 = blockIdx.x * 32;
    int t = threadIdx.x;
    float a0 = 0.f, a1 = 0.f, a2 = 0.f;
    for (int rr = 0; rr < 32; ++rr) {
        int r = r0 + rr;
        float bv = bph[r];
        const float* wr = Wproj + (size_t)r * C_;
        a0 = fmaf(bv, wr[t],       a0);
        a1 = fmaf(bv, wr[t + 256], a1);
        a2 = fmaf(bv, wr[t + 512], a2);
    }
    atomicAdd(&g_bcomb[t],       a0);
    atomicAdd(&g_bcomb[t + 256], a1);
    atomicAdd(&g_bcomb[t + 512], a2);
}

// ------- Wcomb precompute: fp32, 4-way K-split, atomic accumulate -----------
__global__ void __launch_bounds__(256) sgemm64ks(
    const float* __restrict__ A, const float* __restrict__ Bm,
    float* __restrict__ Cm)
{
    __shared__ float As[16][68];
    __shared__ float Bs[16][68];
    const int z = blockIdx.z;
    const float* Ab = A  + (size_t)z * 64 * C_;
    const float* Bb = Bm + (size_t)z * C_ * C_;
    float*       Cb = Cm + (size_t)z * 64 * C_;
    const int tid = threadIdx.x;
    const int tx = tid % 16, ty = tid / 16;
    const int n0 = blockIdx.y * 64;
    const int kbeg = blockIdx.x * 192, kend = kbeg + 192;
    float acc[4][4] = {};
    for (int kt = kbeg; kt < kend; kt += 16) {
        {
            int m = tid / 4, kq = (tid % 4) * 4;
            float4 v = *(const float4*)(Ab + (size_t)m*C_ + kt + kq);
            As[kq+0][m] = v.x; As[kq+1][m] = v.y; As[kq+2][m] = v.z; As[kq+3][m] = v.w;
        }
        {
            int kk = tid / 16, nn = (tid % 16) * 4;
            *(float4*)&Bs[kk][nn] = *(const float4*)(Bb + (size_t)(kt+kk)*C_ + n0 + nn);
        }
        __syncthreads();
        #pragma unroll
        for (int k = 0; k < 16; ++k) {
            float a[4], b[4];
            #pragma unroll
            for (int i = 0; i < 4; ++i) a[i] = As[k][ty*4+i];
            *(float4*)b = *(const float4*)&Bs[k][tx*4];
            #pragma unroll
            for (int i = 0; i < 4; ++i)
                #pragma unroll
                for (int j = 0; j < 4; ++j)
                    acc[i][j] = fmaf(a[i], b[j], acc[i][j]);
        }
        __syncthreads();
    }
    #pragma unroll
    for (int i = 0; i < 4; ++i) {
        int m = ty*4 + i;
        #pragma unroll
        for (int j = 0; j < 4; ++j)
            atomicAdd(&Cb[(size_t)m*C_ + n0 + tx*4 + j], acc[i][j]);
    }
}

// --------- HMMA fp16 single-term GEMM, 128x128 CTA, 32x64 warp tile ---------
// A and B hi-only 8B granules; smem rows 64B/chunk + 32B XOR swizzle on
// (row&2) (verified conflict-free for lds64 phases).
#define RSTR 64
#define ATILE (128*RSTR)      // 8192
#define BTILE (128*RSTR)      // 8192
#define GSTAGE (ATILE+BTILE)  // 16384
#define HM_SMEM (2*GSTAGE)    // 32768

template<int EPI>
__global__ void __launch_bounds__(256, 2) hmma_gemm(
    const uint8_t* __restrict__ Ac, const uint8_t* __restrict__ Bc,
    float* __restrict__ Cout, const float* __restrict__ bias)
{
    extern __shared__ char smem[];
    const uint32_t sbase = smem_u32(smem);
    const int tid = threadIdx.x;
    const int wid = tid >> 5, ln = tid & 31;
    const int n0 = blockIdx.x * 128, m0 = blockIdx.y * 128;
    const int wm = wid & 3, wn = wid >> 2;      // 4 x 2 warp grid
    const int mrow = wm * 32, ncol = wn * 64;
    const int lr = ln >> 2, lc = ln & 3;
    const int lrb = (lr >> 1) & 1;

    const uint8_t* gA = Ac + (size_t)m0 * 1536;
    const uint8_t* gB = Bc + (size_t)n0 * 1536;

    auto load_chunk = [&](int kc, int stage) {
        uint32_t sb = sbase + stage * GSTAGE;
        const uint8_t* pA = gA + kc * 64;       // 64B per row per chunk
        #pragma unroll
        for (int i = 0; i < 4; ++i) {
            int gid = tid + i * 256;            // 0..1023 : 128 rows x 8 grans
            int r = gid >> 3, c = gid & 7;
            int gg = c >> 2, lcx = c & 3;
            uint32_t doff = (uint32_t)(c*8) ^ (uint32_t)((r & 2) << 4);
            asm volatile("cp.async.ca.shared.global [%0], [%1], 8;"
                :: "r"(sb + r*RSTR + doff), "l"(pA + (size_t)r*1536 + gg*32 + lcx*8));
        }
        const uint8_t* pB = gB + kc * 64;
        uint32_t bb = sb + ATILE;
        #pragma unroll
        for (int i = 0; i < 4; ++i) {
            int gid = tid + i * 256;
            int r = gid >> 3, c = gid & 7;
            int gg = c >> 2, lcx = c & 3;
            uint32_t doff = (uint32_t)(c*8) ^ (uint32_t)((r & 2) << 4);
            asm volatile("cp.async.ca.shared.global [%0], [%1], 8;"
                :: "r"(bb + r*RSTR + doff), "l"(pB + (size_t)r*1536 + gg*32 + lcx*8));
        }
        asm volatile("cp.async.commit_group;");
    };

    float acc[2][8][4] = {};
    load_chunk(0, 0);
    for (int c = 0; c < 24; ++c) {
        int s = c & 1;
        asm volatile("cp.async.wait_group 0;");
        __syncthreads();                 // also protects stage s^1 reuse below
        if (c + 1 < 24) load_chunk(c + 1, s ^ 1);

        uint32_t sA = sbase + s * GSTAGE;
        uint32_t aBr = sA + (uint32_t)((mrow + lr)*RSTR + lc*8);
        uint32_t bBr = sA + ATILE + (uint32_t)((ncol + lr)*RSTR + lc*8);

        #pragma unroll
        for (int ks = 0; ks < 2; ++ks) {
            const uint32_t ksB = (uint32_t)((ks ^ lrb) * 32);
            uint32_t aF[2][4];
            #pragma unroll
            for (int mt = 0; mt < 2; ++mt) {
                uint32_t base = aBr + mt*16*RSTR + ksB;
                lds64(base,          aF[mt][0], aF[mt][2]);
                lds64(base + 8*RSTR, aF[mt][1], aF[mt][3]);
            }
            #pragma unroll
            for (int nt = 0; nt < 8; ++nt) {
                uint32_t b0, b1;
                lds64(bBr + nt*8*RSTR + ksB, b0, b1);
                #pragma unroll
                for (int mt = 0; mt < 2; ++mt)
                    mma_f16(acc[mt][nt], aF[mt], b0, b1);
            }
        }
        // no trailing sync: next iteration's barrier protects buffer reuse
    }

    // ------------------------------- epilogue --------------------------------
    if (EPI == 0) {
        #pragma unroll
        for (int mt = 0; mt < 2; ++mt) {
            int m = m0 + mrow + mt*16 + lr;
            #pragma unroll
            for (int nt = 0; nt < 8; ++nt) {
                int n = n0 + ncol + nt*8 + lc*2;
                float b0 = bias[n], b1 = bias[n+1];
                float* ac = acc[mt][nt];
                float2 v0 = {ac[0] + b0, ac[1] + b1};
                float2 v1 = {ac[2] + b0, ac[3] + b1};
                *(float2*)(Cout + (size_t)m * C_ + n) = v0;
                *(float2*)(Cout + (size_t)(m+8) * C_ + n) = v1;
            }
        }
    } else {
        const int nbase = n0 + ncol;                 // 64-aligned, single blk
        const int h = nbase / 192, rbase = nbase % 192;
        const int blk = rbase >> 6;
        __half* dst = (blk == 0) ? g_qhi : ((blk == 1) ? g_khi : g_vhi);
        const float sc = (blk == 0) ? QSCALE : 1.0f;
        #pragma unroll
        for (int mt = 0; mt < 2; ++mt) {
            #pragma unroll
            for (int rr = 0; rr < 2; ++rr) {
                int mm = m0 + mrow + mt*16 + lr + rr*8;
                int b_ = mm >> 9, t_ = mm & 511;
                size_t obase = (((size_t)b_ * H_ + h) * T_ + t_) * 64;
                #pragma unroll
                for (int nt = 0; nt < 8; ++nt) {
                    int n = nbase + nt*8 + lc*2;
                    size_t o = obase + nt*8 + lc*2;
                    float v0 = (acc[mt][nt][rr*2+0] + bias[n])   * sc;
                    float v1 = (acc[mt][nt][rr*2+1] + bias[n+1]) * sc;
                    *(__half2*)(dst + o) = __floats2half2_rn(v0, v1);
                }
            }
        }
    }
}

// ------------------------ V transpose: [s][d] -> [d][s] ----------------------
__global__ void __launch_bounds__(256) k_vT() {
    __shared__ __half thi[64][72];
    const int s0 = blockIdx.x * 64;
    const int bh = blockIdx.y;
    const int tid = threadIdx.x;
    const int r = tid >> 2, cs = (tid & 3) * 16;
    const size_t sbase = ((size_t)bh * T_ + s0 + r) * 64 + cs;
    #pragma unroll
    for (int j = 0; j < 2; ++j)
        *(uint4*)&thi[r][cs + j*8] = *(const uint4*)(g_vhi + sbase + j*8);
    __syncthreads();
    const int d = tid >> 2, ss = (tid & 3) * 16;
    const size_t dbase = ((size_t)bh * 64 + d) * T_ + s0 + ss;
    #pragma unroll
    for (int j = 0; j < 2; ++j) {
        uint32_t ph[4];
        #pragma unroll
        for (int q = 0; q < 4; ++q) {
            int s = ss + j*8 + q*2;
            __half2 a; a.x = thi[s][d]; a.y = thi[s+1][d];
            ph[q] = *(uint32_t*)&a;
        }
        *(uint4*)(g_vthi + dbase + j*8) = *(uint4*)ph;
    }
}

// --------------------------- HMMA fused attention ----------------------------
// All operands single fp16. S: 1 MMA/step; PV: 1 MMA/step.
#define KSTR 144u
#define QSTR 144u
#define VTSTR 1040u
#define SM_K 0u            // 512*144 = 73728
#define SM_VT 0u           // 64*1040 = 66560 (overlays K)
#define SM_Q 73728u        // 9216
#define SM_OBUF 73728u     // 18432 (overlays Q after fragments in regs)
#define OSTRF 72
#define SM_EXM 92160u
#define SM_EXS 93184u
#define ATTN_SMEM 94208

__global__ void __launch_bounds__(512) attn_k(float* __restrict__ probs)
{
    extern __shared__ char smem[];
    const uint32_t sb = smem_u32(smem);
    const int tid = threadIdx.x;
    const int wid = tid >> 5, ln = tid & 31;
    const int wm = wid & 3, wq = wid >> 2;
    const int b = blockIdx.z, h = blockIdx.y, t0 = blockIdx.x * 64;
    const int bh = b * H_ + h;
    const int lr = ln >> 2, lc = ln & 3;

    // ---- load K (512 rows) + Q (64 rows) ----
    {
        const __half* khi = g_khi + (size_t)bh * T_ * 64;
        #pragma unroll
        for (int i = 0; i < 8; ++i) {
            int idx = tid + i * 512;
            int r = idx >> 3, sg = idx & 7;
            asm volatile("cp.async.cg.shared.global [%0], [%1], 16;"
                :: "r"(sb + SM_K + r*KSTR + sg*16), "l"(khi + (size_t)r*64 + sg*8));
        }
        const __half* qhi = g_qhi + ((size_t)bh * T_ + t0) * 64;
        {
            int r = tid >> 3, sg = tid & 7;
            asm volatile("cp.async.cg.shared.global [%0], [%1], 16;"
                :: "r"(sb + SM_Q + r*QSTR + sg*16), "l"(qhi + (size_t)r*64 + sg*8));
        }
        asm volatile("cp.async.commit_group;");
        asm volatile("cp.async.wait_group 0;");
    }
    __syncthreads();

    // ---- Q fragments ----
    uint32_t aH[4][4];
    {
        const int row = wm * 16 + lr;
        #pragma unroll
        for (int ks = 0; ks < 4; ++ks) {
            uint32_t off = row * QSTR + ks * 32 + lc * 4;
            aH[ks][0] = lds32(sb + SM_Q + off);
            aH[ks][1] = lds32(sb + SM_Q + off + 8*QSTR);
            aH[ks][2] = lds32(sb + SM_Q + off + 16);
            aH[ks][3] = lds32(sb + SM_Q + off + 8*QSTR + 16);
        }
    }

    // ---- S = Q K^T  (1 MMA per step) ----
    float acc[16][4];
    #pragma unroll
    for (int nt = 0; nt < 16; ++nt) { acc[nt][0]=acc[nt][1]=acc[nt][2]=acc[nt][3]=0.f; }
    #pragma unroll
    for (int nt = 0; nt < 16; ++nt) {
        uint32_t krow = (uint32_t)(wq * 128 + nt * 8 + lr);
        #pragma unroll
        for (int ks = 0; ks < 4; ++ks) {
            uint32_t boff = krow * KSTR + ks * 32 + lc * 4;
            uint32_t bh0 = lds32(sb + SM_K + boff);
            uint32_t bh1 = lds32(sb + SM_K + boff + 16);
            mma_f16(acc[nt], aH[ks], bh0, bh1);
        }
    }

    // ---- softmax over 512 keys ----
    const int row0 = wm * 16 + lr;
    {
        float mx0 = -1e30f, mx1 = -1e30f;
        #pragma unroll
        for (int nt = 0; nt < 16; ++nt) {
            mx0 = fmaxf(mx0, fmaxf(acc[nt][0], acc[nt][1]));
            mx1 = fmaxf(mx1, fmaxf(acc[nt][2], acc[nt][3]));
        }
        mx0 = fmaxf(mx0, __shfl_xor_sync(0xffffffffu, mx0, 1));
        mx0 = fmaxf(mx0, __shfl_xor_sync(0xffffffffu, mx0, 2));
        mx1 = fmaxf(mx1, __shfl_xor_sync(0xffffffffu, mx1, 1));
        mx1 = fmaxf(mx1, __shfl_xor_sync(0xffffffffu, mx1, 2));
        float* exm = (float*)(smem + SM_EXM);
        if (lc == 0) { exm[wq*64 + row0] = mx0; exm[wq*64 + row0 + 8] = mx1; }
        __syncthreads();     // all warps past S MMAs -> K region dead

        // ---- prefetch VT into K region ----
        {
            const __half* vthi = g_vthi + (size_t)bh * 64 * T_;
            #pragma unroll
            for (int i = 0; i < 8; ++i) {
                int idx = tid + i * 512;
                int d = idx >> 6, sg = idx & 63;
                asm volatile("cp.async.cg.shared.global [%0], [%1], 16;"
                    :: "r"(sb + SM_VT + d*VTSTR + sg*16), "l"(vthi + (size_t)d*T_ + sg*8));
            }
            asm volatile("cp.async.commit_group;");
        }

        float m0 = fmaxf(fmaxf(exm[row0],      exm[64+row0]),
                         fmaxf(exm[128+row0],  exm[192+row0]));
        float m1 = fmaxf(fmaxf(exm[row0+8],    exm[64+row0+8]),
                         fmaxf(exm[128+row0+8],exm[192+row0+8]));
        float s0 = 0.f, s1 = 0.f;
        #pragma unroll
        for (int nt = 0; nt < 16; ++nt) {
            acc[nt][0] = __expf(acc[nt][0] - m0); s0 += acc[nt][0];
            acc[nt][1] = __expf(acc[nt][1] - m0); s0 += acc[nt][1];
            acc[nt][2] = __expf(acc[nt][2] - m1); s1 += acc[nt][2];
            acc[nt][3] = __expf(acc[nt][3] - m1); s1 += acc[nt][3];
        }
        s0 += __shfl_xor_sync(0xffffffffu, s0, 1);
        s0 += __shfl_xor_sync(0xffffffffu, s0, 2);
        s1 += __shfl_xor_sync(0xffffffffu, s1, 1);
        s1 += __shfl_xor_sync(0xffffffffu, s1, 2);
        float* exs = (float*)(smem + SM_EXS);
        if (lc == 0) { exs[wq*64 + row0] = s0; exs[wq*64 + row0 + 8] = s1; }
        __syncthreads();
        float inv0 = 1.0f / (exs[row0] + exs[64+row0] + exs[128+row0] + exs[192+row0]);
        float inv1 = 1.0f / (exs[row0+8] + exs[64+row0+8] + exs[128+row0+8] + exs[192+row0+8]);
        #pragma unroll
        for (int nt = 0; nt < 16; ++nt) {
            acc[nt][0] *= inv0; acc[nt][1] *= inv0;
            acc[nt][2] *= inv1; acc[nt][3] *= inv1;
        }
    }

    // ---- wait VT, then PV with probs stores interleaved ----
    asm volatile("cp.async.wait_group 0;");
    __syncthreads();

    float* p0 = probs + ((size_t)bh * T_ + t0 + row0) * 512 + wq*128 + lc*2;
    float* p1 = p0 + (size_t)8 * 512;

    float oacc[8][4];
    #pragma unroll
    for (int dn = 0; dn < 8; ++dn) { oacc[dn][0]=oacc[dn][1]=oacc[dn][2]=oacc[dn][3]=0.f; }
    #pragma unroll
    for (int kk = 0; kk < 8; ++kk) {
        uint32_t phi[4];
        phi[0] = pack2h(acc[2*kk][0],   acc[2*kk][1]);
        phi[1] = pack2h(acc[2*kk][2],   acc[2*kk][3]);
        phi[2] = pack2h(acc[2*kk+1][0], acc[2*kk+1][1]);
        phi[3] = pack2h(acc[2*kk+1][2], acc[2*kk+1][3]);
        // interleaved probs stores (overlap STG with tensor work)
        {
            float2 v00 = {acc[2*kk][0],   acc[2*kk][1]};
            float2 v01 = {acc[2*kk][2],   acc[2*kk][3]};
            float2 v10 = {acc[2*kk+1][0], acc[2*kk+1][1]};
            float2 v11 = {acc[2*kk+1][2], acc[2*kk+1][3]};
            *(float2*)(p0 + (2*kk)*8)   = v00;
            *(float2*)(p1 + (2*kk)*8)   = v01;
            *(float2*)(p0 + (2*kk+1)*8) = v10;
            *(float2*)(p1 + (2*kk+1)*8) = v11;
        }
        uint32_t colV = (uint32_t)((wq*128 + kk*16 + lc*2) * 2);
        #pragma unroll
        for (int dn = 0; dn < 8; ++dn) {
            uint32_t vrow = (uint32_t)(dn*8 + lr);
            uint32_t offH = vrow * VTSTR + colV;
            uint32_t bh0 = lds32(sb + SM_VT + offH);
            uint32_t bh1 = lds32(sb + SM_VT + offH + 16);
            mma_f16(oacc[dn], phi, bh0, bh1);
        }
    }

    // ---- cross-warp reduce ----
    float* obuf = (float*)(smem + SM_OBUF);
    #pragma unroll
    for (int g = 0; g < 4; ++g) {
        if (wq == g) {
            #pragma unroll
            for (int dn = 0; dn < 8; ++dn) {
                int c = dn*8 + lc*2;
                float* b0 = obuf + row0 * OSTRF + c;
                float* b1 = obuf + (row0 + 8) * OSTRF + c;
                if (g == 0) {
                    b0[0] = oacc[dn][0]; b0[1] = oacc[dn][1];
                    b1[0] = oacc[dn][2]; b1[1] = oacc[dn][3];
                } else {
                    b0[0] += oacc[dn][0]; b0[1] += oacc[dn][1];
                    b1[0] += oacc[dn][2]; b1[1] += oacc[dn][3];
                }
            }
        }
        __syncthreads();
    }

    // ---- write O as hi-only 8B granules for OUT gemm ----
    {
        int row = tid >> 3, s2 = tid & 7;
        const float* src = obuf + row * OSTRF;
        size_t rb = ((size_t)b * T_ + t0 + row) * 1536 + (size_t)h * 128;
        #pragma unroll
        for (int u = 0; u < 2; ++u) {
            int s = s2 * 2 + u;
            int g = s >> 2, lcx = s & 3;
            int k0 = g * 16 + lcx * 2;
            uint32_t w[2];
            pack_g8(src[k0], src[k0+1], src[k0+8], src[k0+9], w);
            *(uint2*)(g_oh + rb + g*32 + lcx*8) = *(uint2*)w;
        }
    }
}

// --------------------------------- launcher ---------------------------------
extern "C" void kernel_launch(void* const* d_in, const int* in_sizes, int n_in,
                              void* d_out, int out_size)
{
    const float* x     = (const float*)d_in[0];
    const float* Wqkv  = (const float*)d_in[1];
    const float* bqkv  = (const float*)d_in[2];
    const float* Wph   = (const float*)d_in[3];
    const float* bph   = (const float*)d_in[4];
    const float* Wproj = (const float*)d_in[5];
    const float* bproj = (const float*)d_in[6];
    float* out = (float*)d_out;
    float* sa_out = out;
    float* probs  = out + (size_t)BT_*C_;

    uint8_t *xh_p, *wqh_p, *oh_p, *wch_p;
    float *wcomb_p, *bcomb_p;
    cudaGetSymbolAddress((void**)&xh_p,   g_xh);
    cudaGetSymbolAddress((void**)&wqh_p,  g_wqh);
    cudaGetSymbolAddress((void**)&oh_p,   g_oh);
    cudaGetSymbolAddress((void**)&wch_p,  g_wch);
    cudaGetSymbolAddress((void**)&wcomb_p, g_wcomb);
    cudaGetSymbolAddress((void**)&bcomb_p, g_bcomb);

    static int attrs_set = 0;
    if (!attrs_set) {
        cudaFuncSetAttribute(hmma_gemm<0>, cudaFuncAttributeMaxDynamicSharedMemorySize, HM_SMEM);
        cudaFuncSetAttribute(hmma_gemm<1>, cudaFuncAttributeMaxDynamicSharedMemorySize, HM_SMEM);
        cudaFuncSetAttribute(attn_k, cudaFuncAttributeMaxDynamicSharedMemorySize, ATTN_SMEM);
        attrs_set = 1;
    }

    // 1-3: prep on QKV critical path (+ wcomb zero / bcomb init)
    k_prep_xh<<<BT_*192/256, 256>>>(x);
    k_prep_wqh<<<NQKV_*192/256, 256>>>(Wqkv);
    k_binit<<<(C_*C_ + C_ + 255)/256, 256>>>(bproj);

    // 4: QKV GEMM (profiled slot) -> q/k/v fp16
    hmma_gemm<1><<<dim3(NQKV_/128, BT_/128), 256, HM_SMEM>>>(
        xh_p, wqh_p, nullptr, bqkv);

    // 5-7: Wcomb chain (independent of attention)
    k_bcomb<<<288, 256>>>(bph, Wproj);
    sgemm64ks<<<dim3(4, 12, 12), 256>>>(Wph, Wproj, wcomb_p);
    k_prep_wch<<<C_*192/256, 256>>>();

    // 8: V transpose
    k_vT<<<dim3(T_/64, B_*H_), 256>>>();

    // 9: fused attention -> probs + O(hi granules)
    attn_k<<<dim3(T_/64, H_, B_), 512, ATTN_SMEM>>>(probs);

    // 10: output GEMM + bcomb -> sa_out
    hmma_gemm<0><<<dim3(C_/128, BT_/128), 256, HM_SMEM>>>(
        oh_p, wch_p, sa_out, bcomb_p);
}

// round 16
// speedup vs baseline: 2.1911x; 1.0040x over previous
#include <cuda_runtime.h>
#include <cuda_fp16.h>
#include <stdint.h>
#include <math.h>

#define H_   12
#define T_   512
#define D_   64
#define C_   768
#define B_   32
#define NQKV_ 2304
#define BT_  16384
#define BHTD_ ((size_t)B_*H_*T_*D_)
#define QSCALE 0.125f

// ------------- device-global scratch (no runtime alloc allowed) -------------
// hi-only granule: 8B = [h(k),h(k+1),h(k+8),h(k+9)] fp16; row = 48 groups x 32B
__device__ __align__(16) uint8_t g_xh[(size_t)BT_*1536];
__device__ __align__(16) uint8_t g_wqh[(size_t)NQKV_*1536];
__device__ __align__(16) uint8_t g_oh[(size_t)BT_*1536];
__device__ __align__(16) uint8_t g_wch[(size_t)C_*1536];
__device__ __align__(16) __half g_qhi[BHTD_];
__device__ __align__(16) __half g_khi[BHTD_];
__device__ __align__(16) __half g_vhi[BHTD_];
__device__ __align__(16) __half g_vthi[BHTD_];   // [b,h,d,s]
__device__ __align__(16) float g_wcomb[C_*C_];
__device__ __align__(16) float g_bcomb[C_];

// ------------------------------ helpers -------------------------------------
__device__ __forceinline__ uint32_t smem_u32(const void* p) {
    uint32_t a;
    asm("{ .reg .u64 t; cvta.to.shared.u64 t, %1; cvt.u32.u64 %0, t; }"
        : "=r"(a) : "l"(p));
    return a;
}
__device__ __forceinline__ void mma_f16(float* c, const uint32_t* a,
                                        uint32_t b0, uint32_t b1) {
    asm volatile(
        "mma.sync.aligned.m16n8k16.row.col.f32.f16.f16.f32 "
        "{%0,%1,%2,%3}, {%4,%5,%6,%7}, {%8,%9}, {%0,%1,%2,%3};"
        : "+f"(c[0]), "+f"(c[1]), "+f"(c[2]), "+f"(c[3])
        : "r"(a[0]), "r"(a[1]), "r"(a[2]), "r"(a[3]), "r"(b0), "r"(b1));
}
__device__ __forceinline__ uint32_t lds32(uint32_t a) {
    uint32_t v;
    asm volatile("ld.shared.b32 %0, [%1];" : "=r"(v) : "r"(a));
    return v;
}
__device__ __forceinline__ void lds64(uint32_t a, uint32_t& x, uint32_t& y) {
    asm volatile("ld.shared.v2.b32 {%0,%1}, [%2];" : "=r"(x), "=r"(y) : "r"(a));
}
__device__ __forceinline__ uint32_t pack2h(float a, float b) {
    __half2 t = __floats2half2_rn(a, b);
    return *(uint32_t*)&t;
}
// 8B hi-only granule from 4 fp32 (k, k+1, k+8, k+9)
__device__ __forceinline__ void pack_g8(float f0, float f1, float f2, float f3,
                                        uint32_t* w) {
    w[0] = pack2h(f0, f1);
    w[1] = pack2h(f2, f3);
}

// ------------------------------ prep kernels --------------------------------
__global__ void __launch_bounds__(256) k_prep_xh(const float* __restrict__ x) {
    int gid = blockIdx.x * 256 + threadIdx.x;     // BT*192 sub-granules
    int lc = gid & 3, g = (gid >> 2) % 48;
    int m = gid / 192;
    const float* xr = x + (size_t)m * 768 + g * 16 + lc * 2;
    uint32_t w[2];
    pack_g8(xr[0], xr[1], xr[8], xr[9], w);
    *(uint2*)(g_xh + (size_t)m * 1536 + g * 32 + lc * 8) = *(uint2*)w;
}

__global__ void __launch_bounds__(256) k_prep_wqh(const float* __restrict__ W) {
    int gid = blockIdx.x * 256 + threadIdx.x;
    int lc = gid & 3, g = (gid >> 2) % 48;
    int n = gid / 192;
    int h = n / 192, j = n % 192;
    const float* wb = W + ((size_t)h * 768 + g * 16 + lc * 2) * 192 + j;
    uint32_t w[2];
    pack_g8(wb[0], wb[192], wb[8*192], wb[9*192], w);
    *(uint2*)(g_wqh + (size_t)n * 1536 + g * 32 + lc * 8) = *(uint2*)w;
}

__global__ void __launch_bounds__(256) k_prep_wch() {
    int gid = blockIdx.x * 256 + threadIdx.x;
    int lc = gid & 3, g = (gid >> 2) % 48;
    int n = gid / 192;
    int k0 = g * 16 + lc * 2;
    uint32_t w[2];
    pack_g8(g_wcomb[(size_t)k0*768 + n],     g_wcomb[(size_t)(k0+1)*768 + n],
            g_wcomb[(size_t)(k0+8)*768 + n], g_wcomb[(size_t)(k0+9)*768 + n], w);
    *(uint2*)(g_wch + (size_t)n * 1536 + g * 32 + lc * 8) = *(uint2*)w;
}

// zero g_wcomb + init g_bcomb = bproj
__global__ void __launch_bounds__(256) k_binit(const float* __restrict__ bproj) {
    int idx = blockIdx.x * 256 + threadIdx.x;
    if (idx < C_*C_) g_wcomb[idx] = 0.0f;
    int j = idx - C_*C_;
    if (j >= 0 && j < C_) g_bcomb[j] = bproj[j];
}

__global__ void __launch_bounds__(256) k_bcomb(const float* __restrict__ bph,
                                               const float* __restrict__ Wproj) {
    int r0 = blockIdx.x * 32;
    int t = threadIdx.x;
    float a0 = 0.f, a1 = 0.f, a2 = 0.f;
    for (int rr = 0; rr < 32; ++rr) {
        int r = r0 + rr;
        float bv = bph[r];
        const float* wr = Wproj + (size_t)r * C_;
        a0 = fmaf(bv, wr[t],       a0);
        a1 = fmaf(bv, wr[t + 256], a1);
        a2 = fmaf(bv, wr[t + 512], a2);
    }
    atomicAdd(&g_bcomb[t],       a0);
    atomicAdd(&g_bcomb[t + 256], a1);
    atomicAdd(&g_bcomb[t + 512], a2);
}

// ------- Wcomb precompute: fp32, 4-way K-split, atomic accumulate -----------
__global__ void __launch_bounds__(256) sgemm64ks(
    const float* __restrict__ A, const float* __restrict__ Bm,
    float* __restrict__ Cm)
{
    __shared__ float As[16][68];
    __shared__ float Bs[16][68];
    const int z = blockIdx.z;
    const float* Ab = A  + (size_t)z * 64 * C_;
    const float* Bb = Bm + (size_t)z * C_ * C_;
    float*       Cb = Cm + (size_t)z * 64 * C_;
    const int tid = threadIdx.x;
    const int tx = tid % 16, ty = tid / 16;
    const int n0 = blockIdx.y * 64;
    const int kbeg = blockIdx.x * 192, kend = kbeg + 192;
    float acc[4][4] = {};
    for (int kt = kbeg; kt < kend; kt += 16) {
        {
            int m = tid / 4, kq = (tid % 4) * 4;
            float4 v = *(const float4*)(Ab + (size_t)m*C_ + kt + kq);
            As[kq+0][m] = v.x; As[kq+1][m] = v.y; As[kq+2][m] = v.z; As[kq+3][m] = v.w;
        }
        {
            int kk = tid / 16, nn = (tid % 16) * 4;
            *(float4*)&Bs[kk][nn] = *(const float4*)(Bb + (size_t)(kt+kk)*C_ + n0 + nn);
        }
        __syncthreads();
        #pragma unroll
        for (int k = 0; k < 16; ++k) {
            float a[4], b[4];
            #pragma unroll
            for (int i = 0; i < 4; ++i) a[i] = As[k][ty*4+i];
            *(float4*)b = *(const float4*)&Bs[k][tx*4];
            #pragma unroll
            for (int i = 0; i < 4; ++i)
                #pragma unroll
                for (int j = 0; j < 4; ++j)
                    acc[i][j] = fmaf(a[i], b[j], acc[i][j]);
        }
        __syncthreads();
    }
    #pragma unroll
    for (int i = 0; i < 4; ++i) {
        int m = ty*4 + i;
        #pragma unroll
        for (int j = 0; j < 4; ++j)
            atomicAdd(&Cb[(size_t)m*C_ + n0 + tx*4 + j], acc[i][j]);
    }
}

// --------- HMMA fp16 single-term GEMM, 128x128 CTA, 32x64 warp tile ---------
// A/B hi-only 8B granules; rows 64B/chunk + 32B XOR swizzle on (row&2).
// 16B cp.async (2 granules each; global contiguous, XOR only flips bit 5).
// 3-stage pipeline, lookahead 2 via wait_group 1.
#define RSTR 64
#define ATILE (128*RSTR)      // 8192
#define BTILE (128*RSTR)      // 8192
#define GSTAGE (ATILE+BTILE)  // 16384
#define HM_SMEM (3*GSTAGE)    // 49152

template<int EPI>
__global__ void __launch_bounds__(256, 2) hmma_gemm(
    const uint8_t* __restrict__ Ac, const uint8_t* __restrict__ Bc,
    float* __restrict__ Cout, const float* __restrict__ bias)
{
    extern __shared__ char smem[];
    const uint32_t sbase = smem_u32(smem);
    const int tid = threadIdx.x;
    const int wid = tid >> 5, ln = tid & 31;
    const int n0 = blockIdx.x * 128, m0 = blockIdx.y * 128;
    const int wm = wid & 3, wn = wid >> 2;      // 4 x 2 warp grid
    const int mrow = wm * 32, ncol = wn * 64;
    const int lr = ln >> 2, lc = ln & 3;
    const int lrb = (lr >> 1) & 1;

    const uint8_t* gA = Ac + (size_t)m0 * 1536;
    const uint8_t* gB = Bc + (size_t)n0 * 1536;

    auto load_chunk = [&](int kc, int stage) {
        uint32_t sb = sbase + (uint32_t)stage * GSTAGE;
        const uint8_t* pA = gA + kc * 64;       // contiguous 64B per row-chunk
        #pragma unroll
        for (int i = 0; i < 2; ++i) {
            int gid = tid + i * 256;            // 0..511 : 128 rows x 4 x16B
            int r = gid >> 2, c2 = gid & 3;
            uint32_t doff = (uint32_t)(c2*16) ^ (uint32_t)((r & 2) << 4);
            asm volatile("cp.async.ca.shared.global [%0], [%1], 16;"
                :: "r"(sb + r*RSTR + doff), "l"(pA + (size_t)r*1536 + c2*16));
        }
        const uint8_t* pB = gB + kc * 64;
        uint32_t bb = sb + ATILE;
        #pragma unroll
        for (int i = 0; i < 2; ++i) {
            int gid = tid + i * 256;
            int r = gid >> 2, c2 = gid & 3;
            uint32_t doff = (uint32_t)(c2*16) ^ (uint32_t)((r & 2) << 4);
            asm volatile("cp.async.ca.shared.global [%0], [%1], 16;"
                :: "r"(bb + r*RSTR + doff), "l"(pB + (size_t)r*1536 + c2*16));
        }
        asm volatile("cp.async.commit_group;");
    };

    float acc[2][8][4] = {};
    load_chunk(0, 0);
    load_chunk(1, 1);
    int sc = 0, sn = 2;
    for (int c = 0; c < 24; ++c) {
        if (c < 23) { asm volatile("cp.async.wait_group 1;"); }
        else        { asm volatile("cp.async.wait_group 0;"); }
        __syncthreads();            // all warps see chunk c; stage sn free
        if (c + 2 < 24) load_chunk(c + 2, sn);

        uint32_t sA = sbase + (uint32_t)sc * GSTAGE;
        uint32_t aBr = sA + (uint32_t)((mrow + lr)*RSTR + lc*8);
        uint32_t bBr = sA + ATILE + (uint32_t)((ncol + lr)*RSTR + lc*8);

        #pragma unroll
        for (int ks = 0; ks < 2; ++ks) {
            const uint32_t ksB = (uint32_t)((ks ^ lrb) * 32);
            uint32_t aF[2][4];
            #pragma unroll
            for (int mt = 0; mt < 2; ++mt) {
                uint32_t base = aBr + mt*16*RSTR + ksB;
                lds64(base,          aF[mt][0], aF[mt][2]);
                lds64(base + 8*RSTR, aF[mt][1], aF[mt][3]);
            }
            #pragma unroll
            for (int nt = 0; nt < 8; ++nt) {
                uint32_t b0, b1;
                lds64(bBr + nt*8*RSTR + ksB, b0, b1);
                #pragma unroll
                for (int mt = 0; mt < 2; ++mt)
                    mma_f16(acc[mt][nt], aF[mt], b0, b1);
            }
        }
        sc = (sc == 2) ? 0 : sc + 1;
        sn = (sn == 2) ? 0 : sn + 1;
        // no trailing sync: next iteration's barrier protects buffer reuse
    }

    // ------------------------------- epilogue --------------------------------
    if (EPI == 0) {
        #pragma unroll
        for (int mt = 0; mt < 2; ++mt) {
            int m = m0 + mrow + mt*16 + lr;
            #pragma unroll
            for (int nt = 0; nt < 8; ++nt) {
                int n = n0 + ncol + nt*8 + lc*2;
                float b0 = bias[n], b1 = bias[n+1];
                float* ac = acc[mt][nt];
                float2 v0 = {ac[0] + b0, ac[1] + b1};
                float2 v1 = {ac[2] + b0, ac[3] + b1};
                *(float2*)(Cout + (size_t)m * C_ + n) = v0;
                *(float2*)(Cout + (size_t)(m+8) * C_ + n) = v1;
            }
        }
    } else {
        const int nbase = n0 + ncol;                 // 64-aligned, single blk
        const int h = nbase / 192, rbase = nbase % 192;
        const int blk = rbase >> 6;
        __half* dst = (blk == 0) ? g_qhi : ((blk == 1) ? g_khi : g_vhi);
        const float sc2 = (blk == 0) ? QSCALE : 1.0f;
        #pragma unroll
        for (int mt = 0; mt < 2; ++mt) {
            #pragma unroll
            for (int rr = 0; rr < 2; ++rr) {
                int mm = m0 + mrow + mt*16 + lr + rr*8;
                int b_ = mm >> 9, t_ = mm & 511;
                size_t obase = (((size_t)b_ * H_ + h) * T_ + t_) * 64;
                #pragma unroll
                for (int nt = 0; nt < 8; ++nt) {
                    int n = nbase + nt*8 + lc*2;
                    size_t o = obase + nt*8 + lc*2;
                    float v0 = (acc[mt][nt][rr*2+0] + bias[n])   * sc2;
                    float v1 = (acc[mt][nt][rr*2+1] + bias[n+1]) * sc2;
                    *(__half2*)(dst + o) = __floats2half2_rn(v0, v1);
                }
            }
        }
    }
}

// ------------------------ V transpose: [s][d] -> [d][s] ----------------------
__global__ void __launch_bounds__(256) k_vT() {
    __shared__ __half thi[64][72];
    const int s0 = blockIdx.x * 64;
    const int bh = blockIdx.y;
    const int tid = threadIdx.x;
    const int r = tid >> 2, cs = (tid & 3) * 16;
    const size_t sbase = ((size_t)bh * T_ + s0 + r) * 64 + cs;
    #pragma unroll
    for (int j = 0; j < 2; ++j)
        *(uint4*)&thi[r][cs + j*8] = *(const uint4*)(g_vhi + sbase + j*8);
    __syncthreads();
    const int d = tid >> 2, ss = (tid & 3) * 16;
    const size_t dbase = ((size_t)bh * 64 + d) * T_ + s0 + ss;
    #pragma unroll
    for (int j = 0; j < 2; ++j) {
        uint32_t ph[4];
        #pragma unroll
        for (int q = 0; q < 4; ++q) {
            int s = ss + j*8 + q*2;
            __half2 a; a.x = thi[s][d]; a.y = thi[s+1][d];
            ph[q] = *(uint32_t*)&a;
        }
        *(uint4*)(g_vthi + dbase + j*8) = *(uint4*)ph;
    }
}

// --------------------------- HMMA fused attention ----------------------------
// All operands single fp16. S: 1 MMA/step; PV: 1 MMA/step.
#define KSTR 144u
#define QSTR 144u
#define VTSTR 1040u
#define SM_K 0u            // 512*144 = 73728
#define SM_VT 0u           // 64*1040 = 66560 (overlays K)
#define SM_Q 73728u        // 9216
#define SM_OBUF 73728u     // 18432 (overlays Q after fragments in regs)
#define OSTRF 72
#define SM_EXM 92160u
#define SM_EXS 93184u
#define ATTN_SMEM 94208

__global__ void __launch_bounds__(512) attn_k(float* __restrict__ probs)
{
    extern __shared__ char smem[];
    const uint32_t sb = smem_u32(smem);
    const int tid = threadIdx.x;
    const int wid = tid >> 5, ln = tid & 31;
    const int wm = wid & 3, wq = wid >> 2;
    const int b = blockIdx.z, h = blockIdx.y, t0 = blockIdx.x * 64;
    const int bh = b * H_ + h;
    const int lr = ln >> 2, lc = ln & 3;

    // ---- load K (512 rows) + Q (64 rows) ----
    {
        const __half* khi = g_khi + (size_t)bh * T_ * 64;
        #pragma unroll
        for (int i = 0; i < 8; ++i) {
            int idx = tid + i * 512;
            int r = idx >> 3, sg = idx & 7;
            asm volatile("cp.async.cg.shared.global [%0], [%1], 16;"
                :: "r"(sb + SM_K + r*KSTR + sg*16), "l"(khi + (size_t)r*64 + sg*8));
        }
        const __half* qhi = g_qhi + ((size_t)bh * T_ + t0) * 64;
        {
            int r = tid >> 3, sg = tid & 7;
            asm volatile("cp.async.cg.shared.global [%0], [%1], 16;"
                :: "r"(sb + SM_Q + r*QSTR + sg*16), "l"(qhi + (size_t)r*64 + sg*8));
        }
        asm volatile("cp.async.commit_group;");
        asm volatile("cp.async.wait_group 0;");
    }
    __syncthreads();

    // ---- Q fragments ----
    uint32_t aH[4][4];
    {
        const int row = wm * 16 + lr;
        #pragma unroll
        for (int ks = 0; ks < 4; ++ks) {
            uint32_t off = row * QSTR + ks * 32 + lc * 4;
            aH[ks][0] = lds32(sb + SM_Q + off);
            aH[ks][1] = lds32(sb + SM_Q + off + 8*QSTR);
            aH[ks][2] = lds32(sb + SM_Q + off + 16);
            aH[ks][3] = lds32(sb + SM_Q + off + 8*QSTR + 16);
        }
    }

    // ---- S = Q K^T  (1 MMA per step) ----
    float acc[16][4];
    #pragma unroll
    for (int nt = 0; nt < 16; ++nt) { acc[nt][0]=acc[nt][1]=acc[nt][2]=acc[nt][3]=0.f; }
    #pragma unroll
    for (int nt = 0; nt < 16; ++nt) {
        uint32_t krow = (uint32_t)(wq * 128 + nt * 8 + lr);
        #pragma unroll
        for (int ks = 0; ks < 4; ++ks) {
            uint32_t boff = krow * KSTR + ks * 32 + lc * 4;
            uint32_t bh0 = lds32(sb + SM_K + boff);
            uint32_t bh1 = lds32(sb + SM_K + boff + 16);
            mma_f16(acc[nt], aH[ks], bh0, bh1);
        }
    }

    // ---- softmax over 512 keys ----
    const int row0 = wm * 16 + lr;
    {
        float mx0 = -1e30f, mx1 = -1e30f;
        #pragma unroll
        for (int nt = 0; nt < 16; ++nt) {
            mx0 = fmaxf(mx0, fmaxf(acc[nt][0], acc[nt][1]));
            mx1 = fmaxf(mx1, fmaxf(acc[nt][2], acc[nt][3]));
        }
        mx0 = fmaxf(mx0, __shfl_xor_sync(0xffffffffu, mx0, 1));
        mx0 = fmaxf(mx0, __shfl_xor_sync(0xffffffffu, mx0, 2));
        mx1 = fmaxf(mx1, __shfl_xor_sync(0xffffffffu, mx1, 1));
        mx1 = fmaxf(mx1, __shfl_xor_sync(0xffffffffu, mx1, 2));
        float* exm = (float*)(smem + SM_EXM);
        if (lc == 0) { exm[wq*64 + row0] = mx0; exm[wq*64 + row0 + 8] = mx1; }
        __syncthreads();     // all warps past S MMAs -> K region dead

        // ---- prefetch VT into K region ----
        {
            const __half* vthi = g_vthi + (size_t)bh * 64 * T_;
            #pragma unroll
            for (int i = 0; i < 8; ++i) {
                int idx = tid + i * 512;
                int d = idx >> 6, sg = idx & 63;
                asm volatile("cp.async.cg.shared.global [%0], [%1], 16;"
                    :: "r"(sb + SM_VT + d*VTSTR + sg*16), "l"(vthi + (size_t)d*T_ + sg*8));
            }
            asm volatile("cp.async.commit_group;");
        }

        float m0 = fmaxf(fmaxf(exm[row0],      exm[64+row0]),
                         fmaxf(exm[128+row0],  exm[192+row0]));
        float m1 = fmaxf(fmaxf(exm[row0+8],    exm[64+row0+8]),
                         fmaxf(exm[128+row0+8],exm[192+row0+8]));
        float s0 = 0.f, s1 = 0.f;
        #pragma unroll
        for (int nt = 0; nt < 16; ++nt) {
            acc[nt][0] = __expf(acc[nt][0] - m0); s0 += acc[nt][0];
            acc[nt][1] = __expf(acc[nt][1] - m0); s0 += acc[nt][1];
            acc[nt][2] = __expf(acc[nt][2] - m1); s1 += acc[nt][2];
            acc[nt][3] = __expf(acc[nt][3] - m1); s1 += acc[nt][3];
        }
        s0 += __shfl_xor_sync(0xffffffffu, s0, 1);
        s0 += __shfl_xor_sync(0xffffffffu, s0, 2);
        s1 += __shfl_xor_sync(0xffffffffu, s1, 1);
        s1 += __shfl_xor_sync(0xffffffffu, s1, 2);
        float* exs = (float*)(smem + SM_EXS);
        if (lc == 0) { exs[wq*64 + row0] = s0; exs[wq*64 + row0 + 8] = s1; }
        __syncthreads();
        float inv0 = 1.0f / (exs[row0] + exs[64+row0] + exs[128+row0] + exs[192+row0]);
        float inv1 = 1.0f / (exs[row0+8] + exs[64+row0+8] + exs[128+row0+8] + exs[192+row0+8]);
        #pragma unroll
        for (int nt = 0; nt < 16; ++nt) {
            acc[nt][0] *= inv0; acc[nt][1] *= inv0;
            acc[nt][2] *= inv1; acc[nt][3] *= inv1;
        }
    }

    // ---- wait VT, then PV with probs stores interleaved ----
    asm volatile("cp.async.wait_group 0;");
    __syncthreads();

    float* p0 = probs + ((size_t)bh * T_ + t0 + row0) * 512 + wq*128 + lc*2;
    float* p1 = p0 + (size_t)8 * 512;

    float oacc[8][4];
    #pragma unroll
    for (int dn = 0; dn < 8; ++dn) { oacc[dn][0]=oacc[dn][1]=oacc[dn][2]=oacc[dn][3]=0.f; }
    #pragma unroll
    for (int kk = 0; kk < 8; ++kk) {
        uint32_t phi[4];
        phi[0] = pack2h(acc[2*kk][0],   acc[2*kk][1]);
        phi[1] = pack2h(acc[2*kk][2],   acc[2*kk][3]);
        phi[2] = pack2h(acc[2*kk+1][0], acc[2*kk+1][1]);
        phi[3] = pack2h(acc[2*kk+1][2], acc[2*kk+1][3]);
        // interleaved probs stores (overlap STG with tensor work)
        {
            float2 v00 = {acc[2*kk][0],   acc[2*kk][1]};
            float2 v01 = {acc[2*kk][2],   acc[2*kk][3]};
            float2 v10 = {acc[2*kk+1][0], acc[2*kk+1][1]};
            float2 v11 = {acc[2*kk+1][2], acc[2*kk+1][3]};
            *(float2*)(p0 + (2*kk)*8)   = v00;
            *(float2*)(p1 + (2*kk)*8)   = v01;
            *(float2*)(p0 + (2*kk+1)*8) = v10;
            *(float2*)(p1 + (2*kk+1)*8) = v11;
        }
        uint32_t colV = (uint32_t)((wq*128 + kk*16 + lc*2) * 2);
        #pragma unroll
        for (int dn = 0; dn < 8; ++dn) {
            uint32_t vrow = (uint32_t)(dn*8 + lr);
            uint32_t offH = vrow * VTSTR + colV;
            uint32_t bh0 = lds32(sb + SM_VT + offH);
            uint32_t bh1 = lds32(sb + SM_VT + offH + 16);
            mma_f16(oacc[dn], phi, bh0, bh1);
        }
    }

    // ---- cross-warp reduce ----
    float* obuf = (float*)(smem + SM_OBUF);
    #pragma unroll
    for (int g = 0; g < 4; ++g) {
        if (wq == g) {
            #pragma unroll
            for (int dn = 0; dn < 8; ++dn) {
                int c = dn*8 + lc*2;
                float* b0 = obuf + row0 * OSTRF + c;
                float* b1 = obuf + (row0 + 8) * OSTRF + c;
                if (g == 0) {
                    b0[0] = oacc[dn][0]; b0[1] = oacc[dn][1];
                    b1[0] = oacc[dn][2]; b1[1] = oacc[dn][3];
                } else {
                    b0[0] += oacc[dn][0]; b0[1] += oacc[dn][1];
                    b1[0] += oacc[dn][2]; b1[1] += oacc[dn][3];
                }
            }
        }
        __syncthreads();
    }

    // ---- write O as hi-only 8B granules for OUT gemm ----
    {
        int row = tid >> 3, s2 = tid & 7;
        const float* src = obuf + row * OSTRF;
        size_t rb = ((size_t)b * T_ + t0 + row) * 1536 + (size_t)h * 128;
        #pragma unroll
        for (int u = 0; u < 2; ++u) {
            int s = s2 * 2 + u;
            int g = s >> 2, lcx = s & 3;
            int k0 = g * 16 + lcx * 2;
            uint32_t w[2];
            pack_g8(src[k0], src[k0+1], src[k0+8], src[k0+9], w);
            *(uint2*)(g_oh + rb + g*32 + lcx*8) = *(uint2*)w;
        }
    }
}

// --------------------------------- launcher ---------------------------------
extern "C" void kernel_launch(void* const* d_in, const int* in_sizes, int n_in,
                              void* d_out, int out_size)
{
    const float* x     = (const float*)d_in[0];
    const float* Wqkv  = (const float*)d_in[1];
    const float* bqkv  = (const float*)d_in[2];
    const float* Wph   = (const float*)d_in[3];
    const float* bph   = (const float*)d_in[4];
    const float* Wproj = (const float*)d_in[5];
    const float* bproj = (const float*)d_in[6];
    float* out = (float*)d_out;
    float* sa_out = out;
    float* probs  = out + (size_t)BT_*C_;

    uint8_t *xh_p, *wqh_p, *oh_p, *wch_p;
    float *wcomb_p, *bcomb_p;
    cudaGetSymbolAddress((void**)&xh_p,   g_xh);
    cudaGetSymbolAddress((void**)&wqh_p,  g_wqh);
    cudaGetSymbolAddress((void**)&oh_p,   g_oh);
    cudaGetSymbolAddress((void**)&wch_p,  g_wch);
    cudaGetSymbolAddress((void**)&wcomb_p, g_wcomb);
    cudaGetSymbolAddress((void**)&bcomb_p, g_bcomb);

    static int attrs_set = 0;
    if (!attrs_set) {
        cudaFuncSetAttribute(hmma_gemm<0>, cudaFuncAttributeMaxDynamicSharedMemorySize, HM_SMEM);
        cudaFuncSetAttribute(hmma_gemm<1>, cudaFuncAttributeMaxDynamicSharedMemorySize, HM_SMEM);
        cudaFuncSetAttribute(attn_k, cudaFuncAttributeMaxDynamicSharedMemorySize, ATTN_SMEM);
        attrs_set = 1;
    }

    // 1-3: prep on QKV critical path (+ wcomb zero / bcomb init)
    k_prep_xh<<<BT_*192/256, 256>>>(x);
    k_prep_wqh<<<NQKV_*192/256, 256>>>(Wqkv);
    k_binit<<<(C_*C_ + C_ + 255)/256, 256>>>(bproj);

    // 4: QKV GEMM (profiled slot) -> q/k/v fp16
    hmma_gemm<1><<<dim3(NQKV_/128, BT_/128), 256, HM_SMEM>>>(
        xh_p, wqh_p, nullptr, bqkv);

    // 5-7: Wcomb chain (independent of attention)
    k_bcomb<<<288, 256>>>(bph, Wproj);
    sgemm64ks<<<dim3(4, 12, 12), 256>>>(Wph, Wproj, wcomb_p);
    k_prep_wch<<<C_*192/256, 256>>>();

    // 8: V transpose
    k_vT<<<dim3(T_/64, B_*H_), 256>>>();

    // 9: fused attention -> probs + O(hi granules)
    attn_k<<<dim3(T_/64, H_, B_), 512, ATTN_SMEM>>>(probs);

    // 10: output GEMM + bcomb -> sa_out
    hmma_gemm<0><<<dim3(C_/128, BT_/128), 256, HM_SMEM>>>(
        oh_p, wch_p, sa_out, bcomb_p);
}